// round 12
// baseline (speedup 1.0000x reference)
#include <cuda_runtime.h>
#include <cuda_bf16.h>
#include <cstdint>
#include <math.h>

#define FULLMASK 0xffffffffu
typedef __nv_bfloat16 bf16;
// B=16, C=384, H=W=64, N=4096, HEADS=4, HD=96

// ---------------- scratch ----------------
__device__ __align__(256) float g_conv[25165824];
__device__ __align__(256) float g_pos[1572864];
__device__ __align__(256) float g_x3[25165824];   // bf16 x3, then bf16 x2s
__device__ __align__(256) float g_attn[2359296];
__device__ __align__(256) float g_norms[24576];
__device__ __align__(256) bf16 g_bx[25165824];
__device__ __align__(256) bf16 g_lnb[25165824];
__device__ __align__(256) bf16 g_kv[50331648];
__device__ __align__(256) bf16 g_kt[25165824];
__device__ __align__(256) bf16 g_b1[25165824];    // XCA AV out -> WA proj out (bf16)
__device__ __align__(256) bf16 g_uqt[25165824];   // unfold(inp) -> MLP out y (bf16)
__device__ __align__(256) bf16 g_battn[2359296];
__device__ __align__(256) bf16 g_h1[100663296];
__device__ __align__(256) bf16 g_wt[2064384];

__global__ void zero_kernel(float* __restrict__ p, long n)
{
    long i = (long)blockIdx.x * 256 + threadIdx.x;
    if (i < n) p[i] = 0.f;
}

__global__ void cvtw_kernel(const float* __restrict__ s0, const float* __restrict__ s1,
                            const float* __restrict__ s2, const float* __restrict__ s3,
                            const float* __restrict__ s4, const float* __restrict__ s5,
                            bf16* __restrict__ out)
{
    long i = (long)blockIdx.x * 256 + threadIdx.x;
    if (i >= 2064384L) return;
    const float* s; long off;
    if (i < 294912)       { s = s0; off = i; }
    else if (i < 442368)  { s = s1; off = i - 294912; }
    else if (i < 737280)  { s = s2; off = i - 442368; }
    else if (i < 884736)  { s = s3; off = i - 737280; }
    else if (i < 1474560) { s = s4; off = i - 884736; }
    else                  { s = s5; off = i - 1474560; }
    out[i] = __float2bfloat16(s[off]);
}

__global__ void cvtx_kernel(const float* __restrict__ x, bf16* __restrict__ bx,
                            bf16* __restrict__ uqT)
{
    long idx = (long)blockIdx.x * 256 + threadIdx.x;
    if (idx >= 25165824L) return;
    float v = x[idx];
    bf16 bv = __float2bfloat16(v);
    bx[idx] = bv;
    int n = (int)(idx & 4095);
    long r = idx >> 12;
    int c = (int)(r % 384), b = (int)(r / 384);
    int hh = n >> 6, ww = n & 63;
    int q = ((hh & 1) << 1) | (ww & 1);
    int p = ((hh >> 1) << 5) | (ww >> 1);
    uqT[((long)(b * 4 + q) * 384 + c) * 1024 + p] = bv;
}

__global__ void pos_kernel(const float* __restrict__ pw, const float* __restrict__ pb,
                           float* __restrict__ pos)
{
    __shared__ float feat[64];
    int n = blockIdx.x, t = threadIdx.x;
    int hh = n >> 6, ww = n & 63;
    if (t < 64) {
        int j = t, jj = j & 31, m = jj >> 1;
        float v = (j < 32) ? (float)(hh + 1) : (float)(ww + 1);
        v = v / (64.0f + 1e-6f) * 6.283185307179586f;
        float arg = v / powf(10000.0f, (float)m / 16.0f);
        feat[j] = (jj & 1) ? cosf(arg) : sinf(arg);
    }
    __syncthreads();
    float acc = pb[t];
    const float* wr = pw + t * 64;
    #pragma unroll
    for (int j = 0; j < 64; j++) acc += feat[j] * wr[j];
    pos[(long)n * 384 + t] = acc;
}

__global__ void __launch_bounds__(256) dwconv3_kernel(
    const float* __restrict__ x, const float* __restrict__ w,
    const float* __restrict__ bias, float* __restrict__ out)
{
    __shared__ float A[66 * 66], Bb[66 * 66];
    int bc = blockIdx.x, b = bc / 96, c = bc % 96, tid = threadIdx.x;
    for (int i = tid; i < 66 * 66; i += 256) { A[i] = 0.f; Bb[i] = 0.f; }
    __syncthreads();
    const float* xp = x + ((long)b * 384 + c) * 4096;
    for (int i = tid; i < 4096; i += 256)
        A[((i >> 6) + 1) * 66 + (i & 63) + 1] = xp[i];
    __syncthreads();
    float* src = A;
    float* dst = Bb;
    #pragma unroll
    for (int ch = 0; ch < 3; ch++) {
        const float* wp = w + (ch * 96 + c) * 9;
        float bv = bias[ch * 96 + c];
        float w00 = wp[0], w01 = wp[1], w02 = wp[2];
        float w10 = wp[3], w11 = wp[4], w12 = wp[5];
        float w20 = wp[6], w21 = wp[7], w22 = wp[8];
        float* op = out + ((long)b * 384 + ch * 96 + c) * 4096;
        const float* xn = (ch < 2) ? x + ((long)b * 384 + (ch + 1) * 96 + c) * 4096 : nullptr;
        for (int i = tid; i < 4096; i += 256) {
            int r = i >> 6, cc = i & 63;
            const float* p = src + r * 66 + cc;
            float acc = bv
                + w00 * p[0]   + w01 * p[1]   + w02 * p[2]
                + w10 * p[66]  + w11 * p[67]  + w12 * p[68]
                + w20 * p[132] + w21 * p[133] + w22 * p[134];
            op[i] = acc;
            if (xn) dst[(r + 1) * 66 + cc + 1] = acc + xn[i];
        }
        __syncthreads();
        float* t = src; src = dst; dst = t;
    }
}

// ---------------- fused transpose+pos+LayerNorm ----------------
// Block: 16 n-rows of one batch. Writes bf16 x3 AND bf16 lnb.
__global__ void __launch_bounds__(256) t1ln_kernel(
    const float* __restrict__ conv, const float* __restrict__ xin,
    const float* __restrict__ pos, const float* __restrict__ w,
    const float* __restrict__ bvec, bf16* __restrict__ x3, bf16* __restrict__ lnb)
{
    __shared__ float s[16 * 385];
    int n0 = blockIdx.x << 4, b = blockIdx.y, tid = threadIdx.x;
    // load 384 c x 16 n, transposed into s[n][c]
    for (int idx = tid; idx < 384 * 16; idx += 256) {
        int n = idx & 15, c = idx >> 4;
        const float* src = (c >= 288) ? xin : conv;
        float v = src[((long)b * 384 + c) * 4096 + n0 + n] + pos[(long)(n0 + n) * 384 + c];
        s[n * 385 + c] = v;
    }
    __syncthreads();
    int wid = tid >> 5, lane = tid & 31;
    #pragma unroll
    for (int r = 0; r < 2; r++) {
        int row = wid + r * 8;
        const float* sr = s + row * 385;
        float sum = 0.f, sq = 0.f;
        #pragma unroll
        for (int i = 0; i < 12; i++) {
            float v = sr[lane + i * 32];
            sum += v; sq += v * v;
        }
        #pragma unroll
        for (int o = 16; o; o >>= 1) {
            sum += __shfl_xor_sync(FULLMASK, sum, o);
            sq  += __shfl_xor_sync(FULLMASK, sq, o);
        }
        float m = sum * (1.0f / 384.0f);
        float rs = rsqrtf(sq * (1.0f / 384.0f) - m * m + 1e-6f);
        long ob = ((long)b * 4096 + n0 + row) * 384;
        #pragma unroll
        for (int i = 0; i < 12; i++) {
            int c = lane + i * 32;
            float v = sr[c];
            x3[ob + c]  = __float2bfloat16(v);
            lnb[ob + c] = __float2bfloat16((v - m) * rs * w[c] + bvec[c]);
        }
    }
}

__global__ void tk_kernel(const bf16* __restrict__ kv, bf16* __restrict__ kT, int R)
{
    __shared__ bf16 tile[32][33];
    int n0 = blockIdx.x << 5, d0 = blockIdx.y << 5, bz = blockIdx.z;
    int tx = threadIdx.x, ty = threadIdx.y;
    #pragma unroll
    for (int r = 0; r < 4; r++)
        tile[ty + r * 8][tx] = kv[((long)bz * R + n0 + ty + r * 8) * 768 + d0 + tx];
    __syncthreads();
    #pragma unroll
    for (int r = 0; r < 4; r++)
        kT[((long)bz * 384 + d0 + ty + r * 8) * R + n0 + tx] = tile[tx][ty + r * 8];
}

__global__ void norms2_k(const bf16* __restrict__ kT, float* __restrict__ norms, int R)
{
    int gw = blockIdx.x * 8 + (threadIdx.x >> 5);
    int lane = threadIdx.x & 31;
    const bf16* p = kT + (long)gw * R;
    float s = 0.f;
    for (int i = lane * 2; i < R; i += 64) {
        __nv_bfloat162 v = *(const __nv_bfloat162*)(p + i);
        float a = __bfloat162float(v.x), b = __bfloat162float(v.y);
        s += a * a + b * b;
    }
    #pragma unroll
    for (int o = 16; o; o >>= 1) s += __shfl_xor_sync(FULLMASK, s, o);
    if (lane == 0) norms[gw] = sqrtf(s);
}

// LayerNorm over C=384, bf16 input, gather applies fold() map
__global__ void lng_kernel(const bf16* __restrict__ in, const float* __restrict__ w,
                           const float* __restrict__ bvec, bf16* __restrict__ out)
{
    int row = blockIdx.x, t = threadIdx.x;
    int b = row >> 12, n = row & 4095;
    int hh = n >> 6, ww = n & 63;
    int q = ((hh & 1) << 1) | (ww & 1);
    int p = ((hh >> 1) << 5) | (ww >> 1);
    long ibase = ((long)(b * 4 + q) * 1024 + p) * 384;
    float v0 = __bfloat162float(in[ibase + t]);
    float v1 = __bfloat162float(in[ibase + t + 128]);
    float v2 = __bfloat162float(in[ibase + t + 256]);
    float s = v0 + v1 + v2;
    float q2 = v0 * v0 + v1 * v1 + v2 * v2;
    #pragma unroll
    for (int o = 16; o; o >>= 1) {
        s += __shfl_down_sync(FULLMASK, s, o);
        q2 += __shfl_down_sync(FULLMASK, q2, o);
    }
    __shared__ float ss[4], sq[4], smean, srstd;
    int wid = t >> 5, lane = t & 31;
    if (lane == 0) { ss[wid] = s; sq[wid] = q2; }
    __syncthreads();
    if (t == 0) {
        float S = ss[0] + ss[1] + ss[2] + ss[3];
        float Q = sq[0] + sq[1] + sq[2] + sq[3];
        float m = S * (1.0f / 384.0f);
        smean = m;
        srstd = rsqrtf(Q * (1.0f / 384.0f) - m * m + 1e-6f);
    }
    __syncthreads();
    float m = smean, r = srstd;
    long ob = (long)row * 384;
    out[ob + t]       = __float2bfloat16((v0 - m) * r * w[t]       + bvec[t]);
    out[ob + t + 128] = __float2bfloat16((v1 - m) * r * w[t + 128] + bvec[t + 128]);
    out[ob + t + 256] = __float2bfloat16((v2 - m) * r * w[t + 256] + bvec[t + 256]);
}

__global__ void xca_softmax_k(const float* __restrict__ G, const float* __restrict__ norms,
                              const float* __restrict__ temp, bf16* __restrict__ P)
{
    int warp = threadIdx.x >> 5, lane = threadIdx.x & 31;
    int row = blockIdx.x * 8 + warp;
    int bh = row / 96, b = bh >> 2, h = bh & 3;
    float tv = temp[h];
    const float* g = G + (long)row * 96;
    bf16* o = P + (long)row * 96;
    const float* nb = norms + b * 384 + h * 96;
    float v[3];
    #pragma unroll
    for (int i = 0; i < 3; i++) { int d = lane + i * 32; v[i] = g[d] * tv / fmaxf(nb[d], 1e-12f); }
    float m = fmaxf(v[0], fmaxf(v[1], v[2]));
    #pragma unroll
    for (int o2 = 16; o2; o2 >>= 1) m = fmaxf(m, __shfl_xor_sync(FULLMASK, m, o2));
    float e[3], s = 0.f;
    #pragma unroll
    for (int i = 0; i < 3; i++) { e[i] = expf(v[i] - m); s += e[i]; }
    #pragma unroll
    for (int o2 = 16; o2; o2 >>= 1) s += __shfl_xor_sync(FULLMASK, s, o2);
    float inv = 1.0f / s;
    #pragma unroll
    for (int i = 0; i < 3; i++) o[lane + i * 32] = __float2bfloat16(e[i] * inv);
}

__global__ void wa_softmax_k(const float* __restrict__ G, const float* __restrict__ norms,
                             bf16* __restrict__ P)
{
    int warp = threadIdx.x >> 5, lane = threadIdx.x & 31;
    int row = blockIdx.x * 8 + warp;
    int bh = row / 96, bq = bh >> 2, h = bh & 3;
    const float* g = G + (long)row * 96;
    bf16* o = P + (long)row * 96;
    const float* nb = norms + bq * 384 + h * 96;
    float l[3];
    #pragma unroll
    for (int i = 0; i < 3; i++) { int d = lane + i * 32; l[i] = g[d] / fmaxf(nb[d], 1e-12f); }
    float m1 = fmaxf(l[0], fmaxf(l[1], l[2]));
    #pragma unroll
    for (int o2 = 16; o2; o2 >>= 1) m1 = fmaxf(m1, __shfl_xor_sync(FULLMASK, m1, o2));
    float e[3], s1 = 0.f;
    #pragma unroll
    for (int i = 0; i < 3; i++) { e[i] = expf(l[i] - m1); s1 += e[i]; }
    #pragma unroll
    for (int o2 = 16; o2; o2 >>= 1) s1 += __shfl_xor_sync(FULLMASK, s1, o2);
    float inv1 = 1.0f / s1, a[3];
    #pragma unroll
    for (int i = 0; i < 3; i++) a[i] = l[i] * 0.051031036307982884f + 0.5f * e[i] * inv1;
    float m2 = fmaxf(a[0], fmaxf(a[1], a[2]));
    #pragma unroll
    for (int o2 = 16; o2; o2 >>= 1) m2 = fmaxf(m2, __shfl_xor_sync(FULLMASK, m2, o2));
    float e2[3], s2 = 0.f;
    #pragma unroll
    for (int i = 0; i < 3; i++) { e2[i] = expf(a[i] - m2); s2 += e2[i]; }
    #pragma unroll
    for (int o2 = 16; o2; o2 >>= 1) s2 += __shfl_xor_sync(FULLMASK, s2, o2);
    float inv2 = 1.0f / s2;
    #pragma unroll
    for (int i = 0; i < 3; i++) o[lane + i * 32] = __float2bfloat16(e2[i] * inv2);
}

__global__ void final_kernel(const bf16* __restrict__ y, const float* __restrict__ xin,
                             const float* __restrict__ gamma, float* __restrict__ out)
{
    __shared__ float tile[32][33];
    int n0 = blockIdx.x << 5, c0 = blockIdx.y << 5, b = blockIdx.z;
    int tx = threadIdx.x, ty = threadIdx.y;
    #pragma unroll
    for (int r = 0; r < 4; r++)
        tile[ty + r * 8][tx] =
            __bfloat162float(y[((long)b * 4096 + n0 + ty + r * 8) * 384 + c0 + tx]);
    __syncthreads();
    #pragma unroll
    for (int r = 0; r < 4; r++) {
        int c = c0 + ty + r * 8;
        long o = ((long)b * 384 + c) * 4096 + n0 + tx;
        out[o] = xin[o] + gamma[c] * tile[tx][ty + r * 8];
    }
}

__device__ __forceinline__ void cpa16s(unsigned sa, const void* g)
{
    asm volatile("cp.async.cg.shared.global [%0], [%1], 16;\n" :: "r"(sa), "l"(g));
}

__device__ __forceinline__ void cpa16p(unsigned sa, const void* g, bool valid)
{
    int sz = valid ? 16 : 0;
    asm volatile("cp.async.cg.shared.global [%0], [%1], 16, %2;\n"
                 :: "r"(sa), "l"(g), "r"(sz));
}

__device__ __forceinline__ unsigned smem_u32(const void* p)
{
    return (unsigned)__cvta_generic_to_shared(p);
}

__device__ __forceinline__ float gelu_f(float v)
{
    return 0.5f * v * (1.0f + erff(v * 0.7071067811865476f));
}

// ============================================================================
// Big-GEMM: 128x128x32 CTA tile, 128 threads, 4 warps of 64x64.
// EPI: 0 plain, 1 GELU, 2 fused e1 scatter. OUTBF: bf16 out else fp32.
// ============================================================================
template<int EPI, int OUTBF>
__global__ void __launch_bounds__(128) bgemm2_k(
    const bf16* __restrict__ A, const bf16* __restrict__ B,
    const float* __restrict__ bias, void* __restrict__ Cg,
    int N, int K,
    const bf16* __restrict__ f1, const float* __restrict__ f2,
    const float* __restrict__ f3, const float* __restrict__ f4)
{
    extern __shared__ __align__(16) bf16 dynb[];
    const int TE = 128 * 40;
    unsigned sbA = smem_u32(dynb);
    unsigned sbB = sbA + 3 * TE * 2;

    int tid = threadIdx.x;
    int m0 = blockIdx.x * 128, n0 = blockIdx.y * 128;

    float c[4][8][4];
    #pragma unroll
    for (int i = 0; i < 4; i++)
        #pragma unroll
        for (int j = 0; j < 8; j++)
            #pragma unroll
            for (int q = 0; q < 4; q++) c[i][j][q] = 0.f;

    int seg = tid & 3, rS = tid >> 2;
    auto stage = [&](int buf, int k0) {
        #pragma unroll
        for (int ps = 0; ps < 4; ps++) {
            int row = rS + ps * 32;
            cpa16s(sbA + (buf * TE + row * 40 + seg * 8) * 2,
                   A + (long)(m0 + row) * K + k0 + seg * 8);
            cpa16s(sbB + (buf * TE + row * 40 + seg * 8) * 2,
                   B + (long)(n0 + row) * K + k0 + seg * 8);
        }
    };

    int nst = K >> 5;
    stage(0, 0);
    asm volatile("cp.async.commit_group;\n");
    if (nst > 1) stage(1, 32);
    asm volatile("cp.async.commit_group;\n");

    int wid = tid >> 5, lane = tid & 31;
    int wm = (wid >> 1) * 64, wn = (wid & 1) * 64;
    int g = lane >> 2, t = lane & 3;
    int aRow = ((lane >> 3) & 1) * 8 + (lane & 7);
    int aK = (lane >> 4) * 8;
    int bRow = ((lane >> 4) & 1) * 8 + (lane & 7);
    int bK = ((lane >> 3) & 1) * 8;

    for (int s = 0; s < nst; s++) {
        int nf = s + 2;
        if (nf < nst) stage(nf % 3, nf << 5);
        asm volatile("cp.async.commit_group;\n");
        asm volatile("cp.async.wait_group 2;\n");
        __syncthreads();
        int buf = s % 3;
        unsigned aT = sbA + buf * TE * 2;
        unsigned bT = sbB + buf * TE * 2;
        #pragma unroll
        for (int ks = 0; ks < 32; ks += 16) {
            unsigned af[4][4], bfm[8][2];
            #pragma unroll
            for (int im = 0; im < 4; im++) {
                unsigned addr = aT + ((wm + im * 16 + aRow) * 40 + ks + aK) * 2;
                asm volatile("ldmatrix.sync.aligned.m8n8.x4.shared.b16 {%0,%1,%2,%3}, [%4];\n"
                             : "=r"(af[im][0]), "=r"(af[im][1]), "=r"(af[im][2]), "=r"(af[im][3])
                             : "r"(addr));
            }
            #pragma unroll
            for (int jp = 0; jp < 4; jp++) {
                unsigned addr = bT + ((wn + jp * 16 + bRow) * 40 + ks + bK) * 2;
                asm volatile("ldmatrix.sync.aligned.m8n8.x4.shared.b16 {%0,%1,%2,%3}, [%4];\n"
                             : "=r"(bfm[2 * jp][0]), "=r"(bfm[2 * jp][1]),
                               "=r"(bfm[2 * jp + 1][0]), "=r"(bfm[2 * jp + 1][1])
                             : "r"(addr));
            }
            #pragma unroll
            for (int im = 0; im < 4; im++)
                #pragma unroll
                for (int jn = 0; jn < 8; jn++)
                    asm volatile(
                        "mma.sync.aligned.m16n8k16.row.col.f32.bf16.bf16.f32 "
                        "{%0,%1,%2,%3},{%4,%5,%6,%7},{%8,%9},{%0,%1,%2,%3};\n"
                        : "+f"(c[im][jn][0]), "+f"(c[im][jn][1]),
                          "+f"(c[im][jn][2]), "+f"(c[im][jn][3])
                        : "r"(af[im][0]), "r"(af[im][1]), "r"(af[im][2]), "r"(af[im][3]),
                          "r"(bfm[jn][0]), "r"(bfm[jn][1]));
        }
        __syncthreads();
    }

    float* Cf = (float*)Cg;
    bf16*  Cb = (bf16*)Cg;
    #pragma unroll
    for (int im = 0; im < 4; im++) {
        int rbase = m0 + wm + im * 16 + g;
        #pragma unroll
        for (int jn = 0; jn < 8; jn++) {
            int col = n0 + wn + jn * 8 + t * 2;
            float b0 = bias ? bias[col] : 0.f;
            float b1 = bias ? bias[col + 1] : 0.f;
            #pragma unroll
            for (int hr = 0; hr < 2; hr++) {
                int rr = rbase + hr * 8;
                float v0 = c[im][jn][hr * 2 + 0] + b0;
                float v1 = c[im][jn][hr * 2 + 1] + b1;
                if (EPI == 1) { v0 = gelu_f(v0); v1 = gelu_f(v1); }
                if (EPI == 2) {
                    long rb = (long)rr * 384 + col;
                    float a0 = (__bfloat162float(f1[rb])     + f2[col]     * v0) * f3[col]     + f4[col];
                    float a1 = (__bfloat162float(f1[rb + 1]) + f2[col + 1] * v1) * f3[col + 1] + f4[col + 1];
                    int n = rr & 4095, b = rr >> 12;
                    int hh2 = n >> 6, ww2 = n & 63;
                    int q = ((hh2 & 1) << 1) | (ww2 & 1);
                    int p = ((hh2 >> 1) << 5) | (ww2 >> 1);
                    bf16* dst = Cb + ((long)(b * 4 + q) * 1024 + p) * 384 + col;
                    *(__nv_bfloat162*)dst = __floats2bfloat162_rn(a0, a1);
                } else if (OUTBF) {
                    *(__nv_bfloat162*)(Cb + (long)rr * N + col) = __floats2bfloat162_rn(v0, v1);
                } else {
                    *(float2*)(Cf + (long)rr * N + col) = make_float2(v0, v1);
                }
            }
        }
    }
}

template<int EPI, int OUTBF>
static void bg2(const bf16* A, const bf16* B, const float* bias, void* C,
                int M, int N, int K,
                const bf16* f1 = nullptr, const float* f2 = nullptr,
                const float* f3 = nullptr, const float* f4 = nullptr)
{
    cudaFuncSetAttribute(bgemm2_k<EPI, OUTBF>,
                         cudaFuncAttributeMaxDynamicSharedMemorySize, 61440);
    dim3 grid(M / 128, N / 128);
    bgemm2_k<EPI, OUTBF><<<grid, 128, 61440>>>(A, B, bias, C, N, K, f1, f2, f3, f4);
}

// ============================================================================
// Batched GEMM, 4-warp 64x64, bounds-guarded.
// OUTM: 0 fp32, 1 bf16, 3 fp32 atomicAdd (split-K)
// ============================================================================
template<int OUTM>
__global__ void __launch_bounds__(128) bg2b_k(
    const bf16* __restrict__ Ag, const bf16* __restrict__ Bg, void* __restrict__ Cg,
    int M, int N, int K, int lda, int ldb, int ldc,
    long sA1, long sA2, long sB1, long sB2, long sC1, long sC2, int HB, int SK)
{
    extern __shared__ __align__(16) bf16 dynb[];
    const int TE = 128 * 40;
    unsigned sbA = smem_u32(dynb);
    unsigned sbB = sbA + 3 * TE * 2;

    int zz = blockIdx.z;
    int ksl = zz % SK, z = zz / SK;
    int zo = z / HB, zi = z - zo * HB;
    const bf16* A = Ag + zo * sA1 + zi * sA2 + (long)ksl * K;
    const bf16* B = Bg + zo * sB1 + zi * sB2 + (long)ksl * K;

    int tid = threadIdx.x;
    int m0 = blockIdx.x * 128, n0 = blockIdx.y * 128;

    float c[4][8][4];
    #pragma unroll
    for (int i = 0; i < 4; i++)
        #pragma unroll
        for (int j = 0; j < 8; j++)
            #pragma unroll
            for (int q = 0; q < 4; q++) c[i][j][q] = 0.f;

    int seg = tid & 3, rS = tid >> 2;
    auto stage = [&](int buf, int k0) {
        #pragma unroll
        for (int ps = 0; ps < 4; ps++) {
            int row = rS + ps * 32;
            int ra = (m0 + row < M) ? m0 + row : M - 1;
            cpa16p(sbA + (buf * TE + row * 40 + seg * 8) * 2,
                   A + (long)ra * lda + k0 + seg * 8, m0 + row < M);
            int rb = (n0 + row < N) ? n0 + row : N - 1;
            cpa16p(sbB + (buf * TE + row * 40 + seg * 8) * 2,
                   B + (long)rb * ldb + k0 + seg * 8, n0 + row < N);
        }
    };

    int nst = K >> 5;
    stage(0, 0);
    asm volatile("cp.async.commit_group;\n");
    if (nst > 1) stage(1, 32);
    asm volatile("cp.async.commit_group;\n");

    int wid = tid >> 5, lane = tid & 31;
    int wm = (wid >> 1) * 64, wn = (wid & 1) * 64;
    int g = lane >> 2, t = lane & 3;
    int aRow = ((lane >> 3) & 1) * 8 + (lane & 7);
    int aK = (lane >> 4) * 8;
    int bRow = ((lane >> 4) & 1) * 8 + (lane & 7);
    int bK = ((lane >> 3) & 1) * 8;

    for (int s = 0; s < nst; s++) {
        int nf = s + 2;
        if (nf < nst) stage(nf % 3, nf << 5);
        asm volatile("cp.async.commit_group;\n");
        asm volatile("cp.async.wait_group 2;\n");
        __syncthreads();
        int buf = s % 3;
        unsigned aT = sbA + buf * TE * 2;
        unsigned bT = sbB + buf * TE * 2;
        #pragma unroll
        for (int ks = 0; ks < 32; ks += 16) {
            unsigned af[4][4], bfm[8][2];
            #pragma unroll
            for (int im = 0; im < 4; im++) {
                unsigned addr = aT + ((wm + im * 16 + aRow) * 40 + ks + aK) * 2;
                asm volatile("ldmatrix.sync.aligned.m8n8.x4.shared.b16 {%0,%1,%2,%3}, [%4];\n"
                             : "=r"(af[im][0]), "=r"(af[im][1]), "=r"(af[im][2]), "=r"(af[im][3])
                             : "r"(addr));
            }
            #pragma unroll
            for (int jp = 0; jp < 4; jp++) {
                unsigned addr = bT + ((wn + jp * 16 + bRow) * 40 + ks + bK) * 2;
                asm volatile("ldmatrix.sync.aligned.m8n8.x4.shared.b16 {%0,%1,%2,%3}, [%4];\n"
                             : "=r"(bfm[2 * jp][0]), "=r"(bfm[2 * jp][1]),
                               "=r"(bfm[2 * jp + 1][0]), "=r"(bfm[2 * jp + 1][1])
                             : "r"(addr));
            }
            #pragma unroll
            for (int im = 0; im < 4; im++)
                #pragma unroll
                for (int jn = 0; jn < 8; jn++)
                    asm volatile(
                        "mma.sync.aligned.m16n8k16.row.col.f32.bf16.bf16.f32 "
                        "{%0,%1,%2,%3},{%4,%5,%6,%7},{%8,%9},{%0,%1,%2,%3};\n"
                        : "+f"(c[im][jn][0]), "+f"(c[im][jn][1]),
                          "+f"(c[im][jn][2]), "+f"(c[im][jn][3])
                        : "r"(af[im][0]), "r"(af[im][1]), "r"(af[im][2]), "r"(af[im][3]),
                          "r"(bfm[jn][0]), "r"(bfm[jn][1]));
        }
        __syncthreads();
    }

    float* Cf = (float*)Cg + zo * sC1 + zi * sC2;
    bf16*  Cb = (bf16*)Cg + zo * sC1 + zi * sC2;
    #pragma unroll
    for (int im = 0; im < 4; im++) {
        int rbase = m0 + wm + im * 16 + g;
        #pragma unroll
        for (int jn = 0; jn < 8; jn++) {
            int col = n0 + wn + jn * 8 + t * 2;
            if (col >= N) continue;
            #pragma unroll
            for (int hr = 0; hr < 2; hr++) {
                int rr = rbase + hr * 8;
                if (rr >= M) continue;
                float v0 = c[im][jn][hr * 2 + 0];
                float v1 = c[im][jn][hr * 2 + 1];
                if (OUTM == 3) {
                    atomicAdd(&Cf[(long)rr * ldc + col], v0);
                    atomicAdd(&Cf[(long)rr * ldc + col + 1], v1);
                } else if (OUTM == 1) {
                    *(__nv_bfloat162*)(Cb + (long)rr * ldc + col) = __floats2bfloat162_rn(v0, v1);
                } else {
                    *(float2*)(Cf + (long)rr * ldc + col) = make_float2(v0, v1);
                }
            }
        }
    }
}

template<int OUTM>
static void bg2b(const bf16* A, const bf16* B, void* C,
                 int M, int N, int K, int lda, int ldb, int ldc,
                 long sA1, long sA2, long sB1, long sB2, long sC1, long sC2,
                 int HB, int Z, int SK = 1)
{
    cudaFuncSetAttribute(bg2b_k<OUTM>,
                         cudaFuncAttributeMaxDynamicSharedMemorySize, 61440);
    dim3 grid((M + 127) / 128, (N + 127) / 128, Z * SK);
    bg2b_k<OUTM><<<grid, 128, 61440>>>(A, B, C, M, N, K / SK, lda, ldb, ldc,
                                       sA1, sA2, sB1, sB2, sC1, sC2, HB, SK);
}

extern "C" void kernel_launch(void* const* d_in, const int* in_sizes, int n_in,
                              void* d_out, int out_size)
{
    const float* x          = (const float*)d_in[0];
    const float* convs_w    = (const float*)d_in[1];
    const float* convs_b    = (const float*)d_in[2];
    const float* pos_w      = (const float*)d_in[3];
    const float* pos_b      = (const float*)d_in[4];
    const float* ln_xca_w   = (const float*)d_in[5];
    const float* ln_xca_b   = (const float*)d_in[6];
    const float* gamma_xca  = (const float*)d_in[7];
    const float* xca_temp   = (const float*)d_in[8];
    const float* xca_kv_w   = (const float*)d_in[9];
    const float* xca_kv_b   = (const float*)d_in[10];
    const float* xca_proj_w = (const float*)d_in[11];
    const float* xca_proj_b = (const float*)d_in[12];
    const float* conv_out_w = (const float*)d_in[13];
    const float* conv_out_b = (const float*)d_in[14];
    const float* wa_kv_w    = (const float*)d_in[15];
    const float* wa_kv_b    = (const float*)d_in[16];
    const float* wa_proj_w  = (const float*)d_in[17];
    const float* wa_proj_b  = (const float*)d_in[18];
    const float* ln_w       = (const float*)d_in[19];
    const float* ln_b       = (const float*)d_in[20];
    const float* pw1_w      = (const float*)d_in[21];
    const float* pw1_b      = (const float*)d_in[22];
    const float* pw2_w      = (const float*)d_in[23];
    const float* pw2_b      = (const float*)d_in[24];
    const float* gamma      = (const float*)d_in[25];
    float* out = (float*)d_out;

    float *conv, *pos, *x3f, *attn, *norms;
    bf16 *bx, *lnb, *kv, *kt, *b1, *uqt, *battn, *h1, *wt;
    cudaGetSymbolAddress((void**)&conv,  g_conv);
    cudaGetSymbolAddress((void**)&pos,   g_pos);
    cudaGetSymbolAddress((void**)&x3f,   g_x3);
    cudaGetSymbolAddress((void**)&attn,  g_attn);
    cudaGetSymbolAddress((void**)&norms, g_norms);
    cudaGetSymbolAddress((void**)&bx,    g_bx);
    cudaGetSymbolAddress((void**)&lnb,   g_lnb);
    cudaGetSymbolAddress((void**)&kv,    g_kv);
    cudaGetSymbolAddress((void**)&kt,    g_kt);
    cudaGetSymbolAddress((void**)&b1,    g_b1);
    cudaGetSymbolAddress((void**)&uqt,   g_uqt);
    cudaGetSymbolAddress((void**)&battn, g_battn);
    cudaGetSymbolAddress((void**)&h1,    g_h1);
    cudaGetSymbolAddress((void**)&wt,    g_wt);

    bf16* x3 = (bf16*)x3f;     // bf16 x3; later reused as x2s

    bf16* w_xkv   = wt;
    bf16* w_xproj = wt + 294912;
    bf16* w_wkv   = wt + 442368;
    bf16* w_wproj = wt + 737280;
    bf16* w_pw1   = wt + 884736;
    bf16* w_pw2   = wt + 1474560;

    cvtw_kernel<<<(2064384 + 255) / 256, 256>>>(xca_kv_w, xca_proj_w, wa_kv_w,
                                                wa_proj_w, pw1_w, pw2_w, wt);
    cvtx_kernel<<<(25165824 + 255) / 256, 256>>>(x, bx, uqt);

    pos_kernel<<<4096, 384>>>(pos_w, pos_b, pos);
    dwconv3_kernel<<<16 * 96, 256>>>(x, convs_w, convs_b, conv);

    // fused transpose+pos+LN: writes x3 (bf16) and lnb (bf16)
    t1ln_kernel<<<dim3(256, 16), 256>>>(conv, x, pos, ln_xca_w, ln_xca_b, x3, lnb);

    // XCA
    bg2<0,1>(lnb, w_xkv, xca_kv_b, kv, 65536, 768, 384);
    dim3 tb(32, 8);
    tk_kernel<<<dim3(128, 12, 16), tb>>>(kv, kt, 4096);
    norms2_k<<<768, 256>>>(kt, norms, 4096);
    zero_kernel<<<(589824 + 255) / 256, 256>>>(attn, 589824);
    bg2b<3>(bx, kt, attn, 96, 96, 4096, 4096, 4096, 96,
            (long)384*4096, (long)96*4096, (long)384*4096, (long)96*4096,
            (long)4*9216, 9216, 4, 64, 4);
    xca_softmax_k<<<768, 256>>>(attn, norms, xca_temp, battn);
    bg2b<1>(kv + 384, battn, b1, 4096, 96, 96, 768, 96, 384,
            (long)4096*768, 96, (long)4*9216, 9216, (long)4096*384, 96, 4, 64);
    bg2<2,1>(b1, w_xproj, xca_proj_b, lnb, 65536, 384, 384,
             x3, gamma_xca, conv_out_w, conv_out_b);

    // Window attention (wx = lnb)
    bg2<0,1>(lnb, w_wkv, wa_kv_b, kv, 65536, 768, 384);
    tk_kernel<<<dim3(32, 12, 64), tb>>>(kv, kt, 1024);
    norms2_k<<<3072, 256>>>(kt, norms, 1024);
    bg2b<0>(uqt, kt, attn, 96, 96, 1024, 1024, 1024, 96,
            (long)384*1024, (long)96*1024, (long)384*1024, (long)96*1024,
            (long)4*9216, 9216, 4, 256);
    wa_softmax_k<<<3072, 256>>>(attn, norms, battn);
    bf16* x2s = x3;   // reuse g_x3
    bg2b<1>(battn, kv + 384, x2s, 96, 1024, 96, 96, 768, 1024,
            (long)4*9216, 9216, (long)1024*768, 96,
            (long)96*1024, (long)64*96*1024, 4, 256);
    // WA proj -> bf16 (reuses b1)
    bg2<0,1>(x2s, w_wproj, wa_proj_b, b1, 65536, 384, 384);

    // fold + gather-LN (bf16 in), MLP, final residual (bf16 y in uqt)
    lng_kernel<<<65536, 128>>>(b1, ln_w, ln_b, lnb);
    bg2<1,1>(lnb, w_pw1, pw1_b, h1, 65536, 1536, 384);
    bg2<0,1>(h1, w_pw2, pw2_b, uqt, 65536, 384, 1536);
    dim3 tg2(128, 12, 16);
    final_kernel<<<tg2, tb>>>(uqt, x, gamma, out);
}

// round 13
// speedup vs baseline: 1.0386x; 1.0386x over previous
#include <cuda_runtime.h>
#include <cuda_bf16.h>
#include <cstdint>
#include <math.h>

#define FULLMASK 0xffffffffu
typedef __nv_bfloat16 bf16;
// B=16, C=384, H=W=64, N=4096, HEADS=4, HD=96

// ---------------- scratch ----------------
__device__ __align__(256) float g_conv[25165824];
__device__ __align__(256) float g_pos[1572864];
__device__ __align__(256) float g_x3[25165824];   // bf16 x3, then bf16 x2s
__device__ __align__(256) float g_attn[2359296];
__device__ __align__(256) float g_norms[24576];
__device__ __align__(256) bf16 g_bx[25165824];
__device__ __align__(256) bf16 g_lnb[25165824];
__device__ __align__(256) bf16 g_kv[50331648];
__device__ __align__(256) bf16 g_kt[25165824];
__device__ __align__(256) bf16 g_b1[25165824];    // XCA AV out -> WA proj out (bf16)
__device__ __align__(256) bf16 g_uqt[25165824];   // unfold(inp) -> MLP out y (bf16)
__device__ __align__(256) bf16 g_battn[2359296];
__device__ __align__(256) bf16 g_h1[100663296];
__device__ __align__(256) bf16 g_wt[2064384];

__global__ void zero_kernel(float* __restrict__ p, long n)
{
    long i = (long)blockIdx.x * 256 + threadIdx.x;
    if (i < n) p[i] = 0.f;
}

__global__ void cvtw_kernel(const float* __restrict__ s0, const float* __restrict__ s1,
                            const float* __restrict__ s2, const float* __restrict__ s3,
                            const float* __restrict__ s4, const float* __restrict__ s5,
                            bf16* __restrict__ out)
{
    long i = (long)blockIdx.x * 256 + threadIdx.x;
    if (i >= 2064384L) return;
    const float* s; long off;
    if (i < 294912)       { s = s0; off = i; }
    else if (i < 442368)  { s = s1; off = i - 294912; }
    else if (i < 737280)  { s = s2; off = i - 442368; }
    else if (i < 884736)  { s = s3; off = i - 737280; }
    else if (i < 1474560) { s = s4; off = i - 884736; }
    else                  { s = s5; off = i - 1474560; }
    out[i] = __float2bfloat16(s[off]);
}

__global__ void cvtx_kernel(const float* __restrict__ x, bf16* __restrict__ bx,
                            bf16* __restrict__ uqT)
{
    long idx = (long)blockIdx.x * 256 + threadIdx.x;
    if (idx >= 25165824L) return;
    float v = x[idx];
    bf16 bv = __float2bfloat16(v);
    bx[idx] = bv;
    int n = (int)(idx & 4095);
    long r = idx >> 12;
    int c = (int)(r % 384), b = (int)(r / 384);
    int hh = n >> 6, ww = n & 63;
    int q = ((hh & 1) << 1) | (ww & 1);
    int p = ((hh >> 1) << 5) | (ww >> 1);
    uqT[((long)(b * 4 + q) * 384 + c) * 1024 + p] = bv;
}

__global__ void pos_kernel(const float* __restrict__ pw, const float* __restrict__ pb,
                           float* __restrict__ pos)
{
    __shared__ float feat[64];
    int n = blockIdx.x, t = threadIdx.x;
    int hh = n >> 6, ww = n & 63;
    if (t < 64) {
        int j = t, jj = j & 31, m = jj >> 1;
        float v = (j < 32) ? (float)(hh + 1) : (float)(ww + 1);
        v = v / (64.0f + 1e-6f) * 6.283185307179586f;
        float arg = v / powf(10000.0f, (float)m / 16.0f);
        feat[j] = (jj & 1) ? cosf(arg) : sinf(arg);
    }
    __syncthreads();
    float acc = pb[t];
    const float* wr = pw + t * 64;
    #pragma unroll
    for (int j = 0; j < 64; j++) acc += feat[j] * wr[j];
    pos[(long)n * 384 + t] = acc;
}

__global__ void __launch_bounds__(256) dwconv3_kernel(
    const float* __restrict__ x, const float* __restrict__ w,
    const float* __restrict__ bias, float* __restrict__ out)
{
    __shared__ float A[66 * 66], Bb[66 * 66];
    int bc = blockIdx.x, b = bc / 96, c = bc % 96, tid = threadIdx.x;
    for (int i = tid; i < 66 * 66; i += 256) { A[i] = 0.f; Bb[i] = 0.f; }
    __syncthreads();
    const float* xp = x + ((long)b * 384 + c) * 4096;
    for (int i = tid; i < 4096; i += 256)
        A[((i >> 6) + 1) * 66 + (i & 63) + 1] = xp[i];
    __syncthreads();
    float* src = A;
    float* dst = Bb;
    #pragma unroll
    for (int ch = 0; ch < 3; ch++) {
        const float* wp = w + (ch * 96 + c) * 9;
        float bv = bias[ch * 96 + c];
        float w00 = wp[0], w01 = wp[1], w02 = wp[2];
        float w10 = wp[3], w11 = wp[4], w12 = wp[5];
        float w20 = wp[6], w21 = wp[7], w22 = wp[8];
        float* op = out + ((long)b * 384 + ch * 96 + c) * 4096;
        const float* xn = (ch < 2) ? x + ((long)b * 384 + (ch + 1) * 96 + c) * 4096 : nullptr;
        for (int i = tid; i < 4096; i += 256) {
            int r = i >> 6, cc = i & 63;
            const float* p = src + r * 66 + cc;
            float acc = bv
                + w00 * p[0]   + w01 * p[1]   + w02 * p[2]
                + w10 * p[66]  + w11 * p[67]  + w12 * p[68]
                + w20 * p[132] + w21 * p[133] + w22 * p[134];
            op[i] = acc;
            if (xn) dst[(r + 1) * 66 + cc + 1] = acc + xn[i];
        }
        __syncthreads();
        float* t = src; src = dst; dst = t;
    }
}

// ---------------- fused transpose+pos+LayerNorm ----------------
__global__ void __launch_bounds__(256) t1ln_kernel(
    const float* __restrict__ conv, const float* __restrict__ xin,
    const float* __restrict__ pos, const float* __restrict__ w,
    const float* __restrict__ bvec, bf16* __restrict__ x3, bf16* __restrict__ lnb)
{
    __shared__ float s[16 * 385];
    int n0 = blockIdx.x << 4, b = blockIdx.y, tid = threadIdx.x;
    for (int idx = tid; idx < 384 * 16; idx += 256) {
        int n = idx & 15, c = idx >> 4;
        const float* src = (c >= 288) ? xin : conv;
        float v = src[((long)b * 384 + c) * 4096 + n0 + n] + pos[(long)(n0 + n) * 384 + c];
        s[n * 385 + c] = v;
    }
    __syncthreads();
    int wid = tid >> 5, lane = tid & 31;
    #pragma unroll
    for (int r = 0; r < 2; r++) {
        int row = wid + r * 8;
        const float* sr = s + row * 385;
        float sum = 0.f, sq = 0.f;
        #pragma unroll
        for (int i = 0; i < 12; i++) {
            float v = sr[lane + i * 32];
            sum += v; sq += v * v;
        }
        #pragma unroll
        for (int o = 16; o; o >>= 1) {
            sum += __shfl_xor_sync(FULLMASK, sum, o);
            sq  += __shfl_xor_sync(FULLMASK, sq, o);
        }
        float m = sum * (1.0f / 384.0f);
        float rs = rsqrtf(sq * (1.0f / 384.0f) - m * m + 1e-6f);
        long ob = ((long)b * 4096 + n0 + row) * 384;
        #pragma unroll
        for (int i = 0; i < 12; i++) {
            int c = lane + i * 32;
            float v = sr[c];
            x3[ob + c]  = __float2bfloat16(v);
            lnb[ob + c] = __float2bfloat16((v - m) * rs * w[c] + bvec[c]);
        }
    }
}

__global__ void tk_kernel(const bf16* __restrict__ kv, bf16* __restrict__ kT, int R)
{
    __shared__ bf16 tile[32][33];
    int n0 = blockIdx.x << 5, d0 = blockIdx.y << 5, bz = blockIdx.z;
    int tx = threadIdx.x, ty = threadIdx.y;
    #pragma unroll
    for (int r = 0; r < 4; r++)
        tile[ty + r * 8][tx] = kv[((long)bz * R + n0 + ty + r * 8) * 768 + d0 + tx];
    __syncthreads();
    #pragma unroll
    for (int r = 0; r < 4; r++)
        kT[((long)bz * 384 + d0 + ty + r * 8) * R + n0 + tx] = tile[tx][ty + r * 8];
}

__global__ void norms2_k(const bf16* __restrict__ kT, float* __restrict__ norms, int R)
{
    int gw = blockIdx.x * 8 + (threadIdx.x >> 5);
    int lane = threadIdx.x & 31;
    const bf16* p = kT + (long)gw * R;
    float s = 0.f;
    for (int i = lane * 2; i < R; i += 64) {
        __nv_bfloat162 v = *(const __nv_bfloat162*)(p + i);
        float a = __bfloat162float(v.x), b = __bfloat162float(v.y);
        s += a * a + b * b;
    }
    #pragma unroll
    for (int o = 16; o; o >>= 1) s += __shfl_xor_sync(FULLMASK, s, o);
    if (lane == 0) norms[gw] = sqrtf(s);
}

__global__ void lng_kernel(const bf16* __restrict__ in, const float* __restrict__ w,
                           const float* __restrict__ bvec, bf16* __restrict__ out)
{
    int row = blockIdx.x, t = threadIdx.x;
    int b = row >> 12, n = row & 4095;
    int hh = n >> 6, ww = n & 63;
    int q = ((hh & 1) << 1) | (ww & 1);
    int p = ((hh >> 1) << 5) | (ww >> 1);
    long ibase = ((long)(b * 4 + q) * 1024 + p) * 384;
    float v0 = __bfloat162float(in[ibase + t]);
    float v1 = __bfloat162float(in[ibase + t + 128]);
    float v2 = __bfloat162float(in[ibase + t + 256]);
    float s = v0 + v1 + v2;
    float q2 = v0 * v0 + v1 * v1 + v2 * v2;
    #pragma unroll
    for (int o = 16; o; o >>= 1) {
        s += __shfl_down_sync(FULLMASK, s, o);
        q2 += __shfl_down_sync(FULLMASK, q2, o);
    }
    __shared__ float ss[4], sq[4], smean, srstd;
    int wid = t >> 5, lane = t & 31;
    if (lane == 0) { ss[wid] = s; sq[wid] = q2; }
    __syncthreads();
    if (t == 0) {
        float S = ss[0] + ss[1] + ss[2] + ss[3];
        float Q = sq[0] + sq[1] + sq[2] + sq[3];
        float m = S * (1.0f / 384.0f);
        smean = m;
        srstd = rsqrtf(Q * (1.0f / 384.0f) - m * m + 1e-6f);
    }
    __syncthreads();
    float m = smean, r = srstd;
    long ob = (long)row * 384;
    out[ob + t]       = __float2bfloat16((v0 - m) * r * w[t]       + bvec[t]);
    out[ob + t + 128] = __float2bfloat16((v1 - m) * r * w[t + 128] + bvec[t + 128]);
    out[ob + t + 256] = __float2bfloat16((v2 - m) * r * w[t + 256] + bvec[t + 256]);
}

__global__ void xca_softmax_k(const float* __restrict__ G, const float* __restrict__ norms,
                              const float* __restrict__ temp, bf16* __restrict__ P)
{
    int warp = threadIdx.x >> 5, lane = threadIdx.x & 31;
    int row = blockIdx.x * 8 + warp;
    int bh = row / 96, b = bh >> 2, h = bh & 3;
    float tv = temp[h];
    const float* g = G + (long)row * 96;
    bf16* o = P + (long)row * 96;
    const float* nb = norms + b * 384 + h * 96;
    float v[3];
    #pragma unroll
    for (int i = 0; i < 3; i++) { int d = lane + i * 32; v[i] = g[d] * tv / fmaxf(nb[d], 1e-12f); }
    float m = fmaxf(v[0], fmaxf(v[1], v[2]));
    #pragma unroll
    for (int o2 = 16; o2; o2 >>= 1) m = fmaxf(m, __shfl_xor_sync(FULLMASK, m, o2));
    float e[3], s = 0.f;
    #pragma unroll
    for (int i = 0; i < 3; i++) { e[i] = expf(v[i] - m); s += e[i]; }
    #pragma unroll
    for (int o2 = 16; o2; o2 >>= 1) s += __shfl_xor_sync(FULLMASK, s, o2);
    float inv = 1.0f / s;
    #pragma unroll
    for (int i = 0; i < 3; i++) o[lane + i * 32] = __float2bfloat16(e[i] * inv);
}

__global__ void wa_softmax_k(const float* __restrict__ G, const float* __restrict__ norms,
                             bf16* __restrict__ P)
{
    int warp = threadIdx.x >> 5, lane = threadIdx.x & 31;
    int row = blockIdx.x * 8 + warp;
    int bh = row / 96, bq = bh >> 2, h = bh & 3;
    const float* g = G + (long)row * 96;
    bf16* o = P + (long)row * 96;
    const float* nb = norms + bq * 384 + h * 96;
    float l[3];
    #pragma unroll
    for (int i = 0; i < 3; i++) { int d = lane + i * 32; l[i] = g[d] / fmaxf(nb[d], 1e-12f); }
    float m1 = fmaxf(l[0], fmaxf(l[1], l[2]));
    #pragma unroll
    for (int o2 = 16; o2; o2 >>= 1) m1 = fmaxf(m1, __shfl_xor_sync(FULLMASK, m1, o2));
    float e[3], s1 = 0.f;
    #pragma unroll
    for (int i = 0; i < 3; i++) { e[i] = expf(l[i] - m1); s1 += e[i]; }
    #pragma unroll
    for (int o2 = 16; o2; o2 >>= 1) s1 += __shfl_xor_sync(FULLMASK, s1, o2);
    float inv1 = 1.0f / s1, a[3];
    #pragma unroll
    for (int i = 0; i < 3; i++) a[i] = l[i] * 0.051031036307982884f + 0.5f * e[i] * inv1;
    float m2 = fmaxf(a[0], fmaxf(a[1], a[2]));
    #pragma unroll
    for (int o2 = 16; o2; o2 >>= 1) m2 = fmaxf(m2, __shfl_xor_sync(FULLMASK, m2, o2));
    float e2[3], s2 = 0.f;
    #pragma unroll
    for (int i = 0; i < 3; i++) { e2[i] = expf(a[i] - m2); s2 += e2[i]; }
    #pragma unroll
    for (int o2 = 16; o2; o2 >>= 1) s2 += __shfl_xor_sync(FULLMASK, s2, o2);
    float inv2 = 1.0f / s2;
    #pragma unroll
    for (int i = 0; i < 3; i++) o[lane + i * 32] = __float2bfloat16(e2[i] * inv2);
}

__global__ void final_kernel(const bf16* __restrict__ y, const float* __restrict__ xin,
                             const float* __restrict__ gamma, float* __restrict__ out)
{
    __shared__ float tile[32][33];
    int n0 = blockIdx.x << 5, c0 = blockIdx.y << 5, b = blockIdx.z;
    int tx = threadIdx.x, ty = threadIdx.y;
    #pragma unroll
    for (int r = 0; r < 4; r++)
        tile[ty + r * 8][tx] =
            __bfloat162float(y[((long)b * 4096 + n0 + ty + r * 8) * 384 + c0 + tx]);
    __syncthreads();
    #pragma unroll
    for (int r = 0; r < 4; r++) {
        int c = c0 + ty + r * 8;
        long o = ((long)b * 384 + c) * 4096 + n0 + tx;
        out[o] = xin[o] + gamma[c] * tile[tx][ty + r * 8];
    }
}

__device__ __forceinline__ void cpa16s(unsigned sa, const void* g)
{
    asm volatile("cp.async.cg.shared.global [%0], [%1], 16;\n" :: "r"(sa), "l"(g));
}

__device__ __forceinline__ void cpa16p(unsigned sa, const void* g, bool valid)
{
    int sz = valid ? 16 : 0;
    asm volatile("cp.async.cg.shared.global [%0], [%1], 16, %2;\n"
                 :: "r"(sa), "l"(g), "r"(sz));
}

__device__ __forceinline__ unsigned smem_u32(const void* p)
{
    return (unsigned)__cvta_generic_to_shared(p);
}

__device__ __forceinline__ float gelu_f(float v)
{
    return 0.5f * v * (1.0f + erff(v * 0.7071067811865476f));
}

// ============================================================================
// Big-GEMM: 128x128 CTA tile, K=64 chunks (3-buffer ring), 128 threads,
// 4 warps of 64x64.  lda=ldb=K, ldc=N; M,N mult of 128, K mult of 64.
// EPI: 0 plain, 1 GELU, 2 fused e1 scatter. OUTBF: bf16 out else fp32.
// ============================================================================
template<int EPI, int OUTBF>
__global__ void __launch_bounds__(128) bgemm2_k(
    const bf16* __restrict__ A, const bf16* __restrict__ B,
    const float* __restrict__ bias, void* __restrict__ Cg,
    int N, int K,
    const bf16* __restrict__ f1, const float* __restrict__ f2,
    const float* __restrict__ f3, const float* __restrict__ f4)
{
    extern __shared__ __align__(16) bf16 dynb[];
    const int TP = 72;                // row pitch (64 k + 8 pad); 144B stride
    const int TE = 128 * TP;          // elems per tile per matrix
    unsigned sbA = smem_u32(dynb);
    unsigned sbB = sbA + 3 * TE * 2;

    int tid = threadIdx.x;
    int m0 = blockIdx.x * 128, n0 = blockIdx.y * 128;

    float c[4][8][4];
    #pragma unroll
    for (int i = 0; i < 4; i++)
        #pragma unroll
        for (int j = 0; j < 8; j++)
            #pragma unroll
            for (int q = 0; q < 4; q++) c[i][j][q] = 0.f;

    int seg = tid & 7, rS = tid >> 3;   // 8 x 16B segs per 128B row; 16 rows per pass
    auto stage = [&](int buf, int k0) {
        #pragma unroll
        for (int ps = 0; ps < 8; ps++) {
            int row = rS + ps * 16;
            cpa16s(sbA + (buf * TE + row * TP + seg * 8) * 2,
                   A + (long)(m0 + row) * K + k0 + seg * 8);
            cpa16s(sbB + (buf * TE + row * TP + seg * 8) * 2,
                   B + (long)(n0 + row) * K + k0 + seg * 8);
        }
        asm volatile("cp.async.commit_group;\n");
    };

    int nst = K >> 6;
    stage(0, 0);
    if (nst > 1) stage(1, 64); else asm volatile("cp.async.commit_group;\n");
    if (nst > 2) stage(2, 128); else asm volatile("cp.async.commit_group;\n");

    int wid = tid >> 5, lane = tid & 31;
    int wm = (wid >> 1) * 64, wn = (wid & 1) * 64;
    int g = lane >> 2, t = lane & 3;
    int aRow = ((lane >> 3) & 1) * 8 + (lane & 7);
    int aK = (lane >> 4) * 8;
    int bRow = ((lane >> 4) & 1) * 8 + (lane & 7);
    int bK = ((lane >> 3) & 1) * 8;

    for (int s = 0; s < nst; s++) {
        asm volatile("cp.async.wait_group 2;\n");
        __syncthreads();
        int buf = s % 3;
        unsigned aT = sbA + buf * TE * 2;
        unsigned bT = sbB + buf * TE * 2;
        #pragma unroll
        for (int ks = 0; ks < 64; ks += 16) {
            unsigned af[4][4], bfm[8][2];
            #pragma unroll
            for (int im = 0; im < 4; im++) {
                unsigned addr = aT + ((wm + im * 16 + aRow) * TP + ks + aK) * 2;
                asm volatile("ldmatrix.sync.aligned.m8n8.x4.shared.b16 {%0,%1,%2,%3}, [%4];\n"
                             : "=r"(af[im][0]), "=r"(af[im][1]), "=r"(af[im][2]), "=r"(af[im][3])
                             : "r"(addr));
            }
            #pragma unroll
            for (int jp = 0; jp < 4; jp++) {
                unsigned addr = bT + ((wn + jp * 16 + bRow) * TP + ks + bK) * 2;
                asm volatile("ldmatrix.sync.aligned.m8n8.x4.shared.b16 {%0,%1,%2,%3}, [%4];\n"
                             : "=r"(bfm[2 * jp][0]), "=r"(bfm[2 * jp][1]),
                               "=r"(bfm[2 * jp + 1][0]), "=r"(bfm[2 * jp + 1][1])
                             : "r"(addr));
            }
            #pragma unroll
            for (int im = 0; im < 4; im++)
                #pragma unroll
                for (int jn = 0; jn < 8; jn++)
                    asm volatile(
                        "mma.sync.aligned.m16n8k16.row.col.f32.bf16.bf16.f32 "
                        "{%0,%1,%2,%3},{%4,%5,%6,%7},{%8,%9},{%0,%1,%2,%3};\n"
                        : "+f"(c[im][jn][0]), "+f"(c[im][jn][1]),
                          "+f"(c[im][jn][2]), "+f"(c[im][jn][3])
                        : "r"(af[im][0]), "r"(af[im][1]), "r"(af[im][2]), "r"(af[im][3]),
                          "r"(bfm[jn][0]), "r"(bfm[jn][1]));
        }
        __syncthreads();
        if (s + 3 < nst) stage((s + 3) % 3, (s + 3) << 6);
        else asm volatile("cp.async.commit_group;\n");
    }

    float* Cf = (float*)Cg;
    bf16*  Cb = (bf16*)Cg;
    #pragma unroll
    for (int im = 0; im < 4; im++) {
        int rbase = m0 + wm + im * 16 + g;
        #pragma unroll
        for (int jn = 0; jn < 8; jn++) {
            int col = n0 + wn + jn * 8 + t * 2;
            float b0 = bias ? bias[col] : 0.f;
            float b1 = bias ? bias[col + 1] : 0.f;
            #pragma unroll
            for (int hr = 0; hr < 2; hr++) {
                int rr = rbase + hr * 8;
                float v0 = c[im][jn][hr * 2 + 0] + b0;
                float v1 = c[im][jn][hr * 2 + 1] + b1;
                if (EPI == 1) { v0 = gelu_f(v0); v1 = gelu_f(v1); }
                if (EPI == 2) {
                    long rb = (long)rr * 384 + col;
                    float a0 = (__bfloat162float(f1[rb])     + f2[col]     * v0) * f3[col]     + f4[col];
                    float a1 = (__bfloat162float(f1[rb + 1]) + f2[col + 1] * v1) * f3[col + 1] + f4[col + 1];
                    int n = rr & 4095, b = rr >> 12;
                    int hh2 = n >> 6, ww2 = n & 63;
                    int q = ((hh2 & 1) << 1) | (ww2 & 1);
                    int p = ((hh2 >> 1) << 5) | (ww2 >> 1);
                    bf16* dst = Cb + ((long)(b * 4 + q) * 1024 + p) * 384 + col;
                    *(__nv_bfloat162*)dst = __floats2bfloat162_rn(a0, a1);
                } else if (OUTBF) {
                    *(__nv_bfloat162*)(Cb + (long)rr * N + col) = __floats2bfloat162_rn(v0, v1);
                } else {
                    *(float2*)(Cf + (long)rr * N + col) = make_float2(v0, v1);
                }
            }
        }
    }
}

template<int EPI, int OUTBF>
static void bg2(const bf16* A, const bf16* B, const float* bias, void* C,
                int M, int N, int K,
                const bf16* f1 = nullptr, const float* f2 = nullptr,
                const float* f3 = nullptr, const float* f4 = nullptr)
{
    cudaFuncSetAttribute(bgemm2_k<EPI, OUTBF>,
                         cudaFuncAttributeMaxDynamicSharedMemorySize, 110592);
    dim3 grid(M / 128, N / 128);
    bgemm2_k<EPI, OUTBF><<<grid, 128, 110592>>>(A, B, bias, C, N, K, f1, f2, f3, f4);
}

// ============================================================================
// Batched GEMM, 4-warp 64x64, K=32 chunks, bounds-guarded (unchanged from R11).
// OUTM: 0 fp32, 1 bf16, 3 fp32 atomicAdd (split-K)
// ============================================================================
template<int OUTM>
__global__ void __launch_bounds__(128) bg2b_k(
    const bf16* __restrict__ Ag, const bf16* __restrict__ Bg, void* __restrict__ Cg,
    int M, int N, int K, int lda, int ldb, int ldc,
    long sA1, long sA2, long sB1, long sB2, long sC1, long sC2, int HB, int SK)
{
    extern __shared__ __align__(16) bf16 dynb[];
    const int TE = 128 * 40;
    unsigned sbA = smem_u32(dynb);
    unsigned sbB = sbA + 3 * TE * 2;

    int zz = blockIdx.z;
    int ksl = zz % SK, z = zz / SK;
    int zo = z / HB, zi = z - zo * HB;
    const bf16* A = Ag + zo * sA1 + zi * sA2 + (long)ksl * K;
    const bf16* B = Bg + zo * sB1 + zi * sB2 + (long)ksl * K;

    int tid = threadIdx.x;
    int m0 = blockIdx.x * 128, n0 = blockIdx.y * 128;

    float c[4][8][4];
    #pragma unroll
    for (int i = 0; i < 4; i++)
        #pragma unroll
        for (int j = 0; j < 8; j++)
            #pragma unroll
            for (int q = 0; q < 4; q++) c[i][j][q] = 0.f;

    int seg = tid & 3, rS = tid >> 2;
    auto stage = [&](int buf, int k0) {
        #pragma unroll
        for (int ps = 0; ps < 4; ps++) {
            int row = rS + ps * 32;
            int ra = (m0 + row < M) ? m0 + row : M - 1;
            cpa16p(sbA + (buf * TE + row * 40 + seg * 8) * 2,
                   A + (long)ra * lda + k0 + seg * 8, m0 + row < M);
            int rb = (n0 + row < N) ? n0 + row : N - 1;
            cpa16p(sbB + (buf * TE + row * 40 + seg * 8) * 2,
                   B + (long)rb * ldb + k0 + seg * 8, n0 + row < N);
        }
    };

    int nst = K >> 5;
    stage(0, 0);
    asm volatile("cp.async.commit_group;\n");
    if (nst > 1) stage(1, 32);
    asm volatile("cp.async.commit_group;\n");

    int wid = tid >> 5, lane = tid & 31;
    int wm = (wid >> 1) * 64, wn = (wid & 1) * 64;
    int g = lane >> 2, t = lane & 3;
    int aRow = ((lane >> 3) & 1) * 8 + (lane & 7);
    int aK = (lane >> 4) * 8;
    int bRow = ((lane >> 4) & 1) * 8 + (lane & 7);
    int bK = ((lane >> 3) & 1) * 8;

    for (int s = 0; s < nst; s++) {
        int nf = s + 2;
        if (nf < nst) stage(nf % 3, nf << 5);
        asm volatile("cp.async.commit_group;\n");
        asm volatile("cp.async.wait_group 2;\n");
        __syncthreads();
        int buf = s % 3;
        unsigned aT = sbA + buf * TE * 2;
        unsigned bT = sbB + buf * TE * 2;
        #pragma unroll
        for (int ks = 0; ks < 32; ks += 16) {
            unsigned af[4][4], bfm[8][2];
            #pragma unroll
            for (int im = 0; im < 4; im++) {
                unsigned addr = aT + ((wm + im * 16 + aRow) * 40 + ks + aK) * 2;
                asm volatile("ldmatrix.sync.aligned.m8n8.x4.shared.b16 {%0,%1,%2,%3}, [%4];\n"
                             : "=r"(af[im][0]), "=r"(af[im][1]), "=r"(af[im][2]), "=r"(af[im][3])
                             : "r"(addr));
            }
            #pragma unroll
            for (int jp = 0; jp < 4; jp++) {
                unsigned addr = bT + ((wn + jp * 16 + bRow) * 40 + ks + bK) * 2;
                asm volatile("ldmatrix.sync.aligned.m8n8.x4.shared.b16 {%0,%1,%2,%3}, [%4];\n"
                             : "=r"(bfm[2 * jp][0]), "=r"(bfm[2 * jp][1]),
                               "=r"(bfm[2 * jp + 1][0]), "=r"(bfm[2 * jp + 1][1])
                             : "r"(addr));
            }
            #pragma unroll
            for (int im = 0; im < 4; im++)
                #pragma unroll
                for (int jn = 0; jn < 8; jn++)
                    asm volatile(
                        "mma.sync.aligned.m16n8k16.row.col.f32.bf16.bf16.f32 "
                        "{%0,%1,%2,%3},{%4,%5,%6,%7},{%8,%9},{%0,%1,%2,%3};\n"
                        : "+f"(c[im][jn][0]), "+f"(c[im][jn][1]),
                          "+f"(c[im][jn][2]), "+f"(c[im][jn][3])
                        : "r"(af[im][0]), "r"(af[im][1]), "r"(af[im][2]), "r"(af[im][3]),
                          "r"(bfm[jn][0]), "r"(bfm[jn][1]));
        }
        __syncthreads();
    }

    float* Cf = (float*)Cg + zo * sC1 + zi * sC2;
    bf16*  Cb = (bf16*)Cg + zo * sC1 + zi * sC2;
    #pragma unroll
    for (int im = 0; im < 4; im++) {
        int rbase = m0 + wm + im * 16 + g;
        #pragma unroll
        for (int jn = 0; jn < 8; jn++) {
            int col = n0 + wn + jn * 8 + t * 2;
            if (col >= N) continue;
            #pragma unroll
            for (int hr = 0; hr < 2; hr++) {
                int rr = rbase + hr * 8;
                if (rr >= M) continue;
                float v0 = c[im][jn][hr * 2 + 0];
                float v1 = c[im][jn][hr * 2 + 1];
                if (OUTM == 3) {
                    atomicAdd(&Cf[(long)rr * ldc + col], v0);
                    atomicAdd(&Cf[(long)rr * ldc + col + 1], v1);
                } else if (OUTM == 1) {
                    *(__nv_bfloat162*)(Cb + (long)rr * ldc + col) = __floats2bfloat162_rn(v0, v1);
                } else {
                    *(float2*)(Cf + (long)rr * ldc + col) = make_float2(v0, v1);
                }
            }
        }
    }
}

template<int OUTM>
static void bg2b(const bf16* A, const bf16* B, void* C,
                 int M, int N, int K, int lda, int ldb, int ldc,
                 long sA1, long sA2, long sB1, long sB2, long sC1, long sC2,
                 int HB, int Z, int SK = 1)
{
    cudaFuncSetAttribute(bg2b_k<OUTM>,
                         cudaFuncAttributeMaxDynamicSharedMemorySize, 61440);
    dim3 grid((M + 127) / 128, (N + 127) / 128, Z * SK);
    bg2b_k<OUTM><<<grid, 128, 61440>>>(A, B, C, M, N, K / SK, lda, ldb, ldc,
                                       sA1, sA2, sB1, sB2, sC1, sC2, HB, SK);
}

extern "C" void kernel_launch(void* const* d_in, const int* in_sizes, int n_in,
                              void* d_out, int out_size)
{
    const float* x          = (const float*)d_in[0];
    const float* convs_w    = (const float*)d_in[1];
    const float* convs_b    = (const float*)d_in[2];
    const float* pos_w      = (const float*)d_in[3];
    const float* pos_b      = (const float*)d_in[4];
    const float* ln_xca_w   = (const float*)d_in[5];
    const float* ln_xca_b   = (const float*)d_in[6];
    const float* gamma_xca  = (const float*)d_in[7];
    const float* xca_temp   = (const float*)d_in[8];
    const float* xca_kv_w   = (const float*)d_in[9];
    const float* xca_kv_b   = (const float*)d_in[10];
    const float* xca_proj_w = (const float*)d_in[11];
    const float* xca_proj_b = (const float*)d_in[12];
    const float* conv_out_w = (const float*)d_in[13];
    const float* conv_out_b = (const float*)d_in[14];
    const float* wa_kv_w    = (const float*)d_in[15];
    const float* wa_kv_b    = (const float*)d_in[16];
    const float* wa_proj_w  = (const float*)d_in[17];
    const float* wa_proj_b  = (const float*)d_in[18];
    const float* ln_w       = (const float*)d_in[19];
    const float* ln_b       = (const float*)d_in[20];
    const float* pw1_w      = (const float*)d_in[21];
    const float* pw1_b      = (const float*)d_in[22];
    const float* pw2_w      = (const float*)d_in[23];
    const float* pw2_b      = (const float*)d_in[24];
    const float* gamma      = (const float*)d_in[25];
    float* out = (float*)d_out;

    float *conv, *pos, *x3f, *attn, *norms;
    bf16 *bx, *lnb, *kv, *kt, *b1, *uqt, *battn, *h1, *wt;
    cudaGetSymbolAddress((void**)&conv,  g_conv);
    cudaGetSymbolAddress((void**)&pos,   g_pos);
    cudaGetSymbolAddress((void**)&x3f,   g_x3);
    cudaGetSymbolAddress((void**)&attn,  g_attn);
    cudaGetSymbolAddress((void**)&norms, g_norms);
    cudaGetSymbolAddress((void**)&bx,    g_bx);
    cudaGetSymbolAddress((void**)&lnb,   g_lnb);
    cudaGetSymbolAddress((void**)&kv,    g_kv);
    cudaGetSymbolAddress((void**)&kt,    g_kt);
    cudaGetSymbolAddress((void**)&b1,    g_b1);
    cudaGetSymbolAddress((void**)&uqt,   g_uqt);
    cudaGetSymbolAddress((void**)&battn, g_battn);
    cudaGetSymbolAddress((void**)&h1,    g_h1);
    cudaGetSymbolAddress((void**)&wt,    g_wt);

    bf16* x3 = (bf16*)x3f;

    bf16* w_xkv   = wt;
    bf16* w_xproj = wt + 294912;
    bf16* w_wkv   = wt + 442368;
    bf16* w_wproj = wt + 737280;
    bf16* w_pw1   = wt + 884736;
    bf16* w_pw2   = wt + 1474560;

    cvtw_kernel<<<(2064384 + 255) / 256, 256>>>(xca_kv_w, xca_proj_w, wa_kv_w,
                                                wa_proj_w, pw1_w, pw2_w, wt);
    cvtx_kernel<<<(25165824 + 255) / 256, 256>>>(x, bx, uqt);

    pos_kernel<<<4096, 384>>>(pos_w, pos_b, pos);
    dwconv3_kernel<<<16 * 96, 256>>>(x, convs_w, convs_b, conv);

    t1ln_kernel<<<dim3(256, 16), 256>>>(conv, x, pos, ln_xca_w, ln_xca_b, x3, lnb);

    // XCA
    bg2<0,1>(lnb, w_xkv, xca_kv_b, kv, 65536, 768, 384);
    dim3 tb(32, 8);
    tk_kernel<<<dim3(128, 12, 16), tb>>>(kv, kt, 4096);
    norms2_k<<<768, 256>>>(kt, norms, 4096);
    zero_kernel<<<(589824 + 255) / 256, 256>>>(attn, 589824);
    bg2b<3>(bx, kt, attn, 96, 96, 4096, 4096, 4096, 96,
            (long)384*4096, (long)96*4096, (long)384*4096, (long)96*4096,
            (long)4*9216, 9216, 4, 64, 4);
    xca_softmax_k<<<768, 256>>>(attn, norms, xca_temp, battn);
    bg2b<1>(kv + 384, battn, b1, 4096, 96, 96, 768, 96, 384,
            (long)4096*768, 96, (long)4*9216, 9216, (long)4096*384, 96, 4, 64);
    bg2<2,1>(b1, w_xproj, xca_proj_b, lnb, 65536, 384, 384,
             x3, gamma_xca, conv_out_w, conv_out_b);

    // Window attention (wx = lnb)
    bg2<0,1>(lnb, w_wkv, wa_kv_b, kv, 65536, 768, 384);
    tk_kernel<<<dim3(32, 12, 64), tb>>>(kv, kt, 1024);
    norms2_k<<<3072, 256>>>(kt, norms, 1024);
    bg2b<0>(uqt, kt, attn, 96, 96, 1024, 1024, 1024, 96,
            (long)384*1024, (long)96*1024, (long)384*1024, (long)96*1024,
            (long)4*9216, 9216, 4, 256);
    wa_softmax_k<<<3072, 256>>>(attn, norms, battn);
    bf16* x2s = x3;
    bg2b<1>(battn, kv + 384, x2s, 96, 1024, 96, 96, 768, 1024,
            (long)4*9216, 9216, (long)1024*768, 96,
            (long)96*1024, (long)64*96*1024, 4, 256);
    bg2<0,1>(x2s, w_wproj, wa_proj_b, b1, 65536, 384, 384);

    // fold + gather-LN, MLP, final residual
    lng_kernel<<<65536, 128>>>(b1, ln_w, ln_b, lnb);
    bg2<1,1>(lnb, w_pw1, pw1_b, h1, 65536, 1536, 384);
    bg2<0,1>(h1, w_pw2, pw2_b, uqt, 65536, 384, 1536);
    dim3 tg2(128, 12, 16);
    final_kernel<<<tg2, tb>>>(uqt, x, gamma, out);
}

// round 14
// speedup vs baseline: 1.0428x; 1.0040x over previous
#include <cuda_runtime.h>
#include <cuda_bf16.h>
#include <cstdint>
#include <math.h>

#define FULLMASK 0xffffffffu
typedef __nv_bfloat16 bf16;
// B=16, C=384, H=W=64, N=4096, HEADS=4, HD=96

// ---------------- scratch ----------------
__device__ __align__(256) float g_conv[25165824];
__device__ __align__(256) float g_pos[1572864];
__device__ __align__(256) float g_x3[25165824];   // bf16 x3, then bf16 x2s
__device__ __align__(256) float g_attn[2359296];
__device__ __align__(256) float g_norms[24576];
__device__ __align__(256) bf16 g_bx[25165824];
__device__ __align__(256) bf16 g_lnb[25165824];
__device__ __align__(256) bf16 g_kv[50331648];
__device__ __align__(256) bf16 g_kt[25165824];
__device__ __align__(256) bf16 g_b1[25165824];
__device__ __align__(256) bf16 g_uqt[25165824];
__device__ __align__(256) bf16 g_battn[2359296];
__device__ __align__(256) bf16 g_h1[100663296];
__device__ __align__(256) bf16 g_wt[2064384];

__global__ void zero_kernel(float* __restrict__ p, long n)
{
    long i = (long)blockIdx.x * 256 + threadIdx.x;
    if (i < n) p[i] = 0.f;
}

__global__ void cvtw_kernel(const float* __restrict__ s0, const float* __restrict__ s1,
                            const float* __restrict__ s2, const float* __restrict__ s3,
                            const float* __restrict__ s4, const float* __restrict__ s5,
                            bf16* __restrict__ out)
{
    long i = (long)blockIdx.x * 256 + threadIdx.x;
    if (i >= 2064384L) return;
    const float* s; long off;
    if (i < 294912)       { s = s0; off = i; }
    else if (i < 442368)  { s = s1; off = i - 294912; }
    else if (i < 737280)  { s = s2; off = i - 442368; }
    else if (i < 884736)  { s = s3; off = i - 737280; }
    else if (i < 1474560) { s = s4; off = i - 884736; }
    else                  { s = s5; off = i - 1474560; }
    out[i] = __float2bfloat16(s[off]);
}

__global__ void cvtx_kernel(const float* __restrict__ x, bf16* __restrict__ bx,
                            bf16* __restrict__ uqT)
{
    long idx = (long)blockIdx.x * 256 + threadIdx.x;
    if (idx >= 25165824L) return;
    float v = x[idx];
    bf16 bv = __float2bfloat16(v);
    bx[idx] = bv;
    int n = (int)(idx & 4095);
    long r = idx >> 12;
    int c = (int)(r % 384), b = (int)(r / 384);
    int hh = n >> 6, ww = n & 63;
    int q = ((hh & 1) << 1) | (ww & 1);
    int p = ((hh >> 1) << 5) | (ww >> 1);
    uqT[((long)(b * 4 + q) * 384 + c) * 1024 + p] = bv;
}

__global__ void pos_kernel(const float* __restrict__ pw, const float* __restrict__ pb,
                           float* __restrict__ pos)
{
    __shared__ float feat[64];
    int n = blockIdx.x, t = threadIdx.x;
    int hh = n >> 6, ww = n & 63;
    if (t < 64) {
        int j = t, jj = j & 31, m = jj >> 1;
        float v = (j < 32) ? (float)(hh + 1) : (float)(ww + 1);
        v = v / (64.0f + 1e-6f) * 6.283185307179586f;
        float arg = v / powf(10000.0f, (float)m / 16.0f);
        feat[j] = (jj & 1) ? cosf(arg) : sinf(arg);
    }
    __syncthreads();
    float acc = pb[t];
    const float* wr = pw + t * 64;
    #pragma unroll
    for (int j = 0; j < 64; j++) acc += feat[j] * wr[j];
    pos[(long)n * 384 + t] = acc;
}

__global__ void __launch_bounds__(256) dwconv3_kernel(
    const float* __restrict__ x, const float* __restrict__ w,
    const float* __restrict__ bias, float* __restrict__ out)
{
    __shared__ float A[66 * 66], Bb[66 * 66];
    int bc = blockIdx.x, b = bc / 96, c = bc % 96, tid = threadIdx.x;
    for (int i = tid; i < 66 * 66; i += 256) { A[i] = 0.f; Bb[i] = 0.f; }
    __syncthreads();
    const float* xp = x + ((long)b * 384 + c) * 4096;
    for (int i = tid; i < 4096; i += 256)
        A[((i >> 6) + 1) * 66 + (i & 63) + 1] = xp[i];
    __syncthreads();
    float* src = A;
    float* dst = Bb;
    #pragma unroll
    for (int ch = 0; ch < 3; ch++) {
        const float* wp = w + (ch * 96 + c) * 9;
        float bv = bias[ch * 96 + c];
        float w00 = wp[0], w01 = wp[1], w02 = wp[2];
        float w10 = wp[3], w11 = wp[4], w12 = wp[5];
        float w20 = wp[6], w21 = wp[7], w22 = wp[8];
        float* op = out + ((long)b * 384 + ch * 96 + c) * 4096;
        const float* xn = (ch < 2) ? x + ((long)b * 384 + (ch + 1) * 96 + c) * 4096 : nullptr;
        for (int i = tid; i < 4096; i += 256) {
            int r = i >> 6, cc = i & 63;
            const float* p = src + r * 66 + cc;
            float acc = bv
                + w00 * p[0]   + w01 * p[1]   + w02 * p[2]
                + w10 * p[66]  + w11 * p[67]  + w12 * p[68]
                + w20 * p[132] + w21 * p[133] + w22 * p[134];
            op[i] = acc;
            if (xn) dst[(r + 1) * 66 + cc + 1] = acc + xn[i];
        }
        __syncthreads();
        float* t = src; src = dst; dst = t;
    }
}

// ---------------- fused transpose+pos+LayerNorm ----------------
__global__ void __launch_bounds__(256) t1ln_kernel(
    const float* __restrict__ conv, const float* __restrict__ xin,
    const float* __restrict__ pos, const float* __restrict__ w,
    const float* __restrict__ bvec, bf16* __restrict__ x3, bf16* __restrict__ lnb)
{
    __shared__ float s[16 * 385];
    int n0 = blockIdx.x << 4, b = blockIdx.y, tid = threadIdx.x;
    for (int idx = tid; idx < 384 * 16; idx += 256) {
        int n = idx & 15, c = idx >> 4;
        const float* src = (c >= 288) ? xin : conv;
        float v = src[((long)b * 384 + c) * 4096 + n0 + n] + pos[(long)(n0 + n) * 384 + c];
        s[n * 385 + c] = v;
    }
    __syncthreads();
    int wid = tid >> 5, lane = tid & 31;
    #pragma unroll
    for (int r = 0; r < 2; r++) {
        int row = wid + r * 8;
        const float* sr = s + row * 385;
        float sum = 0.f, sq = 0.f;
        #pragma unroll
        for (int i = 0; i < 12; i++) {
            float v = sr[lane + i * 32];
            sum += v; sq += v * v;
        }
        #pragma unroll
        for (int o = 16; o; o >>= 1) {
            sum += __shfl_xor_sync(FULLMASK, sum, o);
            sq  += __shfl_xor_sync(FULLMASK, sq, o);
        }
        float m = sum * (1.0f / 384.0f);
        float rs = rsqrtf(sq * (1.0f / 384.0f) - m * m + 1e-6f);
        long ob = ((long)b * 4096 + n0 + row) * 384;
        #pragma unroll
        for (int i = 0; i < 12; i++) {
            int c = lane + i * 32;
            float v = sr[c];
            x3[ob + c]  = __float2bfloat16(v);
            lnb[ob + c] = __float2bfloat16((v - m) * rs * w[c] + bvec[c]);
        }
    }
}

__global__ void tk_kernel(const bf16* __restrict__ kv, bf16* __restrict__ kT, int R)
{
    __shared__ bf16 tile[32][33];
    int n0 = blockIdx.x << 5, d0 = blockIdx.y << 5, bz = blockIdx.z;
    int tx = threadIdx.x, ty = threadIdx.y;
    #pragma unroll
    for (int r = 0; r < 4; r++)
        tile[ty + r * 8][tx] = kv[((long)bz * R + n0 + ty + r * 8) * 768 + d0 + tx];
    __syncthreads();
    #pragma unroll
    for (int r = 0; r < 4; r++)
        kT[((long)bz * 384 + d0 + ty + r * 8) * R + n0 + tx] = tile[tx][ty + r * 8];
}

__global__ void norms2_k(const bf16* __restrict__ kT, float* __restrict__ norms, int R)
{
    int gw = blockIdx.x * 8 + (threadIdx.x >> 5);
    int lane = threadIdx.x & 31;
    const bf16* p = kT + (long)gw * R;
    float s = 0.f;
    for (int i = lane * 2; i < R; i += 64) {
        __nv_bfloat162 v = *(const __nv_bfloat162*)(p + i);
        float a = __bfloat162float(v.x), b = __bfloat162float(v.y);
        s += a * a + b * b;
    }
    #pragma unroll
    for (int o = 16; o; o >>= 1) s += __shfl_xor_sync(FULLMASK, s, o);
    if (lane == 0) norms[gw] = sqrtf(s);
}

__global__ void lng_kernel(const bf16* __restrict__ in, const float* __restrict__ w,
                           const float* __restrict__ bvec, bf16* __restrict__ out)
{
    int row = blockIdx.x, t = threadIdx.x;
    int b = row >> 12, n = row & 4095;
    int hh = n >> 6, ww = n & 63;
    int q = ((hh & 1) << 1) | (ww & 1);
    int p = ((hh >> 1) << 5) | (ww >> 1);
    long ibase = ((long)(b * 4 + q) * 1024 + p) * 384;
    float v0 = __bfloat162float(in[ibase + t]);
    float v1 = __bfloat162float(in[ibase + t + 128]);
    float v2 = __bfloat162float(in[ibase + t + 256]);
    float s = v0 + v1 + v2;
    float q2 = v0 * v0 + v1 * v1 + v2 * v2;
    #pragma unroll
    for (int o = 16; o; o >>= 1) {
        s += __shfl_down_sync(FULLMASK, s, o);
        q2 += __shfl_down_sync(FULLMASK, q2, o);
    }
    __shared__ float ss[4], sq[4], smean, srstd;
    int wid = t >> 5, lane = t & 31;
    if (lane == 0) { ss[wid] = s; sq[wid] = q2; }
    __syncthreads();
    if (t == 0) {
        float S = ss[0] + ss[1] + ss[2] + ss[3];
        float Q = sq[0] + sq[1] + sq[2] + sq[3];
        float m = S * (1.0f / 384.0f);
        smean = m;
        srstd = rsqrtf(Q * (1.0f / 384.0f) - m * m + 1e-6f);
    }
    __syncthreads();
    float m = smean, r = srstd;
    long ob = (long)row * 384;
    out[ob + t]       = __float2bfloat16((v0 - m) * r * w[t]       + bvec[t]);
    out[ob + t + 128] = __float2bfloat16((v1 - m) * r * w[t + 128] + bvec[t + 128]);
    out[ob + t + 256] = __float2bfloat16((v2 - m) * r * w[t + 256] + bvec[t + 256]);
}

__global__ void xca_softmax_k(const float* __restrict__ G, const float* __restrict__ norms,
                              const float* __restrict__ temp, bf16* __restrict__ P)
{
    int warp = threadIdx.x >> 5, lane = threadIdx.x & 31;
    int row = blockIdx.x * 8 + warp;
    int bh = row / 96, b = bh >> 2, h = bh & 3;
    float tv = temp[h];
    const float* g = G + (long)row * 96;
    bf16* o = P + (long)row * 96;
    const float* nb = norms + b * 384 + h * 96;
    float v[3];
    #pragma unroll
    for (int i = 0; i < 3; i++) { int d = lane + i * 32; v[i] = g[d] * tv / fmaxf(nb[d], 1e-12f); }
    float m = fmaxf(v[0], fmaxf(v[1], v[2]));
    #pragma unroll
    for (int o2 = 16; o2; o2 >>= 1) m = fmaxf(m, __shfl_xor_sync(FULLMASK, m, o2));
    float e[3], s = 0.f;
    #pragma unroll
    for (int i = 0; i < 3; i++) { e[i] = expf(v[i] - m); s += e[i]; }
    #pragma unroll
    for (int o2 = 16; o2; o2 >>= 1) s += __shfl_xor_sync(FULLMASK, s, o2);
    float inv = 1.0f / s;
    #pragma unroll
    for (int i = 0; i < 3; i++) o[lane + i * 32] = __float2bfloat16(e[i] * inv);
}

__global__ void wa_softmax_k(const float* __restrict__ G, const float* __restrict__ norms,
                             bf16* __restrict__ P)
{
    int warp = threadIdx.x >> 5, lane = threadIdx.x & 31;
    int row = blockIdx.x * 8 + warp;
    int bh = row / 96, bq = bh >> 2, h = bh & 3;
    const float* g = G + (long)row * 96;
    bf16* o = P + (long)row * 96;
    const float* nb = norms + bq * 384 + h * 96;
    float l[3];
    #pragma unroll
    for (int i = 0; i < 3; i++) { int d = lane + i * 32; l[i] = g[d] / fmaxf(nb[d], 1e-12f); }
    float m1 = fmaxf(l[0], fmaxf(l[1], l[2]));
    #pragma unroll
    for (int o2 = 16; o2; o2 >>= 1) m1 = fmaxf(m1, __shfl_xor_sync(FULLMASK, m1, o2));
    float e[3], s1 = 0.f;
    #pragma unroll
    for (int i = 0; i < 3; i++) { e[i] = expf(l[i] - m1); s1 += e[i]; }
    #pragma unroll
    for (int o2 = 16; o2; o2 >>= 1) s1 += __shfl_xor_sync(FULLMASK, s1, o2);
    float inv1 = 1.0f / s1, a[3];
    #pragma unroll
    for (int i = 0; i < 3; i++) a[i] = l[i] * 0.051031036307982884f + 0.5f * e[i] * inv1;
    float m2 = fmaxf(a[0], fmaxf(a[1], a[2]));
    #pragma unroll
    for (int o2 = 16; o2; o2 >>= 1) m2 = fmaxf(m2, __shfl_xor_sync(FULLMASK, m2, o2));
    float e2[3], s2 = 0.f;
    #pragma unroll
    for (int i = 0; i < 3; i++) { e2[i] = expf(a[i] - m2); s2 += e2[i]; }
    #pragma unroll
    for (int o2 = 16; o2; o2 >>= 1) s2 += __shfl_xor_sync(FULLMASK, s2, o2);
    float inv2 = 1.0f / s2;
    #pragma unroll
    for (int i = 0; i < 3; i++) o[lane + i * 32] = __float2bfloat16(e2[i] * inv2);
}

__global__ void final_kernel(const bf16* __restrict__ y, const float* __restrict__ xin,
                             const float* __restrict__ gamma, float* __restrict__ out)
{
    __shared__ float tile[32][33];
    int n0 = blockIdx.x << 5, c0 = blockIdx.y << 5, b = blockIdx.z;
    int tx = threadIdx.x, ty = threadIdx.y;
    #pragma unroll
    for (int r = 0; r < 4; r++)
        tile[ty + r * 8][tx] =
            __bfloat162float(y[((long)b * 4096 + n0 + ty + r * 8) * 384 + c0 + tx]);
    __syncthreads();
    #pragma unroll
    for (int r = 0; r < 4; r++) {
        int c = c0 + ty + r * 8;
        long o = ((long)b * 384 + c) * 4096 + n0 + tx;
        out[o] = xin[o] + gamma[c] * tile[tx][ty + r * 8];
    }
}

__device__ __forceinline__ void cpa16s(unsigned sa, const void* g)
{
    asm volatile("cp.async.cg.shared.global [%0], [%1], 16;\n" :: "r"(sa), "l"(g));
}

__device__ __forceinline__ void cpa16p(unsigned sa, const void* g, bool valid)
{
    int sz = valid ? 16 : 0;
    asm volatile("cp.async.cg.shared.global [%0], [%1], 16, %2;\n"
                 :: "r"(sa), "l"(g), "r"(sz));
}

__device__ __forceinline__ unsigned smem_u32(const void* p)
{
    return (unsigned)__cvta_generic_to_shared(p);
}

__device__ __forceinline__ float gelu_f(float v)
{
    return 0.5f * v * (1.0f + erff(v * 0.7071067811865476f));
}

// ============================================================================
// Big-GEMM: 128x128 CTA tile, K=64 chunks, 4 warps of 64x64. (R13, unchanged)
// ============================================================================
template<int EPI, int OUTBF>
__global__ void __launch_bounds__(128) bgemm2_k(
    const bf16* __restrict__ A, const bf16* __restrict__ B,
    const float* __restrict__ bias, void* __restrict__ Cg,
    int N, int K,
    const bf16* __restrict__ f1, const float* __restrict__ f2,
    const float* __restrict__ f3, const float* __restrict__ f4)
{
    extern __shared__ __align__(16) bf16 dynb[];
    const int TP = 72;
    const int TE = 128 * TP;
    unsigned sbA = smem_u32(dynb);
    unsigned sbB = sbA + 3 * TE * 2;

    int tid = threadIdx.x;
    int m0 = blockIdx.x * 128, n0 = blockIdx.y * 128;

    float c[4][8][4];
    #pragma unroll
    for (int i = 0; i < 4; i++)
        #pragma unroll
        for (int j = 0; j < 8; j++)
            #pragma unroll
            for (int q = 0; q < 4; q++) c[i][j][q] = 0.f;

    int seg = tid & 7, rS = tid >> 3;
    auto stage = [&](int buf, int k0) {
        #pragma unroll
        for (int ps = 0; ps < 8; ps++) {
            int row = rS + ps * 16;
            cpa16s(sbA + (buf * TE + row * TP + seg * 8) * 2,
                   A + (long)(m0 + row) * K + k0 + seg * 8);
            cpa16s(sbB + (buf * TE + row * TP + seg * 8) * 2,
                   B + (long)(n0 + row) * K + k0 + seg * 8);
        }
        asm volatile("cp.async.commit_group;\n");
    };

    int nst = K >> 6;
    stage(0, 0);
    if (nst > 1) stage(1, 64); else asm volatile("cp.async.commit_group;\n");
    if (nst > 2) stage(2, 128); else asm volatile("cp.async.commit_group;\n");

    int wid = tid >> 5, lane = tid & 31;
    int wm = (wid >> 1) * 64, wn = (wid & 1) * 64;
    int g = lane >> 2, t = lane & 3;
    int aRow = ((lane >> 3) & 1) * 8 + (lane & 7);
    int aK = (lane >> 4) * 8;
    int bRow = ((lane >> 4) & 1) * 8 + (lane & 7);
    int bK = ((lane >> 3) & 1) * 8;

    for (int s = 0; s < nst; s++) {
        asm volatile("cp.async.wait_group 2;\n");
        __syncthreads();
        int buf = s % 3;
        unsigned aT = sbA + buf * TE * 2;
        unsigned bT = sbB + buf * TE * 2;
        #pragma unroll
        for (int ks = 0; ks < 64; ks += 16) {
            unsigned af[4][4], bfm[8][2];
            #pragma unroll
            for (int im = 0; im < 4; im++) {
                unsigned addr = aT + ((wm + im * 16 + aRow) * TP + ks + aK) * 2;
                asm volatile("ldmatrix.sync.aligned.m8n8.x4.shared.b16 {%0,%1,%2,%3}, [%4];\n"
                             : "=r"(af[im][0]), "=r"(af[im][1]), "=r"(af[im][2]), "=r"(af[im][3])
                             : "r"(addr));
            }
            #pragma unroll
            for (int jp = 0; jp < 4; jp++) {
                unsigned addr = bT + ((wn + jp * 16 + bRow) * TP + ks + bK) * 2;
                asm volatile("ldmatrix.sync.aligned.m8n8.x4.shared.b16 {%0,%1,%2,%3}, [%4];\n"
                             : "=r"(bfm[2 * jp][0]), "=r"(bfm[2 * jp][1]),
                               "=r"(bfm[2 * jp + 1][0]), "=r"(bfm[2 * jp + 1][1])
                             : "r"(addr));
            }
            #pragma unroll
            for (int im = 0; im < 4; im++)
                #pragma unroll
                for (int jn = 0; jn < 8; jn++)
                    asm volatile(
                        "mma.sync.aligned.m16n8k16.row.col.f32.bf16.bf16.f32 "
                        "{%0,%1,%2,%3},{%4,%5,%6,%7},{%8,%9},{%0,%1,%2,%3};\n"
                        : "+f"(c[im][jn][0]), "+f"(c[im][jn][1]),
                          "+f"(c[im][jn][2]), "+f"(c[im][jn][3])
                        : "r"(af[im][0]), "r"(af[im][1]), "r"(af[im][2]), "r"(af[im][3]),
                          "r"(bfm[jn][0]), "r"(bfm[jn][1]));
        }
        __syncthreads();
        if (s + 3 < nst) stage((s + 3) % 3, (s + 3) << 6);
        else asm volatile("cp.async.commit_group;\n");
    }

    float* Cf = (float*)Cg;
    bf16*  Cb = (bf16*)Cg;
    #pragma unroll
    for (int im = 0; im < 4; im++) {
        int rbase = m0 + wm + im * 16 + g;
        #pragma unroll
        for (int jn = 0; jn < 8; jn++) {
            int col = n0 + wn + jn * 8 + t * 2;
            float b0 = bias ? bias[col] : 0.f;
            float b1 = bias ? bias[col + 1] : 0.f;
            #pragma unroll
            for (int hr = 0; hr < 2; hr++) {
                int rr = rbase + hr * 8;
                float v0 = c[im][jn][hr * 2 + 0] + b0;
                float v1 = c[im][jn][hr * 2 + 1] + b1;
                if (EPI == 1) { v0 = gelu_f(v0); v1 = gelu_f(v1); }
                if (EPI == 2) {
                    long rb = (long)rr * 384 + col;
                    float a0 = (__bfloat162float(f1[rb])     + f2[col]     * v0) * f3[col]     + f4[col];
                    float a1 = (__bfloat162float(f1[rb + 1]) + f2[col + 1] * v1) * f3[col + 1] + f4[col + 1];
                    int n = rr & 4095, b = rr >> 12;
                    int hh2 = n >> 6, ww2 = n & 63;
                    int q = ((hh2 & 1) << 1) | (ww2 & 1);
                    int p = ((hh2 >> 1) << 5) | (ww2 >> 1);
                    bf16* dst = Cb + ((long)(b * 4 + q) * 1024 + p) * 384 + col;
                    *(__nv_bfloat162*)dst = __floats2bfloat162_rn(a0, a1);
                } else if (OUTBF) {
                    *(__nv_bfloat162*)(Cb + (long)rr * N + col) = __floats2bfloat162_rn(v0, v1);
                } else {
                    *(float2*)(Cf + (long)rr * N + col) = make_float2(v0, v1);
                }
            }
        }
    }
}

template<int EPI, int OUTBF>
static void bg2(const bf16* A, const bf16* B, const float* bias, void* C,
                int M, int N, int K,
                const bf16* f1 = nullptr, const float* f2 = nullptr,
                const float* f3 = nullptr, const float* f4 = nullptr)
{
    cudaFuncSetAttribute(bgemm2_k<EPI, OUTBF>,
                         cudaFuncAttributeMaxDynamicSharedMemorySize, 110592);
    dim3 grid(M / 128, N / 128);
    bgemm2_k<EPI, OUTBF><<<grid, 128, 110592>>>(A, B, bias, C, N, K, f1, f2, f3, f4);
}

// ============================================================================
// Batched GEMM, 4-warp 64x64, templated chunk KCH in {32,64}, bounds-guarded.
// OUTM: 0 fp32, 1 bf16, 3 fp32 atomicAdd (split-K)
// ============================================================================
template<int OUTM, int KCH>
__global__ void __launch_bounds__(128) bg2b_k(
    const bf16* __restrict__ Ag, const bf16* __restrict__ Bg, void* __restrict__ Cg,
    int M, int N, int K, int lda, int ldb, int ldc,
    long sA1, long sA2, long sB1, long sB2, long sC1, long sC2, int HB, int SK)
{
    extern __shared__ __align__(16) bf16 dynb[];
    const int TP = (KCH == 64) ? 72 : 40;
    const int TE = 128 * TP;
    const int SEGS = KCH / 8;            // 16B segs per row
    const int ROWSP = 128 / (128 / SEGS);// rows per pass = SEGS*... compute below
    const int PASSES = 128 / (128 / SEGS);
    unsigned sbA = smem_u32(dynb);
    unsigned sbB = sbA + 3 * TE * 2;

    int zz = blockIdx.z;
    int ksl = zz % SK, z = zz / SK;
    int zo = z / HB, zi = z - zo * HB;
    const bf16* A = Ag + zo * sA1 + zi * sA2 + (long)ksl * K;
    const bf16* B = Bg + zo * sB1 + zi * sB2 + (long)ksl * K;

    int tid = threadIdx.x;
    int m0 = blockIdx.x * 128, n0 = blockIdx.y * 128;

    float c[4][8][4];
    #pragma unroll
    for (int i = 0; i < 4; i++)
        #pragma unroll
        for (int j = 0; j < 8; j++)
            #pragma unroll
            for (int q = 0; q < 4; q++) c[i][j][q] = 0.f;

    int seg = tid & (SEGS - 1);
    int rS = tid / SEGS;
    const int RPP = 128 / (128 / SEGS);  // rows covered per pass = threads/SEGS
    auto stage = [&](int buf, int k0) {
        #pragma unroll
        for (int row = rS; row < 128; row += 128 / SEGS) {
            int ra = (m0 + row < M) ? m0 + row : M - 1;
            cpa16p(sbA + (buf * TE + row * TP + seg * 8) * 2,
                   A + (long)ra * lda + k0 + seg * 8, m0 + row < M);
            int rb = (n0 + row < N) ? n0 + row : N - 1;
            cpa16p(sbB + (buf * TE + row * TP + seg * 8) * 2,
                   B + (long)rb * ldb + k0 + seg * 8, n0 + row < N);
        }
        asm volatile("cp.async.commit_group;\n");
    };

    int nst = K / KCH;
    stage(0, 0);
    if (nst > 1) stage(1, KCH); else asm volatile("cp.async.commit_group;\n");
    if (nst > 2) stage(2, 2 * KCH); else asm volatile("cp.async.commit_group;\n");

    int wid = tid >> 5, lane = tid & 31;
    int wm = (wid >> 1) * 64, wn = (wid & 1) * 64;
    int g = lane >> 2, t = lane & 3;
    int aRow = ((lane >> 3) & 1) * 8 + (lane & 7);
    int aK = (lane >> 4) * 8;
    int bRow = ((lane >> 4) & 1) * 8 + (lane & 7);
    int bK = ((lane >> 3) & 1) * 8;

    for (int s = 0; s < nst; s++) {
        asm volatile("cp.async.wait_group 2;\n");
        __syncthreads();
        int buf = s % 3;
        unsigned aT = sbA + buf * TE * 2;
        unsigned bT = sbB + buf * TE * 2;
        #pragma unroll
        for (int ks = 0; ks < KCH; ks += 16) {
            unsigned af[4][4], bfm[8][2];
            #pragma unroll
            for (int im = 0; im < 4; im++) {
                unsigned addr = aT + ((wm + im * 16 + aRow) * TP + ks + aK) * 2;
                asm volatile("ldmatrix.sync.aligned.m8n8.x4.shared.b16 {%0,%1,%2,%3}, [%4];\n"
                             : "=r"(af[im][0]), "=r"(af[im][1]), "=r"(af[im][2]), "=r"(af[im][3])
                             : "r"(addr));
            }
            #pragma unroll
            for (int jp = 0; jp < 4; jp++) {
                unsigned addr = bT + ((wn + jp * 16 + bRow) * TP + ks + bK) * 2;
                asm volatile("ldmatrix.sync.aligned.m8n8.x4.shared.b16 {%0,%1,%2,%3}, [%4];\n"
                             : "=r"(bfm[2 * jp][0]), "=r"(bfm[2 * jp][1]),
                               "=r"(bfm[2 * jp + 1][0]), "=r"(bfm[2 * jp + 1][1])
                             : "r"(addr));
            }
            #pragma unroll
            for (int im = 0; im < 4; im++)
                #pragma unroll
                for (int jn = 0; jn < 8; jn++)
                    asm volatile(
                        "mma.sync.aligned.m16n8k16.row.col.f32.bf16.bf16.f32 "
                        "{%0,%1,%2,%3},{%4,%5,%6,%7},{%8,%9},{%0,%1,%2,%3};\n"
                        : "+f"(c[im][jn][0]), "+f"(c[im][jn][1]),
                          "+f"(c[im][jn][2]), "+f"(c[im][jn][3])
                        : "r"(af[im][0]), "r"(af[im][1]), "r"(af[im][2]), "r"(af[im][3]),
                          "r"(bfm[jn][0]), "r"(bfm[jn][1]));
        }
        __syncthreads();
        if (s + 3 < nst) stage((s + 3) % 3, (s + 3) * KCH);
        else asm volatile("cp.async.commit_group;\n");
    }

    float* Cf = (float*)Cg + zo * sC1 + zi * sC2;
    bf16*  Cb = (bf16*)Cg + zo * sC1 + zi * sC2;
    #pragma unroll
    for (int im = 0; im < 4; im++) {
        int rbase = m0 + wm + im * 16 + g;
        #pragma unroll
        for (int jn = 0; jn < 8; jn++) {
            int col = n0 + wn + jn * 8 + t * 2;
            if (col >= N) continue;
            #pragma unroll
            for (int hr = 0; hr < 2; hr++) {
                int rr = rbase + hr * 8;
                if (rr >= M) continue;
                float v0 = c[im][jn][hr * 2 + 0];
                float v1 = c[im][jn][hr * 2 + 1];
                if (OUTM == 3) {
                    atomicAdd(&Cf[(long)rr * ldc + col], v0);
                    atomicAdd(&Cf[(long)rr * ldc + col + 1], v1);
                } else if (OUTM == 1) {
                    *(__nv_bfloat162*)(Cb + (long)rr * ldc + col) = __floats2bfloat162_rn(v0, v1);
                } else {
                    *(float2*)(Cf + (long)rr * ldc + col) = make_float2(v0, v1);
                }
            }
        }
    }
}

template<int OUTM, int KCH>
static void bg2b(const bf16* A, const bf16* B, void* C,
                 int M, int N, int K, int lda, int ldb, int ldc,
                 long sA1, long sA2, long sB1, long sB2, long sC1, long sC2,
                 int HB, int Z, int SK = 1)
{
    int smem = (KCH == 64) ? 110592 : 61440;
    cudaFuncSetAttribute(bg2b_k<OUTM, KCH>,
                         cudaFuncAttributeMaxDynamicSharedMemorySize, smem);
    dim3 grid((M + 127) / 128, (N + 127) / 128, Z * SK);
    bg2b_k<OUTM, KCH><<<grid, 128, smem>>>(A, B, C, M, N, K / SK, lda, ldb, ldc,
                                           sA1, sA2, sB1, sB2, sC1, sC2, HB, SK);
}

extern "C" void kernel_launch(void* const* d_in, const int* in_sizes, int n_in,
                              void* d_out, int out_size)
{
    const float* x          = (const float*)d_in[0];
    const float* convs_w    = (const float*)d_in[1];
    const float* convs_b    = (const float*)d_in[2];
    const float* pos_w      = (const float*)d_in[3];
    const float* pos_b      = (const float*)d_in[4];
    const float* ln_xca_w   = (const float*)d_in[5];
    const float* ln_xca_b   = (const float*)d_in[6];
    const float* gamma_xca  = (const float*)d_in[7];
    const float* xca_temp   = (const float*)d_in[8];
    const float* xca_kv_w   = (const float*)d_in[9];
    const float* xca_kv_b   = (const float*)d_in[10];
    const float* xca_proj_w = (const float*)d_in[11];
    const float* xca_proj_b = (const float*)d_in[12];
    const float* conv_out_w = (const float*)d_in[13];
    const float* conv_out_b = (const float*)d_in[14];
    const float* wa_kv_w    = (const float*)d_in[15];
    const float* wa_kv_b    = (const float*)d_in[16];
    const float* wa_proj_w  = (const float*)d_in[17];
    const float* wa_proj_b  = (const float*)d_in[18];
    const float* ln_w       = (const float*)d_in[19];
    const float* ln_b       = (const float*)d_in[20];
    const float* pw1_w      = (const float*)d_in[21];
    const float* pw1_b      = (const float*)d_in[22];
    const float* pw2_w      = (const float*)d_in[23];
    const float* pw2_b      = (const float*)d_in[24];
    const float* gamma      = (const float*)d_in[25];
    float* out = (float*)d_out;

    float *conv, *pos, *x3f, *attn, *norms;
    bf16 *bx, *lnb, *kv, *kt, *b1, *uqt, *battn, *h1, *wt;
    cudaGetSymbolAddress((void**)&conv,  g_conv);
    cudaGetSymbolAddress((void**)&pos,   g_pos);
    cudaGetSymbolAddress((void**)&x3f,   g_x3);
    cudaGetSymbolAddress((void**)&attn,  g_attn);
    cudaGetSymbolAddress((void**)&norms, g_norms);
    cudaGetSymbolAddress((void**)&bx,    g_bx);
    cudaGetSymbolAddress((void**)&lnb,   g_lnb);
    cudaGetSymbolAddress((void**)&kv,    g_kv);
    cudaGetSymbolAddress((void**)&kt,    g_kt);
    cudaGetSymbolAddress((void**)&b1,    g_b1);
    cudaGetSymbolAddress((void**)&uqt,   g_uqt);
    cudaGetSymbolAddress((void**)&battn, g_battn);
    cudaGetSymbolAddress((void**)&h1,    g_h1);
    cudaGetSymbolAddress((void**)&wt,    g_wt);

    bf16* x3 = (bf16*)x3f;

    bf16* w_xkv   = wt;
    bf16* w_xproj = wt + 294912;
    bf16* w_wkv   = wt + 442368;
    bf16* w_wproj = wt + 737280;
    bf16* w_pw1   = wt + 884736;
    bf16* w_pw2   = wt + 1474560;

    cvtw_kernel<<<(2064384 + 255) / 256, 256>>>(xca_kv_w, xca_proj_w, wa_kv_w,
                                                wa_proj_w, pw1_w, pw2_w, wt);
    cvtx_kernel<<<(25165824 + 255) / 256, 256>>>(x, bx, uqt);

    pos_kernel<<<4096, 384>>>(pos_w, pos_b, pos);
    dwconv3_kernel<<<16 * 96, 256>>>(x, convs_w, convs_b, conv);

    t1ln_kernel<<<dim3(256, 16), 256>>>(conv, x, pos, ln_xca_w, ln_xca_b, x3, lnb);

    // XCA
    bg2<0,1>(lnb, w_xkv, xca_kv_b, kv, 65536, 768, 384);
    dim3 tb(32, 8);
    tk_kernel<<<dim3(128, 12, 16), tb>>>(kv, kt, 4096);
    norms2_k<<<768, 256>>>(kt, norms, 4096);
    zero_kernel<<<(589824 + 255) / 256, 256>>>(attn, 589824);
    bg2b<3,64>(bx, kt, attn, 96, 96, 4096, 4096, 4096, 96,
               (long)384*4096, (long)96*4096, (long)384*4096, (long)96*4096,
               (long)4*9216, 9216, 4, 64, 4);
    xca_softmax_k<<<768, 256>>>(attn, norms, xca_temp, battn);
    bg2b<1,32>(kv + 384, battn, b1, 4096, 96, 96, 768, 96, 384,
               (long)4096*768, 96, (long)4*9216, 9216, (long)4096*384, 96, 4, 64);
    bg2<2,1>(b1, w_xproj, xca_proj_b, lnb, 65536, 384, 384,
             x3, gamma_xca, conv_out_w, conv_out_b);

    // Window attention (wx = lnb)
    bg2<0,1>(lnb, w_wkv, wa_kv_b, kv, 65536, 768, 384);
    tk_kernel<<<dim3(32, 12, 64), tb>>>(kv, kt, 1024);
    norms2_k<<<3072, 256>>>(kt, norms, 1024);
    bg2b<0,64>(uqt, kt, attn, 96, 96, 1024, 1024, 1024, 96,
               (long)384*1024, (long)96*1024, (long)384*1024, (long)96*1024,
               (long)4*9216, 9216, 4, 256);
    wa_softmax_k<<<3072, 256>>>(attn, norms, battn);
    bf16* x2s = x3;
    bg2b<1,32>(battn, kv + 384, x2s, 96, 1024, 96, 96, 768, 1024,
               (long)4*9216, 9216, (long)1024*768, 96,
               (long)96*1024, (long)64*96*1024, 4, 256);
    bg2<0,1>(x2s, w_wproj, wa_proj_b, b1, 65536, 384, 384);

    // fold + gather-LN, MLP, final residual
    lng_kernel<<<65536, 128>>>(b1, ln_w, ln_b, lnb);
    bg2<1,1>(lnb, w_pw1, pw1_b, h1, 65536, 1536, 384);
    bg2<0,1>(h1, w_pw2, pw2_b, uqt, 65536, 384, 1536);
    dim3 tg2(128, 12, 16);
    final_kernel<<<tg2, tb>>>(uqt, x, gamma, out);
}

// round 15
// speedup vs baseline: 1.0452x; 1.0023x over previous
#include <cuda_runtime.h>
#include <cuda_bf16.h>
#include <cstdint>
#include <math.h>

#define FULLMASK 0xffffffffu
typedef __nv_bfloat16 bf16;
// B=16, C=384, H=W=64, N=4096, HEADS=4, HD=96

// ---------------- scratch ----------------
__device__ __align__(256) float g_conv[25165824];
__device__ __align__(256) float g_pos[1572864];
__device__ __align__(256) float g_x3[25165824];   // bf16 x3, then bf16 x2s
__device__ __align__(256) float g_attn[2359296];
__device__ __align__(256) float g_norms[24576];
__device__ __align__(256) bf16 g_bx[25165824];
__device__ __align__(256) bf16 g_lnb[25165824];
__device__ __align__(256) bf16 g_kv[50331648];
__device__ __align__(256) bf16 g_kt[25165824];
__device__ __align__(256) bf16 g_b1[25165824];
__device__ __align__(256) bf16 g_uqt[25165824];
__device__ __align__(256) bf16 g_battn[2359296];
__device__ __align__(256) bf16 g_h1[100663296];
__device__ __align__(256) bf16 g_wt[2064384];

__global__ void zero_kernel(float* __restrict__ p, long n)
{
    long i = (long)blockIdx.x * 256 + threadIdx.x;
    if (i < n) p[i] = 0.f;
}

__global__ void cvtw_kernel(const float* __restrict__ s0, const float* __restrict__ s1,
                            const float* __restrict__ s2, const float* __restrict__ s3,
                            const float* __restrict__ s4, const float* __restrict__ s5,
                            bf16* __restrict__ out)
{
    long i = (long)blockIdx.x * 256 + threadIdx.x;
    if (i >= 2064384L) return;
    const float* s; long off;
    if (i < 294912)       { s = s0; off = i; }
    else if (i < 442368)  { s = s1; off = i - 294912; }
    else if (i < 737280)  { s = s2; off = i - 442368; }
    else if (i < 884736)  { s = s3; off = i - 737280; }
    else if (i < 1474560) { s = s4; off = i - 884736; }
    else                  { s = s5; off = i - 1474560; }
    out[i] = __float2bfloat16(s[off]);
}

__global__ void cvtx_kernel(const float* __restrict__ x, bf16* __restrict__ bx,
                            bf16* __restrict__ uqT)
{
    long idx = (long)blockIdx.x * 256 + threadIdx.x;
    if (idx >= 25165824L) return;
    float v = x[idx];
    bf16 bv = __float2bfloat16(v);
    bx[idx] = bv;
    int n = (int)(idx & 4095);
    long r = idx >> 12;
    int c = (int)(r % 384), b = (int)(r / 384);
    int hh = n >> 6, ww = n & 63;
    int q = ((hh & 1) << 1) | (ww & 1);
    int p = ((hh >> 1) << 5) | (ww >> 1);
    uqT[((long)(b * 4 + q) * 384 + c) * 1024 + p] = bv;
}

__global__ void pos_kernel(const float* __restrict__ pw, const float* __restrict__ pb,
                           float* __restrict__ pos)
{
    __shared__ float feat[64];
    int n = blockIdx.x, t = threadIdx.x;
    int hh = n >> 6, ww = n & 63;
    if (t < 64) {
        int j = t, jj = j & 31, m = jj >> 1;
        float v = (j < 32) ? (float)(hh + 1) : (float)(ww + 1);
        v = v / (64.0f + 1e-6f) * 6.283185307179586f;
        float arg = v / powf(10000.0f, (float)m / 16.0f);
        feat[j] = (jj & 1) ? cosf(arg) : sinf(arg);
    }
    __syncthreads();
    float acc = pb[t];
    const float* wr = pw + t * 64;
    #pragma unroll
    for (int j = 0; j < 64; j++) acc += feat[j] * wr[j];
    pos[(long)n * 384 + t] = acc;
}

__global__ void __launch_bounds__(256) dwconv3_kernel(
    const float* __restrict__ x, const float* __restrict__ w,
    const float* __restrict__ bias, float* __restrict__ out)
{
    __shared__ float A[66 * 66], Bb[66 * 66];
    int bc = blockIdx.x, b = bc / 96, c = bc % 96, tid = threadIdx.x;
    for (int i = tid; i < 66 * 66; i += 256) { A[i] = 0.f; Bb[i] = 0.f; }
    __syncthreads();
    const float* xp = x + ((long)b * 384 + c) * 4096;
    for (int i = tid; i < 4096; i += 256)
        A[((i >> 6) + 1) * 66 + (i & 63) + 1] = xp[i];
    __syncthreads();
    float* src = A;
    float* dst = Bb;
    #pragma unroll
    for (int ch = 0; ch < 3; ch++) {
        const float* wp = w + (ch * 96 + c) * 9;
        float bv = bias[ch * 96 + c];
        float w00 = wp[0], w01 = wp[1], w02 = wp[2];
        float w10 = wp[3], w11 = wp[4], w12 = wp[5];
        float w20 = wp[6], w21 = wp[7], w22 = wp[8];
        float* op = out + ((long)b * 384 + ch * 96 + c) * 4096;
        const float* xn = (ch < 2) ? x + ((long)b * 384 + (ch + 1) * 96 + c) * 4096 : nullptr;
        for (int i = tid; i < 4096; i += 256) {
            int r = i >> 6, cc = i & 63;
            const float* p = src + r * 66 + cc;
            float acc = bv
                + w00 * p[0]   + w01 * p[1]   + w02 * p[2]
                + w10 * p[66]  + w11 * p[67]  + w12 * p[68]
                + w20 * p[132] + w21 * p[133] + w22 * p[134];
            op[i] = acc;
            if (xn) dst[(r + 1) * 66 + cc + 1] = acc + xn[i];
        }
        __syncthreads();
        float* t = src; src = dst; dst = t;
    }
}

// ---------------- fused transpose+pos+LayerNorm ----------------
__global__ void __launch_bounds__(256) t1ln_kernel(
    const float* __restrict__ conv, const float* __restrict__ xin,
    const float* __restrict__ pos, const float* __restrict__ w,
    const float* __restrict__ bvec, bf16* __restrict__ x3, bf16* __restrict__ lnb)
{
    __shared__ float s[16 * 385];
    int n0 = blockIdx.x << 4, b = blockIdx.y, tid = threadIdx.x;
    for (int idx = tid; idx < 384 * 16; idx += 256) {
        int n = idx & 15, c = idx >> 4;
        const float* src = (c >= 288) ? xin : conv;
        float v = src[((long)b * 384 + c) * 4096 + n0 + n] + pos[(long)(n0 + n) * 384 + c];
        s[n * 385 + c] = v;
    }
    __syncthreads();
    int wid = tid >> 5, lane = tid & 31;
    #pragma unroll
    for (int r = 0; r < 2; r++) {
        int row = wid + r * 8;
        const float* sr = s + row * 385;
        float sum = 0.f, sq = 0.f;
        #pragma unroll
        for (int i = 0; i < 12; i++) {
            float v = sr[lane + i * 32];
            sum += v; sq += v * v;
        }
        #pragma unroll
        for (int o = 16; o; o >>= 1) {
            sum += __shfl_xor_sync(FULLMASK, sum, o);
            sq  += __shfl_xor_sync(FULLMASK, sq, o);
        }
        float m = sum * (1.0f / 384.0f);
        float rs = rsqrtf(sq * (1.0f / 384.0f) - m * m + 1e-6f);
        long ob = ((long)b * 4096 + n0 + row) * 384;
        #pragma unroll
        for (int i = 0; i < 12; i++) {
            int c = lane + i * 32;
            float v = sr[c];
            x3[ob + c]  = __float2bfloat16(v);
            lnb[ob + c] = __float2bfloat16((v - m) * rs * w[c] + bvec[c]);
        }
    }
}

__global__ void tk_kernel(const bf16* __restrict__ kv, bf16* __restrict__ kT, int R)
{
    __shared__ bf16 tile[32][33];
    int n0 = blockIdx.x << 5, d0 = blockIdx.y << 5, bz = blockIdx.z;
    int tx = threadIdx.x, ty = threadIdx.y;
    #pragma unroll
    for (int r = 0; r < 4; r++)
        tile[ty + r * 8][tx] = kv[((long)bz * R + n0 + ty + r * 8) * 768 + d0 + tx];
    __syncthreads();
    #pragma unroll
    for (int r = 0; r < 4; r++)
        kT[((long)bz * 384 + d0 + ty + r * 8) * R + n0 + tx] = tile[tx][ty + r * 8];
}

__global__ void norms2_k(const bf16* __restrict__ kT, float* __restrict__ norms, int R)
{
    int gw = blockIdx.x * 8 + (threadIdx.x >> 5);
    int lane = threadIdx.x & 31;
    const bf16* p = kT + (long)gw * R;
    float s = 0.f;
    for (int i = lane * 2; i < R; i += 64) {
        __nv_bfloat162 v = *(const __nv_bfloat162*)(p + i);
        float a = __bfloat162float(v.x), b = __bfloat162float(v.y);
        s += a * a + b * b;
    }
    #pragma unroll
    for (int o = 16; o; o >>= 1) s += __shfl_xor_sync(FULLMASK, s, o);
    if (lane == 0) norms[gw] = sqrtf(s);
}

__global__ void lng_kernel(const bf16* __restrict__ in, const float* __restrict__ w,
                           const float* __restrict__ bvec, bf16* __restrict__ out)
{
    int row = blockIdx.x, t = threadIdx.x;
    int b = row >> 12, n = row & 4095;
    int hh = n >> 6, ww = n & 63;
    int q = ((hh & 1) << 1) | (ww & 1);
    int p = ((hh >> 1) << 5) | (ww >> 1);
    long ibase = ((long)(b * 4 + q) * 1024 + p) * 384;
    float v0 = __bfloat162float(in[ibase + t]);
    float v1 = __bfloat162float(in[ibase + t + 128]);
    float v2 = __bfloat162float(in[ibase + t + 256]);
    float s = v0 + v1 + v2;
    float q2 = v0 * v0 + v1 * v1 + v2 * v2;
    #pragma unroll
    for (int o = 16; o; o >>= 1) {
        s += __shfl_down_sync(FULLMASK, s, o);
        q2 += __shfl_down_sync(FULLMASK, q2, o);
    }
    __shared__ float ss[4], sq[4], smean, srstd;
    int wid = t >> 5, lane = t & 31;
    if (lane == 0) { ss[wid] = s; sq[wid] = q2; }
    __syncthreads();
    if (t == 0) {
        float S = ss[0] + ss[1] + ss[2] + ss[3];
        float Q = sq[0] + sq[1] + sq[2] + sq[3];
        float m = S * (1.0f / 384.0f);
        smean = m;
        srstd = rsqrtf(Q * (1.0f / 384.0f) - m * m + 1e-6f);
    }
    __syncthreads();
    float m = smean, r = srstd;
    long ob = (long)row * 384;
    out[ob + t]       = __float2bfloat16((v0 - m) * r * w[t]       + bvec[t]);
    out[ob + t + 128] = __float2bfloat16((v1 - m) * r * w[t + 128] + bvec[t + 128]);
    out[ob + t + 256] = __float2bfloat16((v2 - m) * r * w[t + 256] + bvec[t + 256]);
}

__global__ void xca_softmax_k(const float* __restrict__ G, const float* __restrict__ norms,
                              const float* __restrict__ temp, bf16* __restrict__ P)
{
    int warp = threadIdx.x >> 5, lane = threadIdx.x & 31;
    int row = blockIdx.x * 8 + warp;
    int bh = row / 96, b = bh >> 2, h = bh & 3;
    float tv = temp[h];
    const float* g = G + (long)row * 96;
    bf16* o = P + (long)row * 96;
    const float* nb = norms + b * 384 + h * 96;
    float v[3];
    #pragma unroll
    for (int i = 0; i < 3; i++) { int d = lane + i * 32; v[i] = g[d] * tv / fmaxf(nb[d], 1e-12f); }
    float m = fmaxf(v[0], fmaxf(v[1], v[2]));
    #pragma unroll
    for (int o2 = 16; o2; o2 >>= 1) m = fmaxf(m, __shfl_xor_sync(FULLMASK, m, o2));
    float e[3], s = 0.f;
    #pragma unroll
    for (int i = 0; i < 3; i++) { e[i] = expf(v[i] - m); s += e[i]; }
    #pragma unroll
    for (int o2 = 16; o2; o2 >>= 1) s += __shfl_xor_sync(FULLMASK, s, o2);
    float inv = 1.0f / s;
    #pragma unroll
    for (int i = 0; i < 3; i++) o[lane + i * 32] = __float2bfloat16(e[i] * inv);
}

__global__ void wa_softmax_k(const float* __restrict__ G, const float* __restrict__ norms,
                             bf16* __restrict__ P)
{
    int warp = threadIdx.x >> 5, lane = threadIdx.x & 31;
    int row = blockIdx.x * 8 + warp;
    int bh = row / 96, bq = bh >> 2, h = bh & 3;
    const float* g = G + (long)row * 96;
    bf16* o = P + (long)row * 96;
    const float* nb = norms + bq * 384 + h * 96;
    float l[3];
    #pragma unroll
    for (int i = 0; i < 3; i++) { int d = lane + i * 32; l[i] = g[d] / fmaxf(nb[d], 1e-12f); }
    float m1 = fmaxf(l[0], fmaxf(l[1], l[2]));
    #pragma unroll
    for (int o2 = 16; o2; o2 >>= 1) m1 = fmaxf(m1, __shfl_xor_sync(FULLMASK, m1, o2));
    float e[3], s1 = 0.f;
    #pragma unroll
    for (int i = 0; i < 3; i++) { e[i] = expf(l[i] - m1); s1 += e[i]; }
    #pragma unroll
    for (int o2 = 16; o2; o2 >>= 1) s1 += __shfl_xor_sync(FULLMASK, s1, o2);
    float inv1 = 1.0f / s1, a[3];
    #pragma unroll
    for (int i = 0; i < 3; i++) a[i] = l[i] * 0.051031036307982884f + 0.5f * e[i] * inv1;
    float m2 = fmaxf(a[0], fmaxf(a[1], a[2]));
    #pragma unroll
    for (int o2 = 16; o2; o2 >>= 1) m2 = fmaxf(m2, __shfl_xor_sync(FULLMASK, m2, o2));
    float e2[3], s2 = 0.f;
    #pragma unroll
    for (int i = 0; i < 3; i++) { e2[i] = expf(a[i] - m2); s2 += e2[i]; }
    #pragma unroll
    for (int o2 = 16; o2; o2 >>= 1) s2 += __shfl_xor_sync(FULLMASK, s2, o2);
    float inv2 = 1.0f / s2;
    #pragma unroll
    for (int i = 0; i < 3; i++) o[lane + i * 32] = __float2bfloat16(e2[i] * inv2);
}

__global__ void final_kernel(const bf16* __restrict__ y, const float* __restrict__ xin,
                             const float* __restrict__ gamma, float* __restrict__ out)
{
    __shared__ float tile[32][33];
    int n0 = blockIdx.x << 5, c0 = blockIdx.y << 5, b = blockIdx.z;
    int tx = threadIdx.x, ty = threadIdx.y;
    #pragma unroll
    for (int r = 0; r < 4; r++)
        tile[ty + r * 8][tx] =
            __bfloat162float(y[((long)b * 4096 + n0 + ty + r * 8) * 384 + c0 + tx]);
    __syncthreads();
    #pragma unroll
    for (int r = 0; r < 4; r++) {
        int c = c0 + ty + r * 8;
        long o = ((long)b * 384 + c) * 4096 + n0 + tx;
        out[o] = xin[o] + gamma[c] * tile[tx][ty + r * 8];
    }
}

__device__ __forceinline__ void cpa16s(unsigned sa, const void* g)
{
    asm volatile("cp.async.cg.shared.global [%0], [%1], 16;\n" :: "r"(sa), "l"(g));
}

__device__ __forceinline__ void cpa16p(unsigned sa, const void* g, bool valid)
{
    int sz = valid ? 16 : 0;
    asm volatile("cp.async.cg.shared.global [%0], [%1], 16, %2;\n"
                 :: "r"(sa), "l"(g), "r"(sz));
}

__device__ __forceinline__ unsigned smem_u32(const void* p)
{
    return (unsigned)__cvta_generic_to_shared(p);
}

__device__ __forceinline__ float gelu_f(float v)
{
    return 0.5f * v * (1.0f + erff(v * 0.7071067811865476f));
}

// ============================================================================
// Big-GEMM: 128x128 CTA tile, K=64 chunks, 4 warps of 64x64. (R13/R14, unchanged)
// ============================================================================
template<int EPI, int OUTBF>
__global__ void __launch_bounds__(128) bgemm2_k(
    const bf16* __restrict__ A, const bf16* __restrict__ B,
    const float* __restrict__ bias, void* __restrict__ Cg,
    int N, int K,
    const bf16* __restrict__ f1, const float* __restrict__ f2,
    const float* __restrict__ f3, const float* __restrict__ f4)
{
    extern __shared__ __align__(16) bf16 dynb[];
    const int TP = 72;
    const int TE = 128 * TP;
    unsigned sbA = smem_u32(dynb);
    unsigned sbB = sbA + 3 * TE * 2;

    int tid = threadIdx.x;
    int m0 = blockIdx.x * 128, n0 = blockIdx.y * 128;

    float c[4][8][4];
    #pragma unroll
    for (int i = 0; i < 4; i++)
        #pragma unroll
        for (int j = 0; j < 8; j++)
            #pragma unroll
            for (int q = 0; q < 4; q++) c[i][j][q] = 0.f;

    int seg = tid & 7, rS = tid >> 3;
    auto stage = [&](int buf, int k0) {
        #pragma unroll
        for (int ps = 0; ps < 8; ps++) {
            int row = rS + ps * 16;
            cpa16s(sbA + (buf * TE + row * TP + seg * 8) * 2,
                   A + (long)(m0 + row) * K + k0 + seg * 8);
            cpa16s(sbB + (buf * TE + row * TP + seg * 8) * 2,
                   B + (long)(n0 + row) * K + k0 + seg * 8);
        }
        asm volatile("cp.async.commit_group;\n");
    };

    int nst = K >> 6;
    stage(0, 0);
    if (nst > 1) stage(1, 64); else asm volatile("cp.async.commit_group;\n");
    if (nst > 2) stage(2, 128); else asm volatile("cp.async.commit_group;\n");

    int wid = tid >> 5, lane = tid & 31;
    int wm = (wid >> 1) * 64, wn = (wid & 1) * 64;
    int g = lane >> 2, t = lane & 3;
    int aRow = ((lane >> 3) & 1) * 8 + (lane & 7);
    int aK = (lane >> 4) * 8;
    int bRow = ((lane >> 4) & 1) * 8 + (lane & 7);
    int bK = ((lane >> 3) & 1) * 8;

    for (int s = 0; s < nst; s++) {
        asm volatile("cp.async.wait_group 2;\n");
        __syncthreads();
        int buf = s % 3;
        unsigned aT = sbA + buf * TE * 2;
        unsigned bT = sbB + buf * TE * 2;
        #pragma unroll
        for (int ks = 0; ks < 64; ks += 16) {
            unsigned af[4][4], bfm[8][2];
            #pragma unroll
            for (int im = 0; im < 4; im++) {
                unsigned addr = aT + ((wm + im * 16 + aRow) * TP + ks + aK) * 2;
                asm volatile("ldmatrix.sync.aligned.m8n8.x4.shared.b16 {%0,%1,%2,%3}, [%4];\n"
                             : "=r"(af[im][0]), "=r"(af[im][1]), "=r"(af[im][2]), "=r"(af[im][3])
                             : "r"(addr));
            }
            #pragma unroll
            for (int jp = 0; jp < 4; jp++) {
                unsigned addr = bT + ((wn + jp * 16 + bRow) * TP + ks + bK) * 2;
                asm volatile("ldmatrix.sync.aligned.m8n8.x4.shared.b16 {%0,%1,%2,%3}, [%4];\n"
                             : "=r"(bfm[2 * jp][0]), "=r"(bfm[2 * jp][1]),
                               "=r"(bfm[2 * jp + 1][0]), "=r"(bfm[2 * jp + 1][1])
                             : "r"(addr));
            }
            #pragma unroll
            for (int im = 0; im < 4; im++)
                #pragma unroll
                for (int jn = 0; jn < 8; jn++)
                    asm volatile(
                        "mma.sync.aligned.m16n8k16.row.col.f32.bf16.bf16.f32 "
                        "{%0,%1,%2,%3},{%4,%5,%6,%7},{%8,%9},{%0,%1,%2,%3};\n"
                        : "+f"(c[im][jn][0]), "+f"(c[im][jn][1]),
                          "+f"(c[im][jn][2]), "+f"(c[im][jn][3])
                        : "r"(af[im][0]), "r"(af[im][1]), "r"(af[im][2]), "r"(af[im][3]),
                          "r"(bfm[jn][0]), "r"(bfm[jn][1]));
        }
        __syncthreads();
        if (s + 3 < nst) stage((s + 3) % 3, (s + 3) << 6);
        else asm volatile("cp.async.commit_group;\n");
    }

    float* Cf = (float*)Cg;
    bf16*  Cb = (bf16*)Cg;
    #pragma unroll
    for (int im = 0; im < 4; im++) {
        int rbase = m0 + wm + im * 16 + g;
        #pragma unroll
        for (int jn = 0; jn < 8; jn++) {
            int col = n0 + wn + jn * 8 + t * 2;
            float b0 = bias ? bias[col] : 0.f;
            float b1 = bias ? bias[col + 1] : 0.f;
            #pragma unroll
            for (int hr = 0; hr < 2; hr++) {
                int rr = rbase + hr * 8;
                float v0 = c[im][jn][hr * 2 + 0] + b0;
                float v1 = c[im][jn][hr * 2 + 1] + b1;
                if (EPI == 1) { v0 = gelu_f(v0); v1 = gelu_f(v1); }
                if (EPI == 2) {
                    long rb = (long)rr * 384 + col;
                    float a0 = (__bfloat162float(f1[rb])     + f2[col]     * v0) * f3[col]     + f4[col];
                    float a1 = (__bfloat162float(f1[rb + 1]) + f2[col + 1] * v1) * f3[col + 1] + f4[col + 1];
                    int n = rr & 4095, b = rr >> 12;
                    int hh2 = n >> 6, ww2 = n & 63;
                    int q = ((hh2 & 1) << 1) | (ww2 & 1);
                    int p = ((hh2 >> 1) << 5) | (ww2 >> 1);
                    bf16* dst = Cb + ((long)(b * 4 + q) * 1024 + p) * 384 + col;
                    *(__nv_bfloat162*)dst = __floats2bfloat162_rn(a0, a1);
                } else if (OUTBF) {
                    *(__nv_bfloat162*)(Cb + (long)rr * N + col) = __floats2bfloat162_rn(v0, v1);
                } else {
                    *(float2*)(Cf + (long)rr * N + col) = make_float2(v0, v1);
                }
            }
        }
    }
}

template<int EPI, int OUTBF>
static void bg2(const bf16* A, const bf16* B, const float* bias, void* C,
                int M, int N, int K,
                const bf16* f1 = nullptr, const float* f2 = nullptr,
                const float* f3 = nullptr, const float* f4 = nullptr)
{
    cudaFuncSetAttribute(bgemm2_k<EPI, OUTBF>,
                         cudaFuncAttributeMaxDynamicSharedMemorySize, 110592);
    dim3 grid(M / 128, N / 128);
    bgemm2_k<EPI, OUTBF><<<grid, 128, 110592>>>(A, B, bias, C, N, K, f1, f2, f3, f4);
}

// ============================================================================
// Batched GEMM, 4-warp 64x64, templated chunk KCH in {32,64}, bounds-guarded.
// OUTM: 0 fp32, 1 bf16, 3 fp32 atomicAdd (split-K)
// ============================================================================
template<int OUTM, int KCH>
__global__ void __launch_bounds__(128) bg2b_k(
    const bf16* __restrict__ Ag, const bf16* __restrict__ Bg, void* __restrict__ Cg,
    int M, int N, int K, int lda, int ldb, int ldc,
    long sA1, long sA2, long sB1, long sB2, long sC1, long sC2, int HB, int SK)
{
    extern __shared__ __align__(16) bf16 dynb[];
    const int TP = (KCH == 64) ? 72 : 40;
    const int TE = 128 * TP;
    const int SEGS = KCH / 8;
    unsigned sbA = smem_u32(dynb);
    unsigned sbB = sbA + 3 * TE * 2;

    int zz = blockIdx.z;
    int ksl = zz % SK, z = zz / SK;
    int zo = z / HB, zi = z - zo * HB;
    const bf16* A = Ag + zo * sA1 + zi * sA2 + (long)ksl * K;
    const bf16* B = Bg + zo * sB1 + zi * sB2 + (long)ksl * K;

    int tid = threadIdx.x;
    int m0 = blockIdx.x * 128, n0 = blockIdx.y * 128;

    float c[4][8][4];
    #pragma unroll
    for (int i = 0; i < 4; i++)
        #pragma unroll
        for (int j = 0; j < 8; j++)
            #pragma unroll
            for (int q = 0; q < 4; q++) c[i][j][q] = 0.f;

    int seg = tid & (SEGS - 1);
    int rS = tid / SEGS;
    auto stage = [&](int buf, int k0) {
        #pragma unroll
        for (int row = rS; row < 128; row += 128 / SEGS) {
            int ra = (m0 + row < M) ? m0 + row : M - 1;
            cpa16p(sbA + (buf * TE + row * TP + seg * 8) * 2,
                   A + (long)ra * lda + k0 + seg * 8, m0 + row < M);
            int rb = (n0 + row < N) ? n0 + row : N - 1;
            cpa16p(sbB + (buf * TE + row * TP + seg * 8) * 2,
                   B + (long)rb * ldb + k0 + seg * 8, n0 + row < N);
        }
        asm volatile("cp.async.commit_group;\n");
    };

    int nst = K / KCH;
    stage(0, 0);
    if (nst > 1) stage(1, KCH); else asm volatile("cp.async.commit_group;\n");
    if (nst > 2) stage(2, 2 * KCH); else asm volatile("cp.async.commit_group;\n");

    int wid = tid >> 5, lane = tid & 31;
    int wm = (wid >> 1) * 64, wn = (wid & 1) * 64;
    int g = lane >> 2, t = lane & 3;
    int aRow = ((lane >> 3) & 1) * 8 + (lane & 7);
    int aK = (lane >> 4) * 8;
    int bRow = ((lane >> 4) & 1) * 8 + (lane & 7);
    int bK = ((lane >> 3) & 1) * 8;

    for (int s = 0; s < nst; s++) {
        asm volatile("cp.async.wait_group 2;\n");
        __syncthreads();
        int buf = s % 3;
        unsigned aT = sbA + buf * TE * 2;
        unsigned bT = sbB + buf * TE * 2;
        #pragma unroll
        for (int ks = 0; ks < KCH; ks += 16) {
            unsigned af[4][4], bfm[8][2];
            #pragma unroll
            for (int im = 0; im < 4; im++) {
                unsigned addr = aT + ((wm + im * 16 + aRow) * TP + ks + aK) * 2;
                asm volatile("ldmatrix.sync.aligned.m8n8.x4.shared.b16 {%0,%1,%2,%3}, [%4];\n"
                             : "=r"(af[im][0]), "=r"(af[im][1]), "=r"(af[im][2]), "=r"(af[im][3])
                             : "r"(addr));
            }
            #pragma unroll
            for (int jp = 0; jp < 4; jp++) {
                unsigned addr = bT + ((wn + jp * 16 + bRow) * TP + ks + bK) * 2;
                asm volatile("ldmatrix.sync.aligned.m8n8.x4.shared.b16 {%0,%1,%2,%3}, [%4];\n"
                             : "=r"(bfm[2 * jp][0]), "=r"(bfm[2 * jp][1]),
                               "=r"(bfm[2 * jp + 1][0]), "=r"(bfm[2 * jp + 1][1])
                             : "r"(addr));
            }
            #pragma unroll
            for (int im = 0; im < 4; im++)
                #pragma unroll
                for (int jn = 0; jn < 8; jn++)
                    asm volatile(
                        "mma.sync.aligned.m16n8k16.row.col.f32.bf16.bf16.f32 "
                        "{%0,%1,%2,%3},{%4,%5,%6,%7},{%8,%9},{%0,%1,%2,%3};\n"
                        : "+f"(c[im][jn][0]), "+f"(c[im][jn][1]),
                          "+f"(c[im][jn][2]), "+f"(c[im][jn][3])
                        : "r"(af[im][0]), "r"(af[im][1]), "r"(af[im][2]), "r"(af[im][3]),
                          "r"(bfm[jn][0]), "r"(bfm[jn][1]));
        }
        __syncthreads();
        if (s + 3 < nst) stage((s + 3) % 3, (s + 3) * KCH);
        else asm volatile("cp.async.commit_group;\n");
    }

    float* Cf = (float*)Cg + zo * sC1 + zi * sC2;
    bf16*  Cb = (bf16*)Cg + zo * sC1 + zi * sC2;
    #pragma unroll
    for (int im = 0; im < 4; im++) {
        int rbase = m0 + wm + im * 16 + g;
        #pragma unroll
        for (int jn = 0; jn < 8; jn++) {
            int col = n0 + wn + jn * 8 + t * 2;
            if (col >= N) continue;
            #pragma unroll
            for (int hr = 0; hr < 2; hr++) {
                int rr = rbase + hr * 8;
                if (rr >= M) continue;
                float v0 = c[im][jn][hr * 2 + 0];
                float v1 = c[im][jn][hr * 2 + 1];
                if (OUTM == 3) {
                    atomicAdd(&Cf[(long)rr * ldc + col], v0);
                    atomicAdd(&Cf[(long)rr * ldc + col + 1], v1);
                } else if (OUTM == 1) {
                    *(__nv_bfloat162*)(Cb + (long)rr * ldc + col) = __floats2bfloat162_rn(v0, v1);
                } else {
                    *(float2*)(Cf + (long)rr * ldc + col) = make_float2(v0, v1);
                }
            }
        }
    }
}

template<int OUTM, int KCH>
static void bg2b(const bf16* A, const bf16* B, void* C,
                 int M, int N, int K, int lda, int ldb, int ldc,
                 long sA1, long sA2, long sB1, long sB2, long sC1, long sC2,
                 int HB, int Z, int SK = 1)
{
    int smem = (KCH == 64) ? 110592 : 61440;
    cudaFuncSetAttribute(bg2b_k<OUTM, KCH>,
                         cudaFuncAttributeMaxDynamicSharedMemorySize, smem);
    dim3 grid((M + 127) / 128, (N + 127) / 128, Z * SK);
    bg2b_k<OUTM, KCH><<<grid, 128, smem>>>(A, B, C, M, N, K / SK, lda, ldb, ldc,
                                           sA1, sA2, sB1, sB2, sC1, sC2, HB, SK);
}

extern "C" void kernel_launch(void* const* d_in, const int* in_sizes, int n_in,
                              void* d_out, int out_size)
{
    const float* x          = (const float*)d_in[0];
    const float* convs_w    = (const float*)d_in[1];
    const float* convs_b    = (const float*)d_in[2];
    const float* pos_w      = (const float*)d_in[3];
    const float* pos_b      = (const float*)d_in[4];
    const float* ln_xca_w   = (const float*)d_in[5];
    const float* ln_xca_b   = (const float*)d_in[6];
    const float* gamma_xca  = (const float*)d_in[7];
    const float* xca_temp   = (const float*)d_in[8];
    const float* xca_kv_w   = (const float*)d_in[9];
    const float* xca_kv_b   = (const float*)d_in[10];
    const float* xca_proj_w = (const float*)d_in[11];
    const float* xca_proj_b = (const float*)d_in[12];
    const float* conv_out_w = (const float*)d_in[13];
    const float* conv_out_b = (const float*)d_in[14];
    const float* wa_kv_w    = (const float*)d_in[15];
    const float* wa_kv_b    = (const float*)d_in[16];
    const float* wa_proj_w  = (const float*)d_in[17];
    const float* wa_proj_b  = (const float*)d_in[18];
    const float* ln_w       = (const float*)d_in[19];
    const float* ln_b       = (const float*)d_in[20];
    const float* pw1_w      = (const float*)d_in[21];
    const float* pw1_b      = (const float*)d_in[22];
    const float* pw2_w      = (const float*)d_in[23];
    const float* pw2_b      = (const float*)d_in[24];
    const float* gamma      = (const float*)d_in[25];
    float* out = (float*)d_out;

    float *conv, *pos, *x3f, *attn, *norms;
    bf16 *bx, *lnb, *kv, *kt, *b1, *uqt, *battn, *h1, *wt;
    cudaGetSymbolAddress((void**)&conv,  g_conv);
    cudaGetSymbolAddress((void**)&pos,   g_pos);
    cudaGetSymbolAddress((void**)&x3f,   g_x3);
    cudaGetSymbolAddress((void**)&attn,  g_attn);
    cudaGetSymbolAddress((void**)&norms, g_norms);
    cudaGetSymbolAddress((void**)&bx,    g_bx);
    cudaGetSymbolAddress((void**)&lnb,   g_lnb);
    cudaGetSymbolAddress((void**)&kv,    g_kv);
    cudaGetSymbolAddress((void**)&kt,    g_kt);
    cudaGetSymbolAddress((void**)&b1,    g_b1);
    cudaGetSymbolAddress((void**)&uqt,   g_uqt);
    cudaGetSymbolAddress((void**)&battn, g_battn);
    cudaGetSymbolAddress((void**)&h1,    g_h1);
    cudaGetSymbolAddress((void**)&wt,    g_wt);

    bf16* x3 = (bf16*)x3f;

    bf16* w_xkv   = wt;
    bf16* w_xproj = wt + 294912;
    bf16* w_wkv   = wt + 442368;
    bf16* w_wproj = wt + 737280;
    bf16* w_pw1   = wt + 884736;
    bf16* w_pw2   = wt + 1474560;

    // one-time side stream + fork/join events (created on the uncaptured
    // correctness call; reused every call so captured work is identical)
    static cudaStream_t sB = nullptr;
    static cudaEvent_t evF = nullptr, evJ = nullptr;
    if (sB == nullptr) {
        cudaStreamCreateWithFlags(&sB, cudaStreamNonBlocking);
        cudaEventCreateWithFlags(&evF, cudaEventDisableTiming);
        cudaEventCreateWithFlags(&evJ, cudaEventDisableTiming);
    }

    // fork: chain B (weight/x converts + attn zero) runs beside chain A
    cudaEventRecord(evF, 0);
    cudaStreamWaitEvent(sB, evF, 0);
    cvtw_kernel<<<(2064384 + 255) / 256, 256, 0, sB>>>(
        xca_kv_w, xca_proj_w, wa_kv_w, wa_proj_w, pw1_w, pw2_w, wt);
    cvtx_kernel<<<(25165824 + 255) / 256, 256, 0, sB>>>(x, bx, uqt);
    zero_kernel<<<(589824 + 255) / 256, 256, 0, sB>>>(attn, 589824);
    cudaEventRecord(evJ, sB);

    // chain A (default stream)
    pos_kernel<<<4096, 384>>>(pos_w, pos_b, pos);
    dwconv3_kernel<<<16 * 96, 256>>>(x, convs_w, convs_b, conv);
    t1ln_kernel<<<dim3(256, 16), 256>>>(conv, x, pos, ln_xca_w, ln_xca_b, x3, lnb);

    // join before anything that needs wt/bx/uqt/attn
    cudaStreamWaitEvent(0, evJ, 0);

    // XCA
    bg2<0,1>(lnb, w_xkv, xca_kv_b, kv, 65536, 768, 384);
    dim3 tb(32, 8);
    tk_kernel<<<dim3(128, 12, 16), tb>>>(kv, kt, 4096);
    norms2_k<<<768, 256>>>(kt, norms, 4096);
    bg2b<3,64>(bx, kt, attn, 96, 96, 4096, 4096, 4096, 96,
               (long)384*4096, (long)96*4096, (long)384*4096, (long)96*4096,
               (long)4*9216, 9216, 4, 64, 4);
    xca_softmax_k<<<768, 256>>>(attn, norms, xca_temp, battn);
    bg2b<1,32>(kv + 384, battn, b1, 4096, 96, 96, 768, 96, 384,
               (long)4096*768, 96, (long)4*9216, 9216, (long)4096*384, 96, 4, 64);
    bg2<2,1>(b1, w_xproj, xca_proj_b, lnb, 65536, 384, 384,
             x3, gamma_xca, conv_out_w, conv_out_b);

    // Window attention (wx = lnb)
    bg2<0,1>(lnb, w_wkv, wa_kv_b, kv, 65536, 768, 384);
    tk_kernel<<<dim3(32, 12, 64), tb>>>(kv, kt, 1024);
    norms2_k<<<3072, 256>>>(kt, norms, 1024);
    bg2b<0,64>(uqt, kt, attn, 96, 96, 1024, 1024, 1024, 96,
               (long)384*1024, (long)96*1024, (long)384*1024, (long)96*1024,
               (long)4*9216, 9216, 4, 256);
    wa_softmax_k<<<3072, 256>>>(attn, norms, battn);
    bf16* x2s = x3;
    bg2b<1,32>(battn, kv + 384, x2s, 96, 1024, 96, 96, 768, 1024,
               (long)4*9216, 9216, (long)1024*768, 96,
               (long)96*1024, (long)64*96*1024, 4, 256);
    bg2<0,1>(x2s, w_wproj, wa_proj_b, b1, 65536, 384, 384);

    // fold + gather-LN, MLP, final residual
    lng_kernel<<<65536, 128>>>(b1, ln_w, ln_b, lnb);
    bg2<1,1>(lnb, w_pw1, pw1_b, h1, 65536, 1536, 384);
    bg2<0,1>(h1, w_pw2, pw2_b, uqt, 65536, 384, 1536);
    dim3 tg2(128, 12, 16);
    final_kernel<<<tg2, tb>>>(uqt, x, gamma, out);
}

// round 16
// speedup vs baseline: 1.2627x; 1.2081x over previous
#include <cuda_runtime.h>
#include <cuda_bf16.h>
#include <cstdint>
#include <math.h>

#define FULLMASK 0xffffffffu
typedef __nv_bfloat16 bf16;
// B=16, C=384, H=W=64, N=4096, HEADS=4, HD=96

// ---------------- scratch ----------------
__device__ __align__(256) float g_conv[25165824];
__device__ __align__(256) float g_pos[1572864];
__device__ __align__(256) float g_x3[25165824];   // bf16 x3, then bf16 x2s
__device__ __align__(256) float g_attn[2359296];
__device__ __align__(256) float g_norms[24576];
__device__ __align__(256) bf16 g_bx[25165824];
__device__ __align__(256) bf16 g_lnb[25165824];
__device__ __align__(256) bf16 g_kv[50331648];
__device__ __align__(256) bf16 g_kt[25165824];
__device__ __align__(256) bf16 g_b1[25165824];
__device__ __align__(256) bf16 g_uqt[25165824];
__device__ __align__(256) bf16 g_battn[2359296];  // feat+pw_bf scratch, then probs
__device__ __align__(256) bf16 g_h1[100663296];
__device__ __align__(256) bf16 g_wt[2064384];

__global__ void zero_kernel(float* __restrict__ p, long n)
{
    long i = (long)blockIdx.x * 256 + threadIdx.x;
    if (i < n) p[i] = 0.f;
}

__global__ void cvtw_kernel(const float* __restrict__ s0, const float* __restrict__ s1,
                            const float* __restrict__ s2, const float* __restrict__ s3,
                            const float* __restrict__ s4, const float* __restrict__ s5,
                            bf16* __restrict__ out)
{
    long i = (long)blockIdx.x * 256 + threadIdx.x;
    if (i >= 2064384L) return;
    const float* s; long off;
    if (i < 294912)       { s = s0; off = i; }
    else if (i < 442368)  { s = s1; off = i - 294912; }
    else if (i < 737280)  { s = s2; off = i - 442368; }
    else if (i < 884736)  { s = s3; off = i - 737280; }
    else if (i < 1474560) { s = s4; off = i - 884736; }
    else                  { s = s5; off = i - 1474560; }
    out[i] = __float2bfloat16(s[off]);
}

__global__ void cvtx_kernel(const float* __restrict__ x, bf16* __restrict__ bx,
                            bf16* __restrict__ uqT)
{
    long idx = (long)blockIdx.x * 256 + threadIdx.x;
    if (idx >= 25165824L) return;
    float v = x[idx];
    bf16 bv = __float2bfloat16(v);
    bx[idx] = bv;
    int n = (int)(idx & 4095);
    long r = idx >> 12;
    int c = (int)(r % 384), b = (int)(r / 384);
    int hh = n >> 6, ww = n & 63;
    int q = ((hh & 1) << 1) | (ww & 1);
    int p = ((hh >> 1) << 5) | (ww >> 1);
    uqT[((long)(b * 4 + q) * 384 + c) * 1024 + p] = bv;
}

// ---------------- Fourier features (bf16) + pos_w convert ----------------
// featb: [4096][64] bf16; pwb: [384][64] bf16 (appended at featb+262144)
__global__ void featcvt_kernel(const float* __restrict__ pw, bf16* __restrict__ featb)
{
    long idx = (long)blockIdx.x * 256 + threadIdx.x;
    if (idx < 262144) {
        int n = (int)(idx >> 6), j = (int)(idx & 63);
        int hh = n >> 6, ww = n & 63;
        int jj = j & 31, m = jj >> 1;
        float v = (j < 32) ? (float)(hh + 1) : (float)(ww + 1);
        v = v / (64.0f + 1e-6f) * 6.283185307179586f;
        float arg = v / powf(10000.0f, (float)m / 16.0f);
        featb[idx] = __float2bfloat16((jj & 1) ? cosf(arg) : sinf(arg));
    } else if (idx < 262144 + 24576) {
        long o = idx - 262144;
        featb[idx] = __float2bfloat16(pw[o]);
    }
}

__global__ void __launch_bounds__(256) dwconv3_kernel(
    const float* __restrict__ x, const float* __restrict__ w,
    const float* __restrict__ bias, float* __restrict__ out)
{
    __shared__ float A[66 * 66], Bb[66 * 66];
    int bc = blockIdx.x, b = bc / 96, c = bc % 96, tid = threadIdx.x;
    for (int i = tid; i < 66 * 66; i += 256) { A[i] = 0.f; Bb[i] = 0.f; }
    __syncthreads();
    const float* xp = x + ((long)b * 384 + c) * 4096;
    for (int i = tid; i < 4096; i += 256)
        A[((i >> 6) + 1) * 66 + (i & 63) + 1] = xp[i];
    __syncthreads();
    float* src = A;
    float* dst = Bb;
    #pragma unroll
    for (int ch = 0; ch < 3; ch++) {
        const float* wp = w + (ch * 96 + c) * 9;
        float bv = bias[ch * 96 + c];
        float w00 = wp[0], w01 = wp[1], w02 = wp[2];
        float w10 = wp[3], w11 = wp[4], w12 = wp[5];
        float w20 = wp[6], w21 = wp[7], w22 = wp[8];
        float* op = out + ((long)b * 384 + ch * 96 + c) * 4096;
        const float* xn = (ch < 2) ? x + ((long)b * 384 + (ch + 1) * 96 + c) * 4096 : nullptr;
        for (int i = tid; i < 4096; i += 256) {
            int r = i >> 6, cc = i & 63;
            const float* p = src + r * 66 + cc;
            float acc = bv
                + w00 * p[0]   + w01 * p[1]   + w02 * p[2]
                + w10 * p[66]  + w11 * p[67]  + w12 * p[68]
                + w20 * p[132] + w21 * p[133] + w22 * p[134];
            op[i] = acc;
            if (xn) dst[(r + 1) * 66 + cc + 1] = acc + xn[i];
        }
        __syncthreads();
        float* t = src; src = dst; dst = t;
    }
}

// ---------------- fused transpose+pos+LayerNorm ----------------
__global__ void __launch_bounds__(256) t1ln_kernel(
    const float* __restrict__ conv, const float* __restrict__ xin,
    const float* __restrict__ pos, const float* __restrict__ w,
    const float* __restrict__ bvec, bf16* __restrict__ x3, bf16* __restrict__ lnb)
{
    __shared__ float s[16 * 385];
    int n0 = blockIdx.x << 4, b = blockIdx.y, tid = threadIdx.x;
    for (int idx = tid; idx < 384 * 16; idx += 256) {
        int n = idx & 15, c = idx >> 4;
        const float* src = (c >= 288) ? xin : conv;
        float v = src[((long)b * 384 + c) * 4096 + n0 + n] + pos[(long)(n0 + n) * 384 + c];
        s[n * 385 + c] = v;
    }
    __syncthreads();
    int wid = tid >> 5, lane = tid & 31;
    #pragma unroll
    for (int r = 0; r < 2; r++) {
        int row = wid + r * 8;
        const float* sr = s + row * 385;
        float sum = 0.f, sq = 0.f;
        #pragma unroll
        for (int i = 0; i < 12; i++) {
            float v = sr[lane + i * 32];
            sum += v; sq += v * v;
        }
        #pragma unroll
        for (int o = 16; o; o >>= 1) {
            sum += __shfl_xor_sync(FULLMASK, sum, o);
            sq  += __shfl_xor_sync(FULLMASK, sq, o);
        }
        float m = sum * (1.0f / 384.0f);
        float rs = rsqrtf(sq * (1.0f / 384.0f) - m * m + 1e-6f);
        long ob = ((long)b * 4096 + n0 + row) * 384;
        #pragma unroll
        for (int i = 0; i < 12; i++) {
            int c = lane + i * 32;
            float v = sr[c];
            x3[ob + c]  = __float2bfloat16(v);
            lnb[ob + c] = __float2bfloat16((v - m) * rs * w[c] + bvec[c]);
        }
    }
}

__global__ void tk_kernel(const bf16* __restrict__ kv, bf16* __restrict__ kT, int R)
{
    __shared__ bf16 tile[32][33];
    int n0 = blockIdx.x << 5, d0 = blockIdx.y << 5, bz = blockIdx.z;
    int tx = threadIdx.x, ty = threadIdx.y;
    #pragma unroll
    for (int r = 0; r < 4; r++)
        tile[ty + r * 8][tx] = kv[((long)bz * R + n0 + ty + r * 8) * 768 + d0 + tx];
    __syncthreads();
    #pragma unroll
    for (int r = 0; r < 4; r++)
        kT[((long)bz * 384 + d0 + ty + r * 8) * R + n0 + tx] = tile[tx][ty + r * 8];
}

__global__ void norms2_k(const bf16* __restrict__ kT, float* __restrict__ norms, int R)
{
    int gw = blockIdx.x * 8 + (threadIdx.x >> 5);
    int lane = threadIdx.x & 31;
    const bf16* p = kT + (long)gw * R;
    float s = 0.f;
    for (int i = lane * 2; i < R; i += 64) {
        __nv_bfloat162 v = *(const __nv_bfloat162*)(p + i);
        float a = __bfloat162float(v.x), b = __bfloat162float(v.y);
        s += a * a + b * b;
    }
    #pragma unroll
    for (int o = 16; o; o >>= 1) s += __shfl_xor_sync(FULLMASK, s, o);
    if (lane == 0) norms[gw] = sqrtf(s);
}

__global__ void lng_kernel(const bf16* __restrict__ in, const float* __restrict__ w,
                           const float* __restrict__ bvec, bf16* __restrict__ out)
{
    int row = blockIdx.x, t = threadIdx.x;
    int b = row >> 12, n = row & 4095;
    int hh = n >> 6, ww = n & 63;
    int q = ((hh & 1) << 1) | (ww & 1);
    int p = ((hh >> 1) << 5) | (ww >> 1);
    long ibase = ((long)(b * 4 + q) * 1024 + p) * 384;
    float v0 = __bfloat162float(in[ibase + t]);
    float v1 = __bfloat162float(in[ibase + t + 128]);
    float v2 = __bfloat162float(in[ibase + t + 256]);
    float s = v0 + v1 + v2;
    float q2 = v0 * v0 + v1 * v1 + v2 * v2;
    #pragma unroll
    for (int o = 16; o; o >>= 1) {
        s += __shfl_down_sync(FULLMASK, s, o);
        q2 += __shfl_down_sync(FULLMASK, q2, o);
    }
    __shared__ float ss[4], sq[4], smean, srstd;
    int wid = t >> 5, lane = t & 31;
    if (lane == 0) { ss[wid] = s; sq[wid] = q2; }
    __syncthreads();
    if (t == 0) {
        float S = ss[0] + ss[1] + ss[2] + ss[3];
        float Q = sq[0] + sq[1] + sq[2] + sq[3];
        float m = S * (1.0f / 384.0f);
        smean = m;
        srstd = rsqrtf(Q * (1.0f / 384.0f) - m * m + 1e-6f);
    }
    __syncthreads();
    float m = smean, r = srstd;
    long ob = (long)row * 384;
    out[ob + t]       = __float2bfloat16((v0 - m) * r * w[t]       + bvec[t]);
    out[ob + t + 128] = __float2bfloat16((v1 - m) * r * w[t + 128] + bvec[t + 128]);
    out[ob + t + 256] = __float2bfloat16((v2 - m) * r * w[t + 256] + bvec[t + 256]);
}

__global__ void xca_softmax_k(const float* __restrict__ G, const float* __restrict__ norms,
                              const float* __restrict__ temp, bf16* __restrict__ P)
{
    int warp = threadIdx.x >> 5, lane = threadIdx.x & 31;
    int row = blockIdx.x * 8 + warp;
    int bh = row / 96, b = bh >> 2, h = bh & 3;
    float tv = temp[h];
    const float* g = G + (long)row * 96;
    bf16* o = P + (long)row * 96;
    const float* nb = norms + b * 384 + h * 96;
    float v[3];
    #pragma unroll
    for (int i = 0; i < 3; i++) { int d = lane + i * 32; v[i] = g[d] * tv / fmaxf(nb[d], 1e-12f); }
    float m = fmaxf(v[0], fmaxf(v[1], v[2]));
    #pragma unroll
    for (int o2 = 16; o2; o2 >>= 1) m = fmaxf(m, __shfl_xor_sync(FULLMASK, m, o2));
    float e[3], s = 0.f;
    #pragma unroll
    for (int i = 0; i < 3; i++) { e[i] = expf(v[i] - m); s += e[i]; }
    #pragma unroll
    for (int o2 = 16; o2; o2 >>= 1) s += __shfl_xor_sync(FULLMASK, s, o2);
    float inv = 1.0f / s;
    #pragma unroll
    for (int i = 0; i < 3; i++) o[lane + i * 32] = __float2bfloat16(e[i] * inv);
}

__global__ void wa_softmax_k(const float* __restrict__ G, const float* __restrict__ norms,
                             bf16* __restrict__ P)
{
    int warp = threadIdx.x >> 5, lane = threadIdx.x & 31;
    int row = blockIdx.x * 8 + warp;
    int bh = row / 96, bq = bh >> 2, h = bh & 3;
    const float* g = G + (long)row * 96;
    bf16* o = P + (long)row * 96;
    const float* nb = norms + bq * 384 + h * 96;
    float l[3];
    #pragma unroll
    for (int i = 0; i < 3; i++) { int d = lane + i * 32; l[i] = g[d] / fmaxf(nb[d], 1e-12f); }
    float m1 = fmaxf(l[0], fmaxf(l[1], l[2]));
    #pragma unroll
    for (int o2 = 16; o2; o2 >>= 1) m1 = fmaxf(m1, __shfl_xor_sync(FULLMASK, m1, o2));
    float e[3], s1 = 0.f;
    #pragma unroll
    for (int i = 0; i < 3; i++) { e[i] = expf(l[i] - m1); s1 += e[i]; }
    #pragma unroll
    for (int o2 = 16; o2; o2 >>= 1) s1 += __shfl_xor_sync(FULLMASK, s1, o2);
    float inv1 = 1.0f / s1, a[3];
    #pragma unroll
    for (int i = 0; i < 3; i++) a[i] = l[i] * 0.051031036307982884f + 0.5f * e[i] * inv1;
    float m2 = fmaxf(a[0], fmaxf(a[1], a[2]));
    #pragma unroll
    for (int o2 = 16; o2; o2 >>= 1) m2 = fmaxf(m2, __shfl_xor_sync(FULLMASK, m2, o2));
    float e2[3], s2 = 0.f;
    #pragma unroll
    for (int i = 0; i < 3; i++) { e2[i] = expf(a[i] - m2); s2 += e2[i]; }
    #pragma unroll
    for (int o2 = 16; o2; o2 >>= 1) s2 += __shfl_xor_sync(FULLMASK, s2, o2);
    float inv2 = 1.0f / s2;
    #pragma unroll
    for (int i = 0; i < 3; i++) o[lane + i * 32] = __float2bfloat16(e2[i] * inv2);
}

__global__ void final_kernel(const bf16* __restrict__ y, const float* __restrict__ xin,
                             const float* __restrict__ gamma, float* __restrict__ out)
{
    __shared__ float tile[32][33];
    int n0 = blockIdx.x << 5, c0 = blockIdx.y << 5, b = blockIdx.z;
    int tx = threadIdx.x, ty = threadIdx.y;
    #pragma unroll
    for (int r = 0; r < 4; r++)
        tile[ty + r * 8][tx] =
            __bfloat162float(y[((long)b * 4096 + n0 + ty + r * 8) * 384 + c0 + tx]);
    __syncthreads();
    #pragma unroll
    for (int r = 0; r < 4; r++) {
        int c = c0 + ty + r * 8;
        long o = ((long)b * 384 + c) * 4096 + n0 + tx;
        out[o] = xin[o] + gamma[c] * tile[tx][ty + r * 8];
    }
}

__device__ __forceinline__ void cpa16s(unsigned sa, const void* g)
{
    asm volatile("cp.async.cg.shared.global [%0], [%1], 16;\n" :: "r"(sa), "l"(g));
}

__device__ __forceinline__ void cpa16p(unsigned sa, const void* g, bool valid)
{
    int sz = valid ? 16 : 0;
    asm volatile("cp.async.cg.shared.global [%0], [%1], 16, %2;\n"
                 :: "r"(sa), "l"(g), "r"(sz));
}

__device__ __forceinline__ unsigned smem_u32(const void* p)
{
    return (unsigned)__cvta_generic_to_shared(p);
}

__device__ __forceinline__ float gelu_f(float v)
{
    return 0.5f * v * (1.0f + erff(v * 0.7071067811865476f));
}

// ============================================================================
// Big-GEMM: 128x128 CTA tile, K=64 chunks, 4 warps of 64x64. (unchanged)
// ============================================================================
template<int EPI, int OUTBF>
__global__ void __launch_bounds__(128) bgemm2_k(
    const bf16* __restrict__ A, const bf16* __restrict__ B,
    const float* __restrict__ bias, void* __restrict__ Cg,
    int N, int K,
    const bf16* __restrict__ f1, const float* __restrict__ f2,
    const float* __restrict__ f3, const float* __restrict__ f4)
{
    extern __shared__ __align__(16) bf16 dynb[];
    const int TP = 72;
    const int TE = 128 * TP;
    unsigned sbA = smem_u32(dynb);
    unsigned sbB = sbA + 3 * TE * 2;

    int tid = threadIdx.x;
    int m0 = blockIdx.x * 128, n0 = blockIdx.y * 128;

    float c[4][8][4];
    #pragma unroll
    for (int i = 0; i < 4; i++)
        #pragma unroll
        for (int j = 0; j < 8; j++)
            #pragma unroll
            for (int q = 0; q < 4; q++) c[i][j][q] = 0.f;

    int seg = tid & 7, rS = tid >> 3;
    auto stage = [&](int buf, int k0) {
        #pragma unroll
        for (int ps = 0; ps < 8; ps++) {
            int row = rS + ps * 16;
            cpa16s(sbA + (buf * TE + row * TP + seg * 8) * 2,
                   A + (long)(m0 + row) * K + k0 + seg * 8);
            cpa16s(sbB + (buf * TE + row * TP + seg * 8) * 2,
                   B + (long)(n0 + row) * K + k0 + seg * 8);
        }
        asm volatile("cp.async.commit_group;\n");
    };

    int nst = K >> 6;
    stage(0, 0);
    if (nst > 1) stage(1, 64); else asm volatile("cp.async.commit_group;\n");
    if (nst > 2) stage(2, 128); else asm volatile("cp.async.commit_group;\n");

    int wid = tid >> 5, lane = tid & 31;
    int wm = (wid >> 1) * 64, wn = (wid & 1) * 64;
    int g = lane >> 2, t = lane & 3;
    int aRow = ((lane >> 3) & 1) * 8 + (lane & 7);
    int aK = (lane >> 4) * 8;
    int bRow = ((lane >> 4) & 1) * 8 + (lane & 7);
    int bK = ((lane >> 3) & 1) * 8;

    for (int s = 0; s < nst; s++) {
        asm volatile("cp.async.wait_group 2;\n");
        __syncthreads();
        int buf = s % 3;
        unsigned aT = sbA + buf * TE * 2;
        unsigned bT = sbB + buf * TE * 2;
        #pragma unroll
        for (int ks = 0; ks < 64; ks += 16) {
            unsigned af[4][4], bfm[8][2];
            #pragma unroll
            for (int im = 0; im < 4; im++) {
                unsigned addr = aT + ((wm + im * 16 + aRow) * TP + ks + aK) * 2;
                asm volatile("ldmatrix.sync.aligned.m8n8.x4.shared.b16 {%0,%1,%2,%3}, [%4];\n"
                             : "=r"(af[im][0]), "=r"(af[im][1]), "=r"(af[im][2]), "=r"(af[im][3])
                             : "r"(addr));
            }
            #pragma unroll
            for (int jp = 0; jp < 4; jp++) {
                unsigned addr = bT + ((wn + jp * 16 + bRow) * TP + ks + bK) * 2;
                asm volatile("ldmatrix.sync.aligned.m8n8.x4.shared.b16 {%0,%1,%2,%3}, [%4];\n"
                             : "=r"(bfm[2 * jp][0]), "=r"(bfm[2 * jp][1]),
                               "=r"(bfm[2 * jp + 1][0]), "=r"(bfm[2 * jp + 1][1])
                             : "r"(addr));
            }
            #pragma unroll
            for (int im = 0; im < 4; im++)
                #pragma unroll
                for (int jn = 0; jn < 8; jn++)
                    asm volatile(
                        "mma.sync.aligned.m16n8k16.row.col.f32.bf16.bf16.f32 "
                        "{%0,%1,%2,%3},{%4,%5,%6,%7},{%8,%9},{%0,%1,%2,%3};\n"
                        : "+f"(c[im][jn][0]), "+f"(c[im][jn][1]),
                          "+f"(c[im][jn][2]), "+f"(c[im][jn][3])
                        : "r"(af[im][0]), "r"(af[im][1]), "r"(af[im][2]), "r"(af[im][3]),
                          "r"(bfm[jn][0]), "r"(bfm[jn][1]));
        }
        __syncthreads();
        if (s + 3 < nst) stage((s + 3) % 3, (s + 3) << 6);
        else asm volatile("cp.async.commit_group;\n");
    }

    float* Cf = (float*)Cg;
    bf16*  Cb = (bf16*)Cg;
    #pragma unroll
    for (int im = 0; im < 4; im++) {
        int rbase = m0 + wm + im * 16 + g;
        #pragma unroll
        for (int jn = 0; jn < 8; jn++) {
            int col = n0 + wn + jn * 8 + t * 2;
            float b0 = bias ? bias[col] : 0.f;
            float b1 = bias ? bias[col + 1] : 0.f;
            #pragma unroll
            for (int hr = 0; hr < 2; hr++) {
                int rr = rbase + hr * 8;
                float v0 = c[im][jn][hr * 2 + 0] + b0;
                float v1 = c[im][jn][hr * 2 + 1] + b1;
                if (EPI == 1) { v0 = gelu_f(v0); v1 = gelu_f(v1); }
                if (EPI == 2) {
                    long rb = (long)rr * 384 + col;
                    float a0 = (__bfloat162float(f1[rb])     + f2[col]     * v0) * f3[col]     + f4[col];
                    float a1 = (__bfloat162float(f1[rb + 1]) + f2[col + 1] * v1) * f3[col + 1] + f4[col + 1];
                    int n = rr & 4095, b = rr >> 12;
                    int hh2 = n >> 6, ww2 = n & 63;
                    int q = ((hh2 & 1) << 1) | (ww2 & 1);
                    int p = ((hh2 >> 1) << 5) | (ww2 >> 1);
                    bf16* dst = Cb + ((long)(b * 4 + q) * 1024 + p) * 384 + col;
                    *(__nv_bfloat162*)dst = __floats2bfloat162_rn(a0, a1);
                } else if (OUTBF) {
                    *(__nv_bfloat162*)(Cb + (long)rr * N + col) = __floats2bfloat162_rn(v0, v1);
                } else {
                    *(float2*)(Cf + (long)rr * N + col) = make_float2(v0, v1);
                }
            }
        }
    }
}

template<int EPI, int OUTBF>
static void bg2(const bf16* A, const bf16* B, const float* bias, void* C,
                int M, int N, int K,
                const bf16* f1 = nullptr, const float* f2 = nullptr,
                const float* f3 = nullptr, const float* f4 = nullptr)
{
    cudaFuncSetAttribute(bgemm2_k<EPI, OUTBF>,
                         cudaFuncAttributeMaxDynamicSharedMemorySize, 110592);
    dim3 grid(M / 128, N / 128);
    bgemm2_k<EPI, OUTBF><<<grid, 128, 110592>>>(A, B, bias, C, N, K, f1, f2, f3, f4);
}

// ============================================================================
// Batched GEMM, 4-warp 64x64, templated chunk KCH in {32,64}, bounds-guarded.
// ============================================================================
template<int OUTM, int KCH>
__global__ void __launch_bounds__(128) bg2b_k(
    const bf16* __restrict__ Ag, const bf16* __restrict__ Bg, void* __restrict__ Cg,
    int M, int N, int K, int lda, int ldb, int ldc,
    long sA1, long sA2, long sB1, long sB2, long sC1, long sC2, int HB, int SK)
{
    extern __shared__ __align__(16) bf16 dynb[];
    const int TP = (KCH == 64) ? 72 : 40;
    const int TE = 128 * TP;
    const int SEGS = KCH / 8;
    unsigned sbA = smem_u32(dynb);
    unsigned sbB = sbA + 3 * TE * 2;

    int zz = blockIdx.z;
    int ksl = zz % SK, z = zz / SK;
    int zo = z / HB, zi = z - zo * HB;
    const bf16* A = Ag + zo * sA1 + zi * sA2 + (long)ksl * K;
    const bf16* B = Bg + zo * sB1 + zi * sB2 + (long)ksl * K;

    int tid = threadIdx.x;
    int m0 = blockIdx.x * 128, n0 = blockIdx.y * 128;

    float c[4][8][4];
    #pragma unroll
    for (int i = 0; i < 4; i++)
        #pragma unroll
        for (int j = 0; j < 8; j++)
            #pragma unroll
            for (int q = 0; q < 4; q++) c[i][j][q] = 0.f;

    int seg = tid & (SEGS - 1);
    int rS = tid / SEGS;
    auto stage = [&](int buf, int k0) {
        #pragma unroll
        for (int row = rS; row < 128; row += 128 / SEGS) {
            int ra = (m0 + row < M) ? m0 + row : M - 1;
            cpa16p(sbA + (buf * TE + row * TP + seg * 8) * 2,
                   A + (long)ra * lda + k0 + seg * 8, m0 + row < M);
            int rb = (n0 + row < N) ? n0 + row : N - 1;
            cpa16p(sbB + (buf * TE + row * TP + seg * 8) * 2,
                   B + (long)rb * ldb + k0 + seg * 8, n0 + row < N);
        }
        asm volatile("cp.async.commit_group;\n");
    };

    int nst = K / KCH;
    stage(0, 0);
    if (nst > 1) stage(1, KCH); else asm volatile("cp.async.commit_group;\n");
    if (nst > 2) stage(2, 2 * KCH); else asm volatile("cp.async.commit_group;\n");

    int wid = tid >> 5, lane = tid & 31;
    int wm = (wid >> 1) * 64, wn = (wid & 1) * 64;
    int g = lane >> 2, t = lane & 3;
    int aRow = ((lane >> 3) & 1) * 8 + (lane & 7);
    int aK = (lane >> 4) * 8;
    int bRow = ((lane >> 4) & 1) * 8 + (lane & 7);
    int bK = ((lane >> 3) & 1) * 8;

    for (int s = 0; s < nst; s++) {
        asm volatile("cp.async.wait_group 2;\n");
        __syncthreads();
        int buf = s % 3;
        unsigned aT = sbA + buf * TE * 2;
        unsigned bT = sbB + buf * TE * 2;
        #pragma unroll
        for (int ks = 0; ks < KCH; ks += 16) {
            unsigned af[4][4], bfm[8][2];
            #pragma unroll
            for (int im = 0; im < 4; im++) {
                unsigned addr = aT + ((wm + im * 16 + aRow) * TP + ks + aK) * 2;
                asm volatile("ldmatrix.sync.aligned.m8n8.x4.shared.b16 {%0,%1,%2,%3}, [%4];\n"
                             : "=r"(af[im][0]), "=r"(af[im][1]), "=r"(af[im][2]), "=r"(af[im][3])
                             : "r"(addr));
            }
            #pragma unroll
            for (int jp = 0; jp < 4; jp++) {
                unsigned addr = bT + ((wn + jp * 16 + bRow) * TP + ks + bK) * 2;
                asm volatile("ldmatrix.sync.aligned.m8n8.x4.shared.b16 {%0,%1,%2,%3}, [%4];\n"
                             : "=r"(bfm[2 * jp][0]), "=r"(bfm[2 * jp][1]),
                               "=r"(bfm[2 * jp + 1][0]), "=r"(bfm[2 * jp + 1][1])
                             : "r"(addr));
            }
            #pragma unroll
            for (int im = 0; im < 4; im++)
                #pragma unroll
                for (int jn = 0; jn < 8; jn++)
                    asm volatile(
                        "mma.sync.aligned.m16n8k16.row.col.f32.bf16.bf16.f32 "
                        "{%0,%1,%2,%3},{%4,%5,%6,%7},{%8,%9},{%0,%1,%2,%3};\n"
                        : "+f"(c[im][jn][0]), "+f"(c[im][jn][1]),
                          "+f"(c[im][jn][2]), "+f"(c[im][jn][3])
                        : "r"(af[im][0]), "r"(af[im][1]), "r"(af[im][2]), "r"(af[im][3]),
                          "r"(bfm[jn][0]), "r"(bfm[jn][1]));
        }
        __syncthreads();
        if (s + 3 < nst) stage((s + 3) % 3, (s + 3) * KCH);
        else asm volatile("cp.async.commit_group;\n");
    }

    float* Cf = (float*)Cg + zo * sC1 + zi * sC2;
    bf16*  Cb = (bf16*)Cg + zo * sC1 + zi * sC2;
    #pragma unroll
    for (int im = 0; im < 4; im++) {
        int rbase = m0 + wm + im * 16 + g;
        #pragma unroll
        for (int jn = 0; jn < 8; jn++) {
            int col = n0 + wn + jn * 8 + t * 2;
            if (col >= N) continue;
            #pragma unroll
            for (int hr = 0; hr < 2; hr++) {
                int rr = rbase + hr * 8;
                if (rr >= M) continue;
                float v0 = c[im][jn][hr * 2 + 0];
                float v1 = c[im][jn][hr * 2 + 1];
                if (OUTM == 3) {
                    atomicAdd(&Cf[(long)rr * ldc + col], v0);
                    atomicAdd(&Cf[(long)rr * ldc + col + 1], v1);
                } else if (OUTM == 1) {
                    *(__nv_bfloat162*)(Cb + (long)rr * ldc + col) = __floats2bfloat162_rn(v0, v1);
                } else {
                    *(float2*)(Cf + (long)rr * ldc + col) = make_float2(v0, v1);
                }
            }
        }
    }
}

template<int OUTM, int KCH>
static void bg2b(const bf16* A, const bf16* B, void* C,
                 int M, int N, int K, int lda, int ldb, int ldc,
                 long sA1, long sA2, long sB1, long sB2, long sC1, long sC2,
                 int HB, int Z, int SK = 1)
{
    int smem = (KCH == 64) ? 110592 : 61440;
    cudaFuncSetAttribute(bg2b_k<OUTM, KCH>,
                         cudaFuncAttributeMaxDynamicSharedMemorySize, smem);
    dim3 grid((M + 127) / 128, (N + 127) / 128, Z * SK);
    bg2b_k<OUTM, KCH><<<grid, 128, smem>>>(A, B, C, M, N, K / SK, lda, ldb, ldc,
                                           sA1, sA2, sB1, sB2, sC1, sC2, HB, SK);
}

extern "C" void kernel_launch(void* const* d_in, const int* in_sizes, int n_in,
                              void* d_out, int out_size)
{
    const float* x          = (const float*)d_in[0];
    const float* convs_w    = (const float*)d_in[1];
    const float* convs_b    = (const float*)d_in[2];
    const float* pos_w      = (const float*)d_in[3];
    const float* pos_b      = (const float*)d_in[4];
    const float* ln_xca_w   = (const float*)d_in[5];
    const float* ln_xca_b   = (const float*)d_in[6];
    const float* gamma_xca  = (const float*)d_in[7];
    const float* xca_temp   = (const float*)d_in[8];
    const float* xca_kv_w   = (const float*)d_in[9];
    const float* xca_kv_b   = (const float*)d_in[10];
    const float* xca_proj_w = (const float*)d_in[11];
    const float* xca_proj_b = (const float*)d_in[12];
    const float* conv_out_w = (const float*)d_in[13];
    const float* conv_out_b = (const float*)d_in[14];
    const float* wa_kv_w    = (const float*)d_in[15];
    const float* wa_kv_b    = (const float*)d_in[16];
    const float* wa_proj_w  = (const float*)d_in[17];
    const float* wa_proj_b  = (const float*)d_in[18];
    const float* ln_w       = (const float*)d_in[19];
    const float* ln_b       = (const float*)d_in[20];
    const float* pw1_w      = (const float*)d_in[21];
    const float* pw1_b      = (const float*)d_in[22];
    const float* pw2_w      = (const float*)d_in[23];
    const float* pw2_b      = (const float*)d_in[24];
    const float* gamma      = (const float*)d_in[25];
    float* out = (float*)d_out;

    float *conv, *pos, *x3f, *attn, *norms;
    bf16 *bx, *lnb, *kv, *kt, *b1, *uqt, *battn, *h1, *wt;
    cudaGetSymbolAddress((void**)&conv,  g_conv);
    cudaGetSymbolAddress((void**)&pos,   g_pos);
    cudaGetSymbolAddress((void**)&x3f,   g_x3);
    cudaGetSymbolAddress((void**)&attn,  g_attn);
    cudaGetSymbolAddress((void**)&norms, g_norms);
    cudaGetSymbolAddress((void**)&bx,    g_bx);
    cudaGetSymbolAddress((void**)&lnb,   g_lnb);
    cudaGetSymbolAddress((void**)&kv,    g_kv);
    cudaGetSymbolAddress((void**)&kt,    g_kt);
    cudaGetSymbolAddress((void**)&b1,    g_b1);
    cudaGetSymbolAddress((void**)&uqt,   g_uqt);
    cudaGetSymbolAddress((void**)&battn, g_battn);
    cudaGetSymbolAddress((void**)&h1,    g_h1);
    cudaGetSymbolAddress((void**)&wt,    g_wt);

    bf16* x3 = (bf16*)x3f;
    bf16* featb = battn;            // [4096][64] bf16 scratch (battn free until softmax)
    bf16* pwb   = battn + 262144;   // [384][64] bf16

    bf16* w_xkv   = wt;
    bf16* w_xproj = wt + 294912;
    bf16* w_wkv   = wt + 442368;
    bf16* w_wproj = wt + 737280;
    bf16* w_pw1   = wt + 884736;
    bf16* w_pw2   = wt + 1474560;

    static cudaStream_t sB = nullptr;
    static cudaEvent_t evF = nullptr, evJ = nullptr;
    if (sB == nullptr) {
        cudaStreamCreateWithFlags(&sB, cudaStreamNonBlocking);
        cudaEventCreateWithFlags(&evF, cudaEventDisableTiming);
        cudaEventCreateWithFlags(&evJ, cudaEventDisableTiming);
    }

    // fork: chain B (weight/x converts + attn zero)
    cudaEventRecord(evF, 0);
    cudaStreamWaitEvent(sB, evF, 0);
    cvtw_kernel<<<(2064384 + 255) / 256, 256, 0, sB>>>(
        xca_kv_w, xca_proj_w, wa_kv_w, wa_proj_w, pw1_w, pw2_w, wt);
    cvtx_kernel<<<(25165824 + 255) / 256, 256, 0, sB>>>(x, bx, uqt);
    zero_kernel<<<(589824 + 255) / 256, 256, 0, sB>>>(attn, 589824);
    cudaEventRecord(evJ, sB);

    // chain A: feat gen + pos GEMM + dwconv + fused transpose/LN
    featcvt_kernel<<<(262144 + 24576 + 255) / 256, 256>>>(pos_w, featb);
    bg2<0,0>(featb, pwb, pos_b, pos, 4096, 384, 64);
    dwconv3_kernel<<<16 * 96, 256>>>(x, convs_w, convs_b, conv);
    t1ln_kernel<<<dim3(256, 16), 256>>>(conv, x, pos, ln_xca_w, ln_xca_b, x3, lnb);

    // join before anything needing wt/bx/uqt/attn
    cudaStreamWaitEvent(0, evJ, 0);

    // XCA
    bg2<0,1>(lnb, w_xkv, xca_kv_b, kv, 65536, 768, 384);
    dim3 tb(32, 8);
    tk_kernel<<<dim3(128, 12, 16), tb>>>(kv, kt, 4096);
    norms2_k<<<768, 256>>>(kt, norms, 4096);
    bg2b<3,64>(bx, kt, attn, 96, 96, 4096, 4096, 4096, 96,
               (long)384*4096, (long)96*4096, (long)384*4096, (long)96*4096,
               (long)4*9216, 9216, 4, 64, 4);
    xca_softmax_k<<<768, 256>>>(attn, norms, xca_temp, battn);
    bg2b<1,32>(kv + 384, battn, b1, 4096, 96, 96, 768, 96, 384,
               (long)4096*768, 96, (long)4*9216, 9216, (long)4096*384, 96, 4, 64);
    bg2<2,1>(b1, w_xproj, xca_proj_b, lnb, 65536, 384, 384,
             x3, gamma_xca, conv_out_w, conv_out_b);

    // Window attention (wx = lnb)
    bg2<0,1>(lnb, w_wkv, wa_kv_b, kv, 65536, 768, 384);
    tk_kernel<<<dim3(32, 12, 64), tb>>>(kv, kt, 1024);
    norms2_k<<<3072, 256>>>(kt, norms, 1024);
    bg2b<0,64>(uqt, kt, attn, 96, 96, 1024, 1024, 1024, 96,
               (long)384*1024, (long)96*1024, (long)384*1024, (long)96*1024,
               (long)4*9216, 9216, 4, 256);
    wa_softmax_k<<<3072, 256>>>(attn, norms, battn);
    bf16* x2s = x3;
    bg2b<1,32>(battn, kv + 384, x2s, 96, 1024, 96, 96, 768, 1024,
               (long)4*9216, 9216, (long)1024*768, 96,
               (long)96*1024, (long)64*96*1024, 4, 256);
    bg2<0,1>(x2s, w_wproj, wa_proj_b, b1, 65536, 384, 384);

    // fold + gather-LN, MLP, final residual
    lng_kernel<<<65536, 128>>>(b1, ln_w, ln_b, lnb);
    bg2<1,1>(lnb, w_pw1, pw1_b, h1, 65536, 1536, 384);
    bg2<0,1>(h1, w_pw2, pw2_b, uqt, 65536, 384, 1536);
    dim3 tg2(128, 12, 16);
    final_kernel<<<tg2, tb>>>(uqt, x, gamma, out);
}

// round 17
// speedup vs baseline: 1.2635x; 1.0006x over previous
#include <cuda_runtime.h>
#include <cuda_bf16.h>
#include <cstdint>
#include <math.h>

#define FULLMASK 0xffffffffu
typedef __nv_bfloat16 bf16;
// B=16, C=384, H=W=64, N=4096, HEADS=4, HD=96

// ---------------- scratch ----------------
__device__ __align__(256) float g_conv[25165824];
__device__ __align__(256) float g_pos[1572864];
__device__ __align__(256) float g_x3[25165824];   // bf16 x3, then bf16 x2s
__device__ __align__(256) float g_attn[2359296];
__device__ __align__(256) float g_norms[24576];
__device__ __align__(256) bf16 g_bx[25165824];
__device__ __align__(256) bf16 g_lnb[25165824];
__device__ __align__(256) bf16 g_kv[50331648];
__device__ __align__(256) bf16 g_kt[25165824];
__device__ __align__(256) bf16 g_b1[25165824];
__device__ __align__(256) bf16 g_uqt[25165824];
__device__ __align__(256) bf16 g_battn[2359296];  // feat+pw_bf scratch, then probs
__device__ __align__(256) bf16 g_h1[100663296];
__device__ __align__(256) bf16 g_wt[2064384];

__global__ void zero_kernel(float* __restrict__ p, long n)
{
    long i = (long)blockIdx.x * 256 + threadIdx.x;
    if (i < n) p[i] = 0.f;
}

__global__ void cvtw_kernel(const float* __restrict__ s0, const float* __restrict__ s1,
                            const float* __restrict__ s2, const float* __restrict__ s3,
                            const float* __restrict__ s4, const float* __restrict__ s5,
                            bf16* __restrict__ out)
{
    long i = (long)blockIdx.x * 256 + threadIdx.x;
    if (i >= 2064384L) return;
    const float* s; long off;
    if (i < 294912)       { s = s0; off = i; }
    else if (i < 442368)  { s = s1; off = i - 294912; }
    else if (i < 737280)  { s = s2; off = i - 442368; }
    else if (i < 884736)  { s = s3; off = i - 737280; }
    else if (i < 1474560) { s = s4; off = i - 884736; }
    else                  { s = s5; off = i - 1474560; }
    out[i] = __float2bfloat16(s[off]);
}

__global__ void cvtx_kernel(const float* __restrict__ x, bf16* __restrict__ bx,
                            bf16* __restrict__ uqT)
{
    long idx = (long)blockIdx.x * 256 + threadIdx.x;
    if (idx >= 25165824L) return;
    float v = x[idx];
    bf16 bv = __float2bfloat16(v);
    bx[idx] = bv;
    int n = (int)(idx & 4095);
    long r = idx >> 12;
    int c = (int)(r % 384), b = (int)(r / 384);
    int hh = n >> 6, ww = n & 63;
    int q = ((hh & 1) << 1) | (ww & 1);
    int p = ((hh >> 1) << 5) | (ww >> 1);
    uqT[((long)(b * 4 + q) * 384 + c) * 1024 + p] = bv;
}

// ---------------- Fourier features (bf16) + pos_w convert ----------------
__global__ void featcvt_kernel(const float* __restrict__ pw, bf16* __restrict__ featb)
{
    long idx = (long)blockIdx.x * 256 + threadIdx.x;
    if (idx < 262144) {
        int n = (int)(idx >> 6), j = (int)(idx & 63);
        int hh = n >> 6, ww = n & 63;
        int jj = j & 31, m = jj >> 1;
        float v = (j < 32) ? (float)(hh + 1) : (float)(ww + 1);
        v = v / (64.0f + 1e-6f) * 6.283185307179586f;
        float arg = v / powf(10000.0f, (float)m / 16.0f);
        featb[idx] = __float2bfloat16((jj & 1) ? cosf(arg) : sinf(arg));
    } else if (idx < 262144 + 24576) {
        long o = idx - 262144;
        featb[idx] = __float2bfloat16(pw[o]);
    }
}

__global__ void __launch_bounds__(256) dwconv3_kernel(
    const float* __restrict__ x, const float* __restrict__ w,
    const float* __restrict__ bias, float* __restrict__ out)
{
    __shared__ float A[66 * 66], Bb[66 * 66];
    int bc = blockIdx.x, b = bc / 96, c = bc % 96, tid = threadIdx.x;
    for (int i = tid; i < 66 * 66; i += 256) { A[i] = 0.f; Bb[i] = 0.f; }
    __syncthreads();
    const float* xp = x + ((long)b * 384 + c) * 4096;
    for (int i = tid; i < 4096; i += 256)
        A[((i >> 6) + 1) * 66 + (i & 63) + 1] = xp[i];
    __syncthreads();
    float* src = A;
    float* dst = Bb;
    #pragma unroll
    for (int ch = 0; ch < 3; ch++) {
        const float* wp = w + (ch * 96 + c) * 9;
        float bv = bias[ch * 96 + c];
        float w00 = wp[0], w01 = wp[1], w02 = wp[2];
        float w10 = wp[3], w11 = wp[4], w12 = wp[5];
        float w20 = wp[6], w21 = wp[7], w22 = wp[8];
        float* op = out + ((long)b * 384 + ch * 96 + c) * 4096;
        const float* xn = (ch < 2) ? x + ((long)b * 384 + (ch + 1) * 96 + c) * 4096 : nullptr;
        for (int i = tid; i < 4096; i += 256) {
            int r = i >> 6, cc = i & 63;
            const float* p = src + r * 66 + cc;
            float acc = bv
                + w00 * p[0]   + w01 * p[1]   + w02 * p[2]
                + w10 * p[66]  + w11 * p[67]  + w12 * p[68]
                + w20 * p[132] + w21 * p[133] + w22 * p[134];
            op[i] = acc;
            if (xn) dst[(r + 1) * 66 + cc + 1] = acc + xn[i];
        }
        __syncthreads();
        float* t = src; src = dst; dst = t;
    }
}

// ---------------- fused transpose+pos+LayerNorm ----------------
__global__ void __launch_bounds__(256) t1ln_kernel(
    const float* __restrict__ conv, const float* __restrict__ xin,
    const float* __restrict__ pos, const float* __restrict__ w,
    const float* __restrict__ bvec, bf16* __restrict__ x3, bf16* __restrict__ lnb)
{
    __shared__ float s[16 * 385];
    int n0 = blockIdx.x << 4, b = blockIdx.y, tid = threadIdx.x;
    for (int idx = tid; idx < 384 * 16; idx += 256) {
        int n = idx & 15, c = idx >> 4;
        const float* src = (c >= 288) ? xin : conv;
        float v = src[((long)b * 384 + c) * 4096 + n0 + n] + pos[(long)(n0 + n) * 384 + c];
        s[n * 385 + c] = v;
    }
    __syncthreads();
    int wid = tid >> 5, lane = tid & 31;
    #pragma unroll
    for (int r = 0; r < 2; r++) {
        int row = wid + r * 8;
        const float* sr = s + row * 385;
        float sum = 0.f, sq = 0.f;
        #pragma unroll
        for (int i = 0; i < 12; i++) {
            float v = sr[lane + i * 32];
            sum += v; sq += v * v;
        }
        #pragma unroll
        for (int o = 16; o; o >>= 1) {
            sum += __shfl_xor_sync(FULLMASK, sum, o);
            sq  += __shfl_xor_sync(FULLMASK, sq, o);
        }
        float m = sum * (1.0f / 384.0f);
        float rs = rsqrtf(sq * (1.0f / 384.0f) - m * m + 1e-6f);
        long ob = ((long)b * 4096 + n0 + row) * 384;
        #pragma unroll
        for (int i = 0; i < 12; i++) {
            int c = lane + i * 32;
            float v = sr[c];
            x3[ob + c]  = __float2bfloat16(v);
            lnb[ob + c] = __float2bfloat16((v - m) * rs * w[c] + bvec[c]);
        }
    }
}

// ---------------- kv k-part transpose + fused ssq partials ----------------
__global__ void tk_kernel(const bf16* __restrict__ kv, bf16* __restrict__ kT,
                          float* __restrict__ norms, int R)
{
    __shared__ bf16 tile[32][33];
    int n0 = blockIdx.x << 5, d0 = blockIdx.y << 5, bz = blockIdx.z;
    int tx = threadIdx.x, ty = threadIdx.y;
    #pragma unroll
    for (int r = 0; r < 4; r++)
        tile[ty + r * 8][tx] = kv[((long)bz * R + n0 + ty + r * 8) * 768 + d0 + tx];
    __syncthreads();
    #pragma unroll
    for (int r = 0; r < 4; r++)
        kT[((long)bz * 384 + d0 + ty + r * 8) * R + n0 + tx] = tile[tx][ty + r * 8];
    if (ty == 0) {
        float s = 0.f;
        #pragma unroll
        for (int n = 0; n < 32; n++) {
            float v = __bfloat162float(tile[n][tx]);
            s += v * v;
        }
        atomicAdd(&norms[bz * 384 + d0 + tx], s);
    }
}

__global__ void lng_kernel(const bf16* __restrict__ in, const float* __restrict__ w,
                           const float* __restrict__ bvec, bf16* __restrict__ out)
{
    int row = blockIdx.x, t = threadIdx.x;
    int b = row >> 12, n = row & 4095;
    int hh = n >> 6, ww = n & 63;
    int q = ((hh & 1) << 1) | (ww & 1);
    int p = ((hh >> 1) << 5) | (ww >> 1);
    long ibase = ((long)(b * 4 + q) * 1024 + p) * 384;
    float v0 = __bfloat162float(in[ibase + t]);
    float v1 = __bfloat162float(in[ibase + t + 128]);
    float v2 = __bfloat162float(in[ibase + t + 256]);
    float s = v0 + v1 + v2;
    float q2 = v0 * v0 + v1 * v1 + v2 * v2;
    #pragma unroll
    for (int o = 16; o; o >>= 1) {
        s += __shfl_down_sync(FULLMASK, s, o);
        q2 += __shfl_down_sync(FULLMASK, q2, o);
    }
    __shared__ float ss[4], sq[4], smean, srstd;
    int wid = t >> 5, lane = t & 31;
    if (lane == 0) { ss[wid] = s; sq[wid] = q2; }
    __syncthreads();
    if (t == 0) {
        float S = ss[0] + ss[1] + ss[2] + ss[3];
        float Q = sq[0] + sq[1] + sq[2] + sq[3];
        float m = S * (1.0f / 384.0f);
        smean = m;
        srstd = rsqrtf(Q * (1.0f / 384.0f) - m * m + 1e-6f);
    }
    __syncthreads();
    float m = smean, r = srstd;
    long ob = (long)row * 384;
    out[ob + t]       = __float2bfloat16((v0 - m) * r * w[t]       + bvec[t]);
    out[ob + t + 128] = __float2bfloat16((v1 - m) * r * w[t + 128] + bvec[t + 128]);
    out[ob + t + 256] = __float2bfloat16((v2 - m) * r * w[t + 256] + bvec[t + 256]);
}

// norms now holds sum-of-squares; take sqrt here
__global__ void xca_softmax_k(const float* __restrict__ G, const float* __restrict__ norms,
                              const float* __restrict__ temp, bf16* __restrict__ P)
{
    int warp = threadIdx.x >> 5, lane = threadIdx.x & 31;
    int row = blockIdx.x * 8 + warp;
    int bh = row / 96, b = bh >> 2, h = bh & 3;
    float tv = temp[h];
    const float* g = G + (long)row * 96;
    bf16* o = P + (long)row * 96;
    const float* nb = norms + b * 384 + h * 96;
    float v[3];
    #pragma unroll
    for (int i = 0; i < 3; i++) {
        int d = lane + i * 32;
        v[i] = g[d] * tv / fmaxf(sqrtf(nb[d]), 1e-12f);
    }
    float m = fmaxf(v[0], fmaxf(v[1], v[2]));
    #pragma unroll
    for (int o2 = 16; o2; o2 >>= 1) m = fmaxf(m, __shfl_xor_sync(FULLMASK, m, o2));
    float e[3], s = 0.f;
    #pragma unroll
    for (int i = 0; i < 3; i++) { e[i] = expf(v[i] - m); s += e[i]; }
    #pragma unroll
    for (int o2 = 16; o2; o2 >>= 1) s += __shfl_xor_sync(FULLMASK, s, o2);
    float inv = 1.0f / s;
    #pragma unroll
    for (int i = 0; i < 3; i++) o[lane + i * 32] = __float2bfloat16(e[i] * inv);
}

__global__ void wa_softmax_k(const float* __restrict__ G, const float* __restrict__ norms,
                             bf16* __restrict__ P)
{
    int warp = threadIdx.x >> 5, lane = threadIdx.x & 31;
    int row = blockIdx.x * 8 + warp;
    int bh = row / 96, bq = bh >> 2, h = bh & 3;
    const float* g = G + (long)row * 96;
    bf16* o = P + (long)row * 96;
    const float* nb = norms + bq * 384 + h * 96;
    float l[3];
    #pragma unroll
    for (int i = 0; i < 3; i++) {
        int d = lane + i * 32;
        l[i] = g[d] / fmaxf(sqrtf(nb[d]), 1e-12f);
    }
    float m1 = fmaxf(l[0], fmaxf(l[1], l[2]));
    #pragma unroll
    for (int o2 = 16; o2; o2 >>= 1) m1 = fmaxf(m1, __shfl_xor_sync(FULLMASK, m1, o2));
    float e[3], s1 = 0.f;
    #pragma unroll
    for (int i = 0; i < 3; i++) { e[i] = expf(l[i] - m1); s1 += e[i]; }
    #pragma unroll
    for (int o2 = 16; o2; o2 >>= 1) s1 += __shfl_xor_sync(FULLMASK, s1, o2);
    float inv1 = 1.0f / s1, a[3];
    #pragma unroll
    for (int i = 0; i < 3; i++) a[i] = l[i] * 0.051031036307982884f + 0.5f * e[i] * inv1;
    float m2 = fmaxf(a[0], fmaxf(a[1], a[2]));
    #pragma unroll
    for (int o2 = 16; o2; o2 >>= 1) m2 = fmaxf(m2, __shfl_xor_sync(FULLMASK, m2, o2));
    float e2[3], s2 = 0.f;
    #pragma unroll
    for (int i = 0; i < 3; i++) { e2[i] = expf(a[i] - m2); s2 += e2[i]; }
    #pragma unroll
    for (int o2 = 16; o2; o2 >>= 1) s2 += __shfl_xor_sync(FULLMASK, s2, o2);
    float inv2 = 1.0f / s2;
    #pragma unroll
    for (int i = 0; i < 3; i++) o[lane + i * 32] = __float2bfloat16(e2[i] * inv2);
}

__global__ void final_kernel(const bf16* __restrict__ y, const float* __restrict__ xin,
                             const float* __restrict__ gamma, float* __restrict__ out)
{
    __shared__ float tile[32][33];
    int n0 = blockIdx.x << 5, c0 = blockIdx.y << 5, b = blockIdx.z;
    int tx = threadIdx.x, ty = threadIdx.y;
    #pragma unroll
    for (int r = 0; r < 4; r++)
        tile[ty + r * 8][tx] =
            __bfloat162float(y[((long)b * 4096 + n0 + ty + r * 8) * 384 + c0 + tx]);
    __syncthreads();
    #pragma unroll
    for (int r = 0; r < 4; r++) {
        int c = c0 + ty + r * 8;
        long o = ((long)b * 384 + c) * 4096 + n0 + tx;
        out[o] = xin[o] + gamma[c] * tile[tx][ty + r * 8];
    }
}

__device__ __forceinline__ void cpa16s(unsigned sa, const void* g)
{
    asm volatile("cp.async.cg.shared.global [%0], [%1], 16;\n" :: "r"(sa), "l"(g));
}

__device__ __forceinline__ void cpa16p(unsigned sa, const void* g, bool valid)
{
    int sz = valid ? 16 : 0;
    asm volatile("cp.async.cg.shared.global [%0], [%1], 16, %2;\n"
                 :: "r"(sa), "l"(g), "r"(sz));
}

__device__ __forceinline__ unsigned smem_u32(const void* p)
{
    return (unsigned)__cvta_generic_to_shared(p);
}

__device__ __forceinline__ float gelu_f(float v)
{
    return 0.5f * v * (1.0f + erff(v * 0.7071067811865476f));
}

// ============================================================================
// Big-GEMM: 128x128 CTA tile, K=64 chunks, 4 warps of 64x64. (unchanged)
// ============================================================================
template<int EPI, int OUTBF>
__global__ void __launch_bounds__(128) bgemm2_k(
    const bf16* __restrict__ A, const bf16* __restrict__ B,
    const float* __restrict__ bias, void* __restrict__ Cg,
    int N, int K,
    const bf16* __restrict__ f1, const float* __restrict__ f2,
    const float* __restrict__ f3, const float* __restrict__ f4)
{
    extern __shared__ __align__(16) bf16 dynb[];
    const int TP = 72;
    const int TE = 128 * TP;
    unsigned sbA = smem_u32(dynb);
    unsigned sbB = sbA + 3 * TE * 2;

    int tid = threadIdx.x;
    int m0 = blockIdx.x * 128, n0 = blockIdx.y * 128;

    float c[4][8][4];
    #pragma unroll
    for (int i = 0; i < 4; i++)
        #pragma unroll
        for (int j = 0; j < 8; j++)
            #pragma unroll
            for (int q = 0; q < 4; q++) c[i][j][q] = 0.f;

    int seg = tid & 7, rS = tid >> 3;
    auto stage = [&](int buf, int k0) {
        #pragma unroll
        for (int ps = 0; ps < 8; ps++) {
            int row = rS + ps * 16;
            cpa16s(sbA + (buf * TE + row * TP + seg * 8) * 2,
                   A + (long)(m0 + row) * K + k0 + seg * 8);
            cpa16s(sbB + (buf * TE + row * TP + seg * 8) * 2,
                   B + (long)(n0 + row) * K + k0 + seg * 8);
        }
        asm volatile("cp.async.commit_group;\n");
    };

    int nst = K >> 6;
    stage(0, 0);
    if (nst > 1) stage(1, 64); else asm volatile("cp.async.commit_group;\n");
    if (nst > 2) stage(2, 128); else asm volatile("cp.async.commit_group;\n");

    int wid = tid >> 5, lane = tid & 31;
    int wm = (wid >> 1) * 64, wn = (wid & 1) * 64;
    int g = lane >> 2, t = lane & 3;
    int aRow = ((lane >> 3) & 1) * 8 + (lane & 7);
    int aK = (lane >> 4) * 8;
    int bRow = ((lane >> 4) & 1) * 8 + (lane & 7);
    int bK = ((lane >> 3) & 1) * 8;

    for (int s = 0; s < nst; s++) {
        asm volatile("cp.async.wait_group 2;\n");
        __syncthreads();
        int buf = s % 3;
        unsigned aT = sbA + buf * TE * 2;
        unsigned bT = sbB + buf * TE * 2;
        #pragma unroll
        for (int ks = 0; ks < 64; ks += 16) {
            unsigned af[4][4], bfm[8][2];
            #pragma unroll
            for (int im = 0; im < 4; im++) {
                unsigned addr = aT + ((wm + im * 16 + aRow) * TP + ks + aK) * 2;
                asm volatile("ldmatrix.sync.aligned.m8n8.x4.shared.b16 {%0,%1,%2,%3}, [%4];\n"
                             : "=r"(af[im][0]), "=r"(af[im][1]), "=r"(af[im][2]), "=r"(af[im][3])
                             : "r"(addr));
            }
            #pragma unroll
            for (int jp = 0; jp < 4; jp++) {
                unsigned addr = bT + ((wn + jp * 16 + bRow) * TP + ks + bK) * 2;
                asm volatile("ldmatrix.sync.aligned.m8n8.x4.shared.b16 {%0,%1,%2,%3}, [%4];\n"
                             : "=r"(bfm[2 * jp][0]), "=r"(bfm[2 * jp][1]),
                               "=r"(bfm[2 * jp + 1][0]), "=r"(bfm[2 * jp + 1][1])
                             : "r"(addr));
            }
            #pragma unroll
            for (int im = 0; im < 4; im++)
                #pragma unroll
                for (int jn = 0; jn < 8; jn++)
                    asm volatile(
                        "mma.sync.aligned.m16n8k16.row.col.f32.bf16.bf16.f32 "
                        "{%0,%1,%2,%3},{%4,%5,%6,%7},{%8,%9},{%0,%1,%2,%3};\n"
                        : "+f"(c[im][jn][0]), "+f"(c[im][jn][1]),
                          "+f"(c[im][jn][2]), "+f"(c[im][jn][3])
                        : "r"(af[im][0]), "r"(af[im][1]), "r"(af[im][2]), "r"(af[im][3]),
                          "r"(bfm[jn][0]), "r"(bfm[jn][1]));
        }
        __syncthreads();
        if (s + 3 < nst) stage((s + 3) % 3, (s + 3) << 6);
        else asm volatile("cp.async.commit_group;\n");
    }

    float* Cf = (float*)Cg;
    bf16*  Cb = (bf16*)Cg;
    #pragma unroll
    for (int im = 0; im < 4; im++) {
        int rbase = m0 + wm + im * 16 + g;
        #pragma unroll
        for (int jn = 0; jn < 8; jn++) {
            int col = n0 + wn + jn * 8 + t * 2;
            float b0 = bias ? bias[col] : 0.f;
            float b1 = bias ? bias[col + 1] : 0.f;
            #pragma unroll
            for (int hr = 0; hr < 2; hr++) {
                int rr = rbase + hr * 8;
                float v0 = c[im][jn][hr * 2 + 0] + b0;
                float v1 = c[im][jn][hr * 2 + 1] + b1;
                if (EPI == 1) { v0 = gelu_f(v0); v1 = gelu_f(v1); }
                if (EPI == 2) {
                    long rb = (long)rr * 384 + col;
                    float a0 = (__bfloat162float(f1[rb])     + f2[col]     * v0) * f3[col]     + f4[col];
                    float a1 = (__bfloat162float(f1[rb + 1]) + f2[col + 1] * v1) * f3[col + 1] + f4[col + 1];
                    int n = rr & 4095, b = rr >> 12;
                    int hh2 = n >> 6, ww2 = n & 63;
                    int q = ((hh2 & 1) << 1) | (ww2 & 1);
                    int p = ((hh2 >> 1) << 5) | (ww2 >> 1);
                    bf16* dst = Cb + ((long)(b * 4 + q) * 1024 + p) * 384 + col;
                    *(__nv_bfloat162*)dst = __floats2bfloat162_rn(a0, a1);
                } else if (OUTBF) {
                    *(__nv_bfloat162*)(Cb + (long)rr * N + col) = __floats2bfloat162_rn(v0, v1);
                } else {
                    *(float2*)(Cf + (long)rr * N + col) = make_float2(v0, v1);
                }
            }
        }
    }
}

template<int EPI, int OUTBF>
static void bg2(const bf16* A, const bf16* B, const float* bias, void* C,
                int M, int N, int K,
                const bf16* f1 = nullptr, const float* f2 = nullptr,
                const float* f3 = nullptr, const float* f4 = nullptr)
{
    cudaFuncSetAttribute(bgemm2_k<EPI, OUTBF>,
                         cudaFuncAttributeMaxDynamicSharedMemorySize, 110592);
    dim3 grid(M / 128, N / 128);
    bgemm2_k<EPI, OUTBF><<<grid, 128, 110592>>>(A, B, bias, C, N, K, f1, f2, f3, f4);
}

// ============================================================================
// Batched GEMM, 4-warp 64x64, templated chunk KCH in {32,64}, bounds-guarded.
// ============================================================================
template<int OUTM, int KCH>
__global__ void __launch_bounds__(128) bg2b_k(
    const bf16* __restrict__ Ag, const bf16* __restrict__ Bg, void* __restrict__ Cg,
    int M, int N, int K, int lda, int ldb, int ldc,
    long sA1, long sA2, long sB1, long sB2, long sC1, long sC2, int HB, int SK)
{
    extern __shared__ __align__(16) bf16 dynb[];
    const int TP = (KCH == 64) ? 72 : 40;
    const int TE = 128 * TP;
    const int SEGS = KCH / 8;
    unsigned sbA = smem_u32(dynb);
    unsigned sbB = sbA + 3 * TE * 2;

    int zz = blockIdx.z;
    int ksl = zz % SK, z = zz / SK;
    int zo = z / HB, zi = z - zo * HB;
    const bf16* A = Ag + zo * sA1 + zi * sA2 + (long)ksl * K;
    const bf16* B = Bg + zo * sB1 + zi * sB2 + (long)ksl * K;

    int tid = threadIdx.x;
    int m0 = blockIdx.x * 128, n0 = blockIdx.y * 128;

    float c[4][8][4];
    #pragma unroll
    for (int i = 0; i < 4; i++)
        #pragma unroll
        for (int j = 0; j < 8; j++)
            #pragma unroll
            for (int q = 0; q < 4; q++) c[i][j][q] = 0.f;

    int seg = tid & (SEGS - 1);
    int rS = tid / SEGS;
    auto stage = [&](int buf, int k0) {
        #pragma unroll
        for (int row = rS; row < 128; row += 128 / SEGS) {
            int ra = (m0 + row < M) ? m0 + row : M - 1;
            cpa16p(sbA + (buf * TE + row * TP + seg * 8) * 2,
                   A + (long)ra * lda + k0 + seg * 8, m0 + row < M);
            int rb = (n0 + row < N) ? n0 + row : N - 1;
            cpa16p(sbB + (buf * TE + row * TP + seg * 8) * 2,
                   B + (long)rb * ldb + k0 + seg * 8, n0 + row < N);
        }
        asm volatile("cp.async.commit_group;\n");
    };

    int nst = K / KCH;
    stage(0, 0);
    if (nst > 1) stage(1, KCH); else asm volatile("cp.async.commit_group;\n");
    if (nst > 2) stage(2, 2 * KCH); else asm volatile("cp.async.commit_group;\n");

    int wid = tid >> 5, lane = tid & 31;
    int wm = (wid >> 1) * 64, wn = (wid & 1) * 64;
    int g = lane >> 2, t = lane & 3;
    int aRow = ((lane >> 3) & 1) * 8 + (lane & 7);
    int aK = (lane >> 4) * 8;
    int bRow = ((lane >> 4) & 1) * 8 + (lane & 7);
    int bK = ((lane >> 3) & 1) * 8;

    for (int s = 0; s < nst; s++) {
        asm volatile("cp.async.wait_group 2;\n");
        __syncthreads();
        int buf = s % 3;
        unsigned aT = sbA + buf * TE * 2;
        unsigned bT = sbB + buf * TE * 2;
        #pragma unroll
        for (int ks = 0; ks < KCH; ks += 16) {
            unsigned af[4][4], bfm[8][2];
            #pragma unroll
            for (int im = 0; im < 4; im++) {
                unsigned addr = aT + ((wm + im * 16 + aRow) * TP + ks + aK) * 2;
                asm volatile("ldmatrix.sync.aligned.m8n8.x4.shared.b16 {%0,%1,%2,%3}, [%4];\n"
                             : "=r"(af[im][0]), "=r"(af[im][1]), "=r"(af[im][2]), "=r"(af[im][3])
                             : "r"(addr));
            }
            #pragma unroll
            for (int jp = 0; jp < 4; jp++) {
                unsigned addr = bT + ((wn + jp * 16 + bRow) * TP + ks + bK) * 2;
                asm volatile("ldmatrix.sync.aligned.m8n8.x4.shared.b16 {%0,%1,%2,%3}, [%4];\n"
                             : "=r"(bfm[2 * jp][0]), "=r"(bfm[2 * jp][1]),
                               "=r"(bfm[2 * jp + 1][0]), "=r"(bfm[2 * jp + 1][1])
                             : "r"(addr));
            }
            #pragma unroll
            for (int im = 0; im < 4; im++)
                #pragma unroll
                for (int jn = 0; jn < 8; jn++)
                    asm volatile(
                        "mma.sync.aligned.m16n8k16.row.col.f32.bf16.bf16.f32 "
                        "{%0,%1,%2,%3},{%4,%5,%6,%7},{%8,%9},{%0,%1,%2,%3};\n"
                        : "+f"(c[im][jn][0]), "+f"(c[im][jn][1]),
                          "+f"(c[im][jn][2]), "+f"(c[im][jn][3])
                        : "r"(af[im][0]), "r"(af[im][1]), "r"(af[im][2]), "r"(af[im][3]),
                          "r"(bfm[jn][0]), "r"(bfm[jn][1]));
        }
        __syncthreads();
        if (s + 3 < nst) stage((s + 3) % 3, (s + 3) * KCH);
        else asm volatile("cp.async.commit_group;\n");
    }

    float* Cf = (float*)Cg + zo * sC1 + zi * sC2;
    bf16*  Cb = (bf16*)Cg + zo * sC1 + zi * sC2;
    #pragma unroll
    for (int im = 0; im < 4; im++) {
        int rbase = m0 + wm + im * 16 + g;
        #pragma unroll
        for (int jn = 0; jn < 8; jn++) {
            int col = n0 + wn + jn * 8 + t * 2;
            if (col >= N) continue;
            #pragma unroll
            for (int hr = 0; hr < 2; hr++) {
                int rr = rbase + hr * 8;
                if (rr >= M) continue;
                float v0 = c[im][jn][hr * 2 + 0];
                float v1 = c[im][jn][hr * 2 + 1];
                if (OUTM == 3) {
                    atomicAdd(&Cf[(long)rr * ldc + col], v0);
                    atomicAdd(&Cf[(long)rr * ldc + col + 1], v1);
                } else if (OUTM == 1) {
                    *(__nv_bfloat162*)(Cb + (long)rr * ldc + col) = __floats2bfloat162_rn(v0, v1);
                } else {
                    *(float2*)(Cf + (long)rr * ldc + col) = make_float2(v0, v1);
                }
            }
        }
    }
}

template<int OUTM, int KCH>
static void bg2b(const bf16* A, const bf16* B, void* C,
                 int M, int N, int K, int lda, int ldb, int ldc,
                 long sA1, long sA2, long sB1, long sB2, long sC1, long sC2,
                 int HB, int Z, int SK = 1)
{
    int smem = (KCH == 64) ? 110592 : 61440;
    cudaFuncSetAttribute(bg2b_k<OUTM, KCH>,
                         cudaFuncAttributeMaxDynamicSharedMemorySize, smem);
    dim3 grid((M + 127) / 128, (N + 127) / 128, Z * SK);
    bg2b_k<OUTM, KCH><<<grid, 128, smem>>>(A, B, C, M, N, K / SK, lda, ldb, ldc,
                                           sA1, sA2, sB1, sB2, sC1, sC2, HB, SK);
}

extern "C" void kernel_launch(void* const* d_in, const int* in_sizes, int n_in,
                              void* d_out, int out_size)
{
    const float* x          = (const float*)d_in[0];
    const float* convs_w    = (const float*)d_in[1];
    const float* convs_b    = (const float*)d_in[2];
    const float* pos_w      = (const float*)d_in[3];
    const float* pos_b      = (const float*)d_in[4];
    const float* ln_xca_w   = (const float*)d_in[5];
    const float* ln_xca_b   = (const float*)d_in[6];
    const float* gamma_xca  = (const float*)d_in[7];
    const float* xca_temp   = (const float*)d_in[8];
    const float* xca_kv_w   = (const float*)d_in[9];
    const float* xca_kv_b   = (const float*)d_in[10];
    const float* xca_proj_w = (const float*)d_in[11];
    const float* xca_proj_b = (const float*)d_in[12];
    const float* conv_out_w = (const float*)d_in[13];
    const float* conv_out_b = (const float*)d_in[14];
    const float* wa_kv_w    = (const float*)d_in[15];
    const float* wa_kv_b    = (const float*)d_in[16];
    const float* wa_proj_w  = (const float*)d_in[17];
    const float* wa_proj_b  = (const float*)d_in[18];
    const float* ln_w       = (const float*)d_in[19];
    const float* ln_b       = (const float*)d_in[20];
    const float* pw1_w      = (const float*)d_in[21];
    const float* pw1_b      = (const float*)d_in[22];
    const float* pw2_w      = (const float*)d_in[23];
    const float* pw2_b      = (const float*)d_in[24];
    const float* gamma      = (const float*)d_in[25];
    float* out = (float*)d_out;

    float *conv, *pos, *x3f, *attn, *norms;
    bf16 *bx, *lnb, *kv, *kt, *b1, *uqt, *battn, *h1, *wt;
    cudaGetSymbolAddress((void**)&conv,  g_conv);
    cudaGetSymbolAddress((void**)&pos,   g_pos);
    cudaGetSymbolAddress((void**)&x3f,   g_x3);
    cudaGetSymbolAddress((void**)&attn,  g_attn);
    cudaGetSymbolAddress((void**)&norms, g_norms);
    cudaGetSymbolAddress((void**)&bx,    g_bx);
    cudaGetSymbolAddress((void**)&lnb,   g_lnb);
    cudaGetSymbolAddress((void**)&kv,    g_kv);
    cudaGetSymbolAddress((void**)&kt,    g_kt);
    cudaGetSymbolAddress((void**)&b1,    g_b1);
    cudaGetSymbolAddress((void**)&uqt,   g_uqt);
    cudaGetSymbolAddress((void**)&battn, g_battn);
    cudaGetSymbolAddress((void**)&h1,    g_h1);
    cudaGetSymbolAddress((void**)&wt,    g_wt);

    bf16* x3 = (bf16*)x3f;
    bf16* featb = battn;            // [4096][64] bf16 scratch
    bf16* pwb   = battn + 262144;   // [384][64] bf16

    bf16* w_xkv   = wt;
    bf16* w_xproj = wt + 294912;
    bf16* w_wkv   = wt + 442368;
    bf16* w_wproj = wt + 737280;
    bf16* w_pw1   = wt + 884736;
    bf16* w_pw2   = wt + 1474560;

    static cudaStream_t sB = nullptr;
    static cudaEvent_t evF = nullptr, evJ = nullptr;
    if (sB == nullptr) {
        cudaStreamCreateWithFlags(&sB, cudaStreamNonBlocking);
        cudaEventCreateWithFlags(&evF, cudaEventDisableTiming);
        cudaEventCreateWithFlags(&evJ, cudaEventDisableTiming);
    }

    // fork: chain B (weight/x converts + attn zero + norms zero)
    cudaEventRecord(evF, 0);
    cudaStreamWaitEvent(sB, evF, 0);
    cvtw_kernel<<<(2064384 + 255) / 256, 256, 0, sB>>>(
        xca_kv_w, xca_proj_w, wa_kv_w, wa_proj_w, pw1_w, pw2_w, wt);
    cvtx_kernel<<<(25165824 + 255) / 256, 256, 0, sB>>>(x, bx, uqt);
    zero_kernel<<<(589824 + 255) / 256, 256, 0, sB>>>(attn, 589824);
    zero_kernel<<<96, 256, 0, sB>>>(norms, 24576);
    cudaEventRecord(evJ, sB);

    // chain A: feat gen + pos GEMM + dwconv + fused transpose/LN
    featcvt_kernel<<<(262144 + 24576 + 255) / 256, 256>>>(pos_w, featb);
    bg2<0,0>(featb, pwb, pos_b, pos, 4096, 384, 64);
    dwconv3_kernel<<<16 * 96, 256>>>(x, convs_w, convs_b, conv);
    t1ln_kernel<<<dim3(256, 16), 256>>>(conv, x, pos, ln_xca_w, ln_xca_b, x3, lnb);

    // join before anything needing wt/bx/uqt/attn/norms
    cudaStreamWaitEvent(0, evJ, 0);

    // XCA
    bg2<0,1>(lnb, w_xkv, xca_kv_b, kv, 65536, 768, 384);
    dim3 tb(32, 8);
    tk_kernel<<<dim3(128, 12, 16), tb>>>(kv, kt, norms, 4096);
    bg2b<3,64>(bx, kt, attn, 96, 96, 4096, 4096, 4096, 96,
               (long)384*4096, (long)96*4096, (long)384*4096, (long)96*4096,
               (long)4*9216, 9216, 4, 64, 8);
    xca_softmax_k<<<768, 256>>>(attn, norms, xca_temp, battn);
    bg2b<1,32>(kv + 384, battn, b1, 4096, 96, 96, 768, 96, 384,
               (long)4096*768, 96, (long)4*9216, 9216, (long)4096*384, 96, 4, 64);
    bg2<2,1>(b1, w_xproj, xca_proj_b, lnb, 65536, 384, 384,
             x3, gamma_xca, conv_out_w, conv_out_b);

    // Window attention (wx = lnb); norms re-zeroed for WA accumulation
    zero_kernel<<<96, 256>>>(norms, 24576);
    bg2<0,1>(lnb, w_wkv, wa_kv_b, kv, 65536, 768, 384);
    tk_kernel<<<dim3(32, 12, 64), tb>>>(kv, kt, norms, 1024);
    bg2b<0,64>(uqt, kt, attn, 96, 96, 1024, 1024, 1024, 96,
               (long)384*1024, (long)96*1024, (long)384*1024, (long)96*1024,
               (long)4*9216, 9216, 4, 256);
    wa_softmax_k<<<3072, 256>>>(attn, norms, battn);
    bf16* x2s = x3;
    bg2b<1,32>(battn, kv + 384, x2s, 96, 1024, 96, 96, 768, 1024,
               (long)4*9216, 9216, (long)1024*768, 96,
               (long)96*1024, (long)64*96*1024, 4, 256);
    bg2<0,1>(x2s, w_wproj, wa_proj_b, b1, 65536, 384, 384);

    // fold + gather-LN, MLP, final residual
    lng_kernel<<<65536, 128>>>(b1, ln_w, ln_b, lnb);
    bg2<1,1>(lnb, w_pw1, pw1_b, h1, 65536, 1536, 384);
    bg2<0,1>(h1, w_pw2, pw2_b, uqt, 65536, 384, 1536);
    dim3 tg2(128, 12, 16);
    final_kernel<<<tg2, tb>>>(uqt, x, gamma, out);
}